// round 5
// baseline (speedup 1.0000x reference)
#include <cuda_runtime.h>
#include <cstdint>

#define CS 2048
#define CH 16
#define ATT_SCALE 0.07216878364870323f   // 192^-0.5

// ---------------- scratch (device globals, fp32 pre-rounded to tf32) --------
__device__ __align__(256) float g_xr [(size_t)4096*2048];
__device__ __align__(256) float g_wqar[(size_t)1536*2048];
__device__ __align__(256) float g_wkvar[(size_t)576*2048];
__device__ __align__(256) float g_wqbr[(size_t)3072*1536];
__device__ __align__(256) float g_wor[(size_t)2048*2048];
__device__ __align__(256) float g_wvr[(size_t)16*128*512];
__device__ __align__(256) float g_wnt[(size_t)16*512*128];
__device__ __align__(256) float g_q1 [(size_t)4096*1536];
__device__ __align__(256) float g_kv [(size_t)4096*576];
__device__ __align__(256) float g_kt [(size_t)2*512*2048];
__device__ __align__(256) float g_q2 [(size_t)4096*3072];
__device__ __align__(256) float g_qp [(size_t)4096*9216];
__device__ __align__(256) float g_pf [(size_t)2*CH*CS*CS];
__device__ __align__(256) float g_oc [(size_t)4096*8192];
__device__ __align__(256) float g_ov [(size_t)4096*2048];

// ---------------- helpers ----------------
__device__ __forceinline__ float rne_tf32(float f) {
    uint32_t u;
    asm("cvt.rna.tf32.f32 %0, %1;" : "=r"(u) : "f"(f));
    return __uint_as_float(u);
}
__device__ __forceinline__ void cp16(uint32_t saddr, const void* gptr) {
    asm volatile("cp.async.cg.shared.global [%0], [%1], 16;" :: "r"(saddr), "l"(gptr));
}
__device__ __forceinline__ void cp16z(uint32_t saddr, const void* gptr, int sz) {
    asm volatile("cp.async.cg.shared.global [%0], [%1], 16, %2;" :: "r"(saddr), "l"(gptr), "r"(sz));
}
__device__ __forceinline__ void mma_tf32(float* c, const uint32_t* a, uint32_t b0, uint32_t b1) {
    asm volatile(
        "mma.sync.aligned.m16n8k8.row.col.f32.tf32.tf32.f32 "
        "{%0,%1,%2,%3},{%4,%5,%6,%7},{%8,%9},{%0,%1,%2,%3};"
        : "+f"(c[0]), "+f"(c[1]), "+f"(c[2]), "+f"(c[3])
        : "r"(a[0]), "r"(a[1]), "r"(a[2]), "r"(a[3]), "r"(b0), "r"(b1));
}

// ---------------- tensor-core tf32 GEMM: C[m,n] = sum_k A[m,k]*B[n,k] -------
// A: [M,K] k-major (lda). B: [N,K] k-major (ldb). Both PRE-ROUNDED to tf32.
// CTA tile 256x128, k-chunk 32; 8 warps (4x2), warp tile 64x64, m16n8k8.
// causal: skip tiles where n0 > m0+255.  kclamp: Keff = min(K, m0+256).
#define TLD 36
#define ABUF (256 * TLD)
#define BBUF (128 * TLD)

__global__ __launch_bounds__(256) void gemm_tc(
    const float* __restrict__ A, int lda, long long strA,
    const float* __restrict__ B, int ldb, long long strB,
    float* __restrict__ C, int ldc, long long strC,
    int M, int N, int K, int causal, int kclamp, int roundC)
{
    int bm = blockIdx.y, bn = blockIdx.x;
    int m0 = bm * 256, n0 = bn * 128;
    if (causal && n0 > m0 + 255) return;
    long long z = blockIdx.z;
    A += z * strA;
    B += z * strB;
    C += z * strC;
    int Keff = kclamp ? (K < m0 + 256 ? K : m0 + 256) : K;
    int ntk = Keff >> 5;

    extern __shared__ float smem[];
    float* As = smem;                     // [2][256][36]
    float* Bs = smem + 2 * ABUF;          // [2][128][36]
    uint32_t sbase = (uint32_t)__cvta_generic_to_shared(smem);
    uint32_t sAs = sbase;
    uint32_t sBs = sbase + 2 * ABUF * 4;

    int tid = threadIdx.x;
    int wid = tid >> 5, lane = tid & 31;
    int wm = wid >> 1, wn = wid & 1;
    int g = lane >> 2, tg = lane & 3;

    float acc[4][8][4];
#pragma unroll
    for (int mi = 0; mi < 4; mi++)
#pragma unroll
        for (int j = 0; j < 8; j++)
#pragma unroll
            for (int r = 0; r < 4; r++) acc[mi][j][r] = 0.f;

    auto load_tile = [&](int kt, int buf) {
        long long k0 = (long long)kt * 32;
#pragma unroll
        for (int i = 0; i < 8; i++) {
            int idx = tid + i * 256;
            int row = idx >> 3, c8 = idx & 7;
            cp16(sAs + (uint32_t)(buf * ABUF + row * TLD + c8 * 4) * 4,
                 A + (long long)(m0 + row) * lda + k0 + c8 * 4);
        }
#pragma unroll
        for (int i = 0; i < 4; i++) {
            int idx = tid + i * 256;
            int row = idx >> 3, c8 = idx & 7;
            int gn = n0 + row;
            cp16z(sBs + (uint32_t)(buf * BBUF + row * TLD + c8 * 4) * 4,
                  B + (long long)(gn < N ? gn : 0) * ldb + k0 + c8 * 4,
                  gn < N ? 16 : 0);
        }
        asm volatile("cp.async.commit_group;" ::: "memory");
    };

    load_tile(0, 0);

    for (int kt = 0; kt < ntk; kt++) {
        int buf = kt & 1;
        if (kt + 1 < ntk) {
            load_tile(kt + 1, buf ^ 1);
            asm volatile("cp.async.wait_group 1;" ::: "memory");
        } else {
            asm volatile("cp.async.wait_group 0;" ::: "memory");
        }
        __syncthreads();

        const float* Asb = As + buf * ABUF;
        const float* Bsb = Bs + buf * BBUF;
#pragma unroll
        for (int ks = 0; ks < 4; ks++) {
            int kk = ks * 8;
            uint32_t a[4][4];
#pragma unroll
            for (int mi = 0; mi < 4; mi++) {
                int r = wm * 64 + mi * 16 + g;
                a[mi][0] = __float_as_uint(Asb[r * TLD + kk + tg]);
                a[mi][1] = __float_as_uint(Asb[(r + 8) * TLD + kk + tg]);
                a[mi][2] = __float_as_uint(Asb[r * TLD + kk + tg + 4]);
                a[mi][3] = __float_as_uint(Asb[(r + 8) * TLD + kk + tg + 4]);
            }
#pragma unroll
            for (int j = 0; j < 8; j++) {
                int c = wn * 64 + j * 8 + g;
                uint32_t b0 = __float_as_uint(Bsb[c * TLD + kk + tg]);
                uint32_t b1 = __float_as_uint(Bsb[c * TLD + kk + tg + 4]);
#pragma unroll
                for (int mi = 0; mi < 4; mi++)
                    mma_tf32(acc[mi][j], a[mi], b0, b1);
            }
        }
        __syncthreads();
    }

    // epilogue
#pragma unroll
    for (int mi = 0; mi < 4; mi++) {
#pragma unroll
        for (int j = 0; j < 8; j++) {
            int row = m0 + wm * 64 + mi * 16 + g;
            int col = n0 + wn * 64 + j * 8 + 2 * tg;
            if (col < N) {
                float v0 = acc[mi][j][0], v1 = acc[mi][j][1];
                float v2 = acc[mi][j][2], v3 = acc[mi][j][3];
                if (roundC) {
                    v0 = rne_tf32(v0); v1 = rne_tf32(v1);
                    v2 = rne_tf32(v2); v3 = rne_tf32(v3);
                }
                *(float2*)&C[(long long)row * ldc + col] = make_float2(v0, v1);
                *(float2*)&C[(long long)(row + 8) * ldc + col] = make_float2(v2, v3);
            }
        }
    }
}

// ---------------- prep: rounded copies / transposes --------------------------
__global__ void round_copy(const float* __restrict__ s, float* __restrict__ d, long long n4)
{
    long long i = (long long)blockIdx.x * 256 + threadIdx.x;
    if (i >= n4) return;
    float4 v = ((const float4*)s)[i];
    v.x = rne_tf32(v.x); v.y = rne_tf32(v.y);
    v.z = rne_tf32(v.z); v.w = rne_tf32(v.w);
    ((float4*)d)[i] = v;
}

__global__ void round_wv(const float* __restrict__ wkvb, float* __restrict__ d)
{
    long long i4 = (long long)blockIdx.x * 256 + threadIdx.x;
    long long head = i4 >> 14, off = (i4 & 16383) * 4;
    float4 v = *(const float4*)(wkvb + head * 131072 + 65536 + off);
    v.x = rne_tf32(v.x); v.y = rne_tf32(v.y);
    v.z = rne_tf32(v.z); v.w = rne_tf32(v.w);
    ((float4*)d)[i4] = v;
}

__global__ void transpose_round(const float* __restrict__ src, float* __restrict__ dst,
                                int R, int C, int sld, long long sstr, long long dstr)
{
    __shared__ float tile[32][33];
    src += (long long)blockIdx.z * sstr;
    dst += (long long)blockIdx.z * dstr;
    int c0 = blockIdx.x * 32, r0 = blockIdx.y * 32;
    int x = threadIdx.x, y = threadIdx.y;
#pragma unroll
    for (int j = 0; j < 32; j += 8)
        tile[y + j][x] = src[(long long)(r0 + y + j) * sld + c0 + x];
    __syncthreads();
#pragma unroll
    for (int j = 0; j < 32; j += 8)
        dst[(long long)(c0 + y + j) * R + r0 + x] = rne_tf32(tile[x][y + j]);
}

// ---------------- rmsnorm rows (in-place, rounded stores) --------------------
__global__ void rmsnorm_rows(float* __restrict__ x, const float* __restrict__ w, int n)
{
    long long row = blockIdx.x;
    float* r = x + row * n;
    float ss = 0.f;
    for (int i = threadIdx.x; i < n; i += 256) { float v = r[i]; ss += v * v; }
    __shared__ float red[8];
#pragma unroll
    for (int o = 16; o; o >>= 1) ss += __shfl_xor_sync(0xffffffffu, ss, o);
    if ((threadIdx.x & 31) == 0) red[threadIdx.x >> 5] = ss;
    __syncthreads();
    float tot = 0.f;
#pragma unroll
    for (int wv = 0; wv < 8; wv++) tot += red[wv];
    float scale = rsqrtf(tot / (float)n + 1e-6f);
    for (int i = threadIdx.x; i < n; i += 256) r[i] = rne_tf32(r[i] * scale * w[i]);
}

// -------- kv row: rmsnorm first 512 (+w), rope last 64; rounded stores ------
__global__ void kv_process(float* __restrict__ kv, const float* __restrict__ w,
                           const float* __restrict__ cosp, const float* __restrict__ sinp)
{
    int row = blockIdx.x;
    int s = row % CS;
    float* r = kv + (long long)row * 576;
    float ss = 0.f;
    for (int i = threadIdx.x; i < 512; i += 128) { float v = r[i]; ss += v * v; }
    __shared__ float red[4];
#pragma unroll
    for (int o = 16; o; o >>= 1) ss += __shfl_xor_sync(0xffffffffu, ss, o);
    if ((threadIdx.x & 31) == 0) red[threadIdx.x >> 5] = ss;
    __syncthreads();
    float tot = red[0] + red[1] + red[2] + red[3];
    float scale = rsqrtf(tot / 512.f + 1e-6f);
    for (int i = threadIdx.x; i < 512; i += 128) r[i] = rne_tf32(r[i] * scale * w[i]);
    if (threadIdx.x < 32) {
        int i = threadIdx.x;
        float x0 = r[512 + 2 * i], x1 = r[512 + 2 * i + 1];
        float c = cosp[s * 32 + i], sn = sinp[s * 32 + i];
        r[512 + 2 * i]     = rne_tf32(x0 * c - x1 * sn);
        r[512 + 2 * i + 1] = rne_tf32(x0 * sn + x1 * c);
    }
}

// ---------------- RoPE on q_pe: q2 -> qp (rounded) ---------------------------
__global__ void rope_q(const float* __restrict__ q2, float* __restrict__ qp,
                       const float* __restrict__ cosp, const float* __restrict__ sinp)
{
    int idx = blockIdx.x * 256 + threadIdx.x;
    if (idx >= 4096 * CH * 32) return;
    int i = idx & 31;
    int h = (idx >> 5) & 15;
    int row = idx >> 9;
    int s = row % CS;
    const float* src = q2 + (long long)row * 3072 + h * 192 + 128 + 2 * i;
    float x0 = src[0], x1 = src[1];
    float c = cosp[s * 32 + i], sn = sinp[s * 32 + i];
    float* dst = qp + (long long)row * 9216 + h * 576 + 512 + 2 * i;
    dst[0] = rne_tf32(x0 * c - x1 * sn);
    dst[1] = rne_tf32(x0 * sn + x1 * c);
}

// ---------------- causal softmax over P rows (in-place, rounded) -------------
__global__ __launch_bounds__(256) void softmax_causal(float* __restrict__ P)
{
    int row = blockIdx.x;
    int s = row & (CS - 1);
    float* pr = P + (long long)row * CS;
    int tid = threadIdx.x;

    float v[8];
    float m = -1e30f;
#pragma unroll
    for (int i = 0; i < 8; i++) {
        int t = tid + i * 256;
        v[i] = (t <= s) ? pr[t] * ATT_SCALE : -1e30f;
        m = fmaxf(m, v[i]);
    }
    __shared__ float red[8];
#pragma unroll
    for (int o = 16; o; o >>= 1) m = fmaxf(m, __shfl_xor_sync(0xffffffffu, m, o));
    if ((tid & 31) == 0) red[tid >> 5] = m;
    __syncthreads();
    m = red[0];
#pragma unroll
    for (int w = 1; w < 8; w++) m = fmaxf(m, red[w]);

    float sum = 0.f;
#pragma unroll
    for (int i = 0; i < 8; i++) {
        int t = tid + i * 256;
        v[i] = (t <= s) ? __expf(v[i] - m) : 0.f;
        sum += v[i];
    }
    __syncthreads();
#pragma unroll
    for (int o = 16; o; o >>= 1) sum += __shfl_xor_sync(0xffffffffu, sum, o);
    if ((tid & 31) == 0) red[tid >> 5] = sum;
    __syncthreads();
    sum = 0.f;
#pragma unroll
    for (int w = 0; w < 8; w++) sum += red[w];
    float inv = 1.f / sum;
#pragma unroll
    for (int i = 0; i < 8; i++)
        pr[tid + i * 256] = rne_tf32(v[i] * inv);
}

// ---------------------------------------------------------------------------
extern "C" void kernel_launch(void* const* d_in, const int* in_sizes, int n_in,
                              void* d_out, int out_size)
{
    (void)in_sizes; (void)n_in; (void)out_size;
    const float* x        = (const float*)d_in[0];
    const float* wq_a     = (const float*)d_in[1];
    const float* q_norm_w = (const float*)d_in[2];
    const float* wq_b     = (const float*)d_in[3];
    const float* wkv_a    = (const float*)d_in[4];
    const float* kv_norm_w= (const float*)d_in[5];
    const float* wkv_b    = (const float*)d_in[6];
    const float* wo       = (const float*)d_in[7];
    const float* cosp     = (const float*)d_in[8];
    const float* sinp     = (const float*)d_in[9];
    float* out = (float*)d_out;

    float *xr, *wqar, *wkvar, *wqbr, *wor, *wvr, *wnt;
    float *q1, *kvb, *kt, *q2, *qp, *pf, *oc, *ov;
    cudaGetSymbolAddress((void**)&xr,   g_xr);
    cudaGetSymbolAddress((void**)&wqar, g_wqar);
    cudaGetSymbolAddress((void**)&wkvar,g_wkvar);
    cudaGetSymbolAddress((void**)&wqbr, g_wqbr);
    cudaGetSymbolAddress((void**)&wor,  g_wor);
    cudaGetSymbolAddress((void**)&wvr,  g_wvr);
    cudaGetSymbolAddress((void**)&wnt,  g_wnt);
    cudaGetSymbolAddress((void**)&q1,   g_q1);
    cudaGetSymbolAddress((void**)&kvb,  g_kv);
    cudaGetSymbolAddress((void**)&kt,   g_kt);
    cudaGetSymbolAddress((void**)&q2,   g_q2);
    cudaGetSymbolAddress((void**)&qp,   g_qp);
    cudaGetSymbolAddress((void**)&pf,   g_pf);
    cudaGetSymbolAddress((void**)&oc,   g_oc);
    cudaGetSymbolAddress((void**)&ov,   g_ov);

    const int SMEM = 2 * (ABUF + BBUF) * 4;   // 110592
    cudaFuncSetAttribute(gemm_tc, cudaFuncAttributeMaxDynamicSharedMemorySize, SMEM);

    dim3 t32(32, 8);
    // ---- prep: round everything to tf32 once ----
    round_copy<<<8192, 256>>>(x,     xr,    2097152);
    round_copy<<<3072, 256>>>(wq_a,  wqar,  786432);
    round_copy<<<1152, 256>>>(wkv_a, wkvar, 294912);
    round_copy<<<4608, 256>>>(wq_b,  wqbr,  1179648);
    round_copy<<<4096, 256>>>(wo,    wor,   1048576);
    round_wv<<<1024, 256>>>(wkv_b, wvr);
    transpose_round<<<dim3(16, 4, 16), t32>>>(wkv_b, wnt, 128, 512, 512, 131072, 65536);

    // 1) q1 = x @ wq_a^T
    gemm_tc<<<dim3(12, 16, 1), 256, SMEM>>>(xr, 2048, 0, wqar, 2048, 0,
        q1, 1536, 0, 4096, 1536, 2048, 0, 0, 0);
    // 2) rmsnorm q1 (rounds)
    rmsnorm_rows<<<4096, 256>>>(q1, q_norm_w, 1536);
    // 3) kv = x @ wkv_a^T
    gemm_tc<<<dim3(5, 16, 1), 256, SMEM>>>(xr, 2048, 0, wkvar, 2048, 0,
        kvb, 576, 0, 4096, 576, 2048, 0, 0, 0);
    // 4) rmsnorm kv_c + rope k_pe (rounds)
    kv_process<<<4096, 128>>>(kvb, kv_norm_w, cosp, sinp);
    // 5) kv_c^T per batch -> kt [b][512][2048]
    transpose_round<<<dim3(16, 64, 2), t32>>>(kvb, kt, 2048, 512, 576,
        (long long)2048 * 576, (long long)512 * 2048);
    // 6) q2 = q1 @ wq_b^T (rounded out)
    gemm_tc<<<dim3(24, 16, 1), 256, SMEM>>>(q1, 1536, 0, wqbr, 1536, 0,
        q2, 3072, 0, 4096, 3072, 1536, 0, 0, 1);
    // 7) q_abs per head: q2[:,h*192:+128] @ wnt[h]^T -> qp[:,h*576:+512] (rounded)
    gemm_tc<<<dim3(4, 16, 16), 256, SMEM>>>(q2, 3072, 192, wnt, 128, 65536,
        qp, 9216, 576, 4096, 512, 128, 0, 0, 1);
    // 8) rope q_pe -> qp[:,h*576+512:+64] (rounded)
    rope_q<<<8192, 256>>>(q2, qp, cosp, sinp);
    // 9) scores per (b,h): P = Q' @ K'^T, causal tile skip
    for (int b = 0; b < 2; b++) {
        gemm_tc<<<dim3(16, 8, 16), 256, SMEM>>>(
            qp + (long long)b * CS * 9216, 9216, 576,
            kvb + (long long)b * CS * 576, 576, 0,
            pf + (long long)b * CH * CS * CS, CS, (long long)CS * CS,
            2048, 2048, 576, 1, 0, 0);
    }
    // 10) softmax in-place (rounds)
    softmax_causal<<<2 * CH * CS, 256>>>(pf);
    // 11) O = P @ kv_c^T' (K clamped to m0+256, rounded out)
    for (int b = 0; b < 2; b++) {
        gemm_tc<<<dim3(4, 8, 16), 256, SMEM>>>(
            pf + (long long)b * CH * CS * CS, CS, (long long)CS * CS,
            kt + (long long)b * 512 * 2048, 2048, 0,
            oc + (long long)b * CS * 8192, 8192, 512,
            2048, 512, 2048, 0, 1, 1);
    }
    // 12) o_v per head: oc[:,h*512:+512] @ w_v[h] -> ov[:,h*128:+128] (rounded)
    gemm_tc<<<dim3(1, 16, 16), 256, SMEM>>>(oc, 8192, 512, wvr, 512, 65536,
        ov, 2048, 128, 4096, 128, 512, 0, 0, 1);
    // 13) out = ov @ wo^T (full fp32 out)
    gemm_tc<<<dim3(16, 16, 1), 256, SMEM>>>(ov, 2048, 0, wor, 2048, 0,
        out, 2048, 0, 4096, 2048, 2048, 0, 0, 0);
}

// round 6
// speedup vs baseline: 1.4146x; 1.4146x over previous
#include <cuda_runtime.h>
#include <cuda.h>
#include <cstdint>
#include <dlfcn.h>

#define CS 2048
#define CH 16
#define ATT_SCALE 0.07216878364870323f   // 192^-0.5

// ---------------- scratch (device globals, fp32 pre-rounded to tf32) --------
__device__ __align__(256) float g_xr [(size_t)4096*2048];
__device__ __align__(256) float g_wqar[(size_t)1536*2048];
__device__ __align__(256) float g_wkvar[(size_t)576*2048];
__device__ __align__(256) float g_wqbr[(size_t)3072*1536];
__device__ __align__(256) float g_wor[(size_t)2048*2048];
__device__ __align__(256) float g_wvr[(size_t)16*128*512];
__device__ __align__(256) float g_wnt[(size_t)16*512*128];
__device__ __align__(256) float g_q1 [(size_t)4096*1536];
__device__ __align__(256) float g_kv [(size_t)4096*576];
__device__ __align__(256) float g_kt [(size_t)2*512*2048];
__device__ __align__(256) float g_q2 [(size_t)4096*3072];
__device__ __align__(256) float g_qp [(size_t)4096*9216];
__device__ __align__(256) float g_pf [(size_t)2*CH*CS*CS];
__device__ __align__(256) float g_oc [(size_t)4096*8192];
__device__ __align__(256) float g_ov [(size_t)4096*2048];

// ---------------- helpers ----------------
__device__ __forceinline__ float rne_tf32(float f) {
    uint32_t u;
    asm("cvt.rna.tf32.f32 %0, %1;" : "=r"(u) : "f"(f));
    return __uint_as_float(u);
}
__device__ __forceinline__ void mma_tf32(float* c, const uint32_t* a, uint32_t b0, uint32_t b1) {
    asm volatile(
        "mma.sync.aligned.m16n8k8.row.col.f32.tf32.tf32.f32 "
        "{%0,%1,%2,%3},{%4,%5,%6,%7},{%8,%9},{%0,%1,%2,%3};"
        : "+f"(c[0]), "+f"(c[1]), "+f"(c[2]), "+f"(c[3])
        : "r"(a[0]), "r"(a[1]), "r"(a[2]), "r"(a[3]), "r"(b0), "r"(b1));
}
#define MBAR_INIT(a, c) \
    asm volatile("mbarrier.init.shared.b64 [%0], %1;" :: "r"(a), "r"(c) : "memory")
#define MBAR_EXPECT(a, tx) \
    asm volatile("mbarrier.arrive.expect_tx.shared.b64 _, [%0], %1;" :: "r"(a), "r"(tx) : "memory")
#define MBAR_WAIT(a, ph) do { \
    asm volatile("{\n\t.reg .pred P1;\n\tWL%=:\n\t" \
        "mbarrier.try_wait.parity.acquire.cta.shared::cta.b64 P1, [%0], %1, 0x989680;\n\t" \
        "@P1 bra.uni WD%=;\n\tbra.uni WL%=;\n\tWD%=:\n\t}" \
        :: "r"(a), "r"(ph) : "memory"); } while (0)
__device__ __forceinline__ void tma2d(uint32_t dst, const void* map, int x, int y, uint32_t mbar) {
    asm volatile(
        "cp.async.bulk.tensor.2d.shared::cta.global.tile.mbarrier::complete_tx::bytes "
        "[%0], [%1, {%2, %3}], [%4];"
        :: "r"(dst), "l"(map), "r"(x), "r"(y), "r"(mbar) : "memory");
}

// ---------------- TMA tf32 GEMM: C[m,n] = sum_k A[m,k]*B[n,k] ----------------
// A,B fetched via 2D tensormaps (SW128, box [32,128]). 128x128x32 CTA tile,
// 8 warps (4x2), warp tile 32x64, m16n8k8. 3-stage mbarrier pipeline.
// coords: A (k0+z*axz, m0+z*ayz), B (k0+z*bxz, n0+z*byz).
#define NST 3
#define STAGE 32768
#define SMEM_TMA (1024 + NST * STAGE)

__global__ __launch_bounds__(256, 2) void gemm_tma(
    const __grid_constant__ CUtensorMap mA,
    const __grid_constant__ CUtensorMap mB,
    int axz, int ayz, int bxz, int byz,
    float* __restrict__ C, int ldc, long long strC,
    int M, int N, int K, int causal, int kclamp, int roundC)
{
    int bm = blockIdx.y, bn = blockIdx.x;
    if (causal && bn > bm) return;
    int z = blockIdx.z;
    C += (long long)z * strC;
    int m0 = bm * 128, n0 = bn * 128;
    int Keff = kclamp ? (K < m0 + 128 ? K : m0 + 128) : K;
    int ntk = Keff >> 5;

    extern __shared__ __align__(1024) char smem[];
    uint32_t sbase = (uint32_t)__cvta_generic_to_shared(smem);

    int tid = threadIdx.x;
    int wid = tid >> 5, lane = tid & 31;
    int wm = wid >> 1, wn = wid & 1;
    int g = lane >> 2, tg = lane & 3;

    if (tid == 0) {
#pragma unroll
        for (int s = 0; s < NST; s++) MBAR_INIT(sbase + s * 8, 1);
    }
    __syncthreads();

    int xa = z * axz, ya = m0 + z * ayz;
    int xb = z * bxz, yb = n0 + z * byz;

    auto issue = [&](int j, int jb) {
        uint32_t mb = sbase + jb * 8;
        uint32_t da = sbase + 1024 + jb * STAGE;
        int k0 = j * 32;
        MBAR_EXPECT(mb, STAGE);
        tma2d(da, &mA, xa + k0, ya, mb);
        tma2d(da + 16384, &mB, xb + k0, yb, mb);
    };

    if (tid == 0) {
        issue(0, 0);
        if (ntk > 1) issue(1, 1);
    }

    float acc[2][8][4];
#pragma unroll
    for (int mi = 0; mi < 2; mi++)
#pragma unroll
        for (int j = 0; j < 8; j++)
#pragma unroll
            for (int r = 0; r < 4; r++) acc[mi][j][r] = 0.f;

    uint32_t xorv = (uint32_t)g << 4;
    int buf = 0, ph = 0;
    int pj = NST - 1, pbuf = NST - 1;

    for (int kt = 0; kt < ntk; kt++) {
        MBAR_WAIT(sbase + buf * 8, ph);
        const char* As = smem + 1024 + buf * STAGE;
        const char* Bs = As + 16384;
#pragma unroll
        for (int ks = 0; ks < 4; ks++) {
            uint32_t kb = (uint32_t)(ks * 32 + tg * 4);
            uint32_t c0 = kb ^ xorv;
            uint32_t c1 = (kb + 16u) ^ xorv;
            uint32_t a[2][4];
#pragma unroll
            for (int mi = 0; mi < 2; mi++) {
                int r = wm * 32 + mi * 16 + g;
                a[mi][0] = *(const uint32_t*)(As + r * 128 + c0);
                a[mi][1] = *(const uint32_t*)(As + (r + 8) * 128 + c0);
                a[mi][2] = *(const uint32_t*)(As + r * 128 + c1);
                a[mi][3] = *(const uint32_t*)(As + (r + 8) * 128 + c1);
            }
#pragma unroll
            for (int j = 0; j < 8; j++) {
                int c = wn * 64 + j * 8 + g;
                uint32_t b0 = *(const uint32_t*)(Bs + c * 128 + c0);
                uint32_t b1 = *(const uint32_t*)(Bs + c * 128 + c1);
                mma_tf32(acc[0][j], a[0], b0, b1);
                mma_tf32(acc[1][j], a[1], b0, b1);
            }
        }
        __syncthreads();
        if (tid == 0 && pj < ntk) issue(pj, pbuf);
        pj++;
        if (++pbuf == NST) pbuf = 0;
        if (++buf == NST) { buf = 0; ph ^= 1; }
    }

    // epilogue
#pragma unroll
    for (int mi = 0; mi < 2; mi++) {
#pragma unroll
        for (int j = 0; j < 8; j++) {
            int row = m0 + wm * 32 + mi * 16 + g;
            int col = n0 + wn * 64 + j * 8 + 2 * tg;
            if (col < N) {
                float v0 = acc[mi][j][0], v1 = acc[mi][j][1];
                float v2 = acc[mi][j][2], v3 = acc[mi][j][3];
                if (roundC) {
                    v0 = rne_tf32(v0); v1 = rne_tf32(v1);
                    v2 = rne_tf32(v2); v3 = rne_tf32(v3);
                }
                *(float2*)&C[(long long)row * ldc + col] = make_float2(v0, v1);
                *(float2*)&C[(long long)(row + 8) * ldc + col] = make_float2(v2, v3);
            }
        }
    }
}

// ---------------- prep: rounded copies / transposes --------------------------
__global__ void round_copy(const float* __restrict__ s, float* __restrict__ d, long long n4)
{
    long long i = (long long)blockIdx.x * 256 + threadIdx.x;
    if (i >= n4) return;
    float4 v = ((const float4*)s)[i];
    v.x = rne_tf32(v.x); v.y = rne_tf32(v.y);
    v.z = rne_tf32(v.z); v.w = rne_tf32(v.w);
    ((float4*)d)[i] = v;
}

__global__ void round_wv(const float* __restrict__ wkvb, float* __restrict__ d)
{
    long long i4 = (long long)blockIdx.x * 256 + threadIdx.x;
    long long head = i4 >> 14, off = (i4 & 16383) * 4;
    float4 v = *(const float4*)(wkvb + head * 131072 + 65536 + off);
    v.x = rne_tf32(v.x); v.y = rne_tf32(v.y);
    v.z = rne_tf32(v.z); v.w = rne_tf32(v.w);
    ((float4*)d)[i4] = v;
}

__global__ void transpose_round(const float* __restrict__ src, float* __restrict__ dst,
                                int R, int C, int sld, long long sstr, long long dstr)
{
    __shared__ float tile[32][33];
    src += (long long)blockIdx.z * sstr;
    dst += (long long)blockIdx.z * dstr;
    int c0 = blockIdx.x * 32, r0 = blockIdx.y * 32;
    int x = threadIdx.x, y = threadIdx.y;
#pragma unroll
    for (int j = 0; j < 32; j += 8)
        tile[y + j][x] = src[(long long)(r0 + y + j) * sld + c0 + x];
    __syncthreads();
#pragma unroll
    for (int j = 0; j < 32; j += 8)
        dst[(long long)(c0 + y + j) * R + r0 + x] = rne_tf32(tile[x][y + j]);
}

// ---------------- rmsnorm rows (in-place, rounded stores) --------------------
__global__ void rmsnorm_rows(float* __restrict__ x, const float* __restrict__ w, int n)
{
    long long row = blockIdx.x;
    float* r = x + row * n;
    float ss = 0.f;
    for (int i = threadIdx.x; i < n; i += 256) { float v = r[i]; ss += v * v; }
    __shared__ float red[8];
#pragma unroll
    for (int o = 16; o; o >>= 1) ss += __shfl_xor_sync(0xffffffffu, ss, o);
    if ((threadIdx.x & 31) == 0) red[threadIdx.x >> 5] = ss;
    __syncthreads();
    float tot = 0.f;
#pragma unroll
    for (int wv = 0; wv < 8; wv++) tot += red[wv];
    float scale = rsqrtf(tot / (float)n + 1e-6f);
    for (int i = threadIdx.x; i < n; i += 256) r[i] = rne_tf32(r[i] * scale * w[i]);
}

// -------- kv row: rmsnorm first 512 (+w), rope last 64; rounded stores ------
__global__ void kv_process(float* __restrict__ kv, const float* __restrict__ w,
                           const float* __restrict__ cosp, const float* __restrict__ sinp)
{
    int row = blockIdx.x;
    int s = row % CS;
    float* r = kv + (long long)row * 576;
    float ss = 0.f;
    for (int i = threadIdx.x; i < 512; i += 128) { float v = r[i]; ss += v * v; }
    __shared__ float red[4];
#pragma unroll
    for (int o = 16; o; o >>= 1) ss += __shfl_xor_sync(0xffffffffu, ss, o);
    if ((threadIdx.x & 31) == 0) red[threadIdx.x >> 5] = ss;
    __syncthreads();
    float tot = red[0] + red[1] + red[2] + red[3];
    float scale = rsqrtf(tot / 512.f + 1e-6f);
    for (int i = threadIdx.x; i < 512; i += 128) r[i] = rne_tf32(r[i] * scale * w[i]);
    if (threadIdx.x < 32) {
        int i = threadIdx.x;
        float x0 = r[512 + 2 * i], x1 = r[512 + 2 * i + 1];
        float c = cosp[s * 32 + i], sn = sinp[s * 32 + i];
        r[512 + 2 * i]     = rne_tf32(x0 * c - x1 * sn);
        r[512 + 2 * i + 1] = rne_tf32(x0 * sn + x1 * c);
    }
}

// ---------------- RoPE on q_pe: q2 -> qp (rounded) ---------------------------
__global__ void rope_q(const float* __restrict__ q2, float* __restrict__ qp,
                       const float* __restrict__ cosp, const float* __restrict__ sinp)
{
    int idx = blockIdx.x * 256 + threadIdx.x;
    if (idx >= 4096 * CH * 32) return;
    int i = idx & 31;
    int h = (idx >> 5) & 15;
    int row = idx >> 9;
    int s = row % CS;
    const float* src = q2 + (long long)row * 3072 + h * 192 + 128 + 2 * i;
    float x0 = src[0], x1 = src[1];
    float c = cosp[s * 32 + i], sn = sinp[s * 32 + i];
    float* dst = qp + (long long)row * 9216 + h * 576 + 512 + 2 * i;
    dst[0] = rne_tf32(x0 * c - x1 * sn);
    dst[1] = rne_tf32(x0 * sn + x1 * c);
}

// ---------------- causal softmax over P rows (in-place, rounded) -------------
__global__ __launch_bounds__(256) void softmax_causal(float* __restrict__ P)
{
    int row = blockIdx.x;
    int s = row & (CS - 1);
    float* pr = P + (long long)row * CS;
    int tid = threadIdx.x;

    float v[8];
    float m = -1e30f;
#pragma unroll
    for (int i = 0; i < 8; i++) {
        int t = tid + i * 256;
        v[i] = (t <= s) ? pr[t] * ATT_SCALE : -1e30f;
        m = fmaxf(m, v[i]);
    }
    __shared__ float red[8];
#pragma unroll
    for (int o = 16; o; o >>= 1) m = fmaxf(m, __shfl_xor_sync(0xffffffffu, m, o));
    if ((tid & 31) == 0) red[tid >> 5] = m;
    __syncthreads();
    m = red[0];
#pragma unroll
    for (int w = 1; w < 8; w++) m = fmaxf(m, red[w]);

    float sum = 0.f;
#pragma unroll
    for (int i = 0; i < 8; i++) {
        int t = tid + i * 256;
        v[i] = (t <= s) ? __expf(v[i] - m) : 0.f;
        sum += v[i];
    }
    __syncthreads();
#pragma unroll
    for (int o = 16; o; o >>= 1) sum += __shfl_xor_sync(0xffffffffu, sum, o);
    if ((tid & 31) == 0) red[tid >> 5] = sum;
    __syncthreads();
    sum = 0.f;
#pragma unroll
    for (int w = 0; w < 8; w++) sum += red[w];
    float inv = 1.f / sum;
#pragma unroll
    for (int i = 0; i < 8; i++)
        pr[tid + i * 256] = rne_tf32(v[i] * inv);
}

// ---------------- host: tensormap encode via dlopen(libcuda) -----------------
typedef CUresult (*PFN_tmEncode)(
    CUtensorMap*, CUtensorMapDataType, cuuint32_t, void*,
    const cuuint64_t*, const cuuint64_t*, const cuuint32_t*, const cuuint32_t*,
    CUtensorMapInterleave, CUtensorMapSwizzle, CUtensorMapL2promotion,
    CUtensorMapFloatOOBfill);

static PFN_tmEncode tm_encode()
{
    static PFN_tmEncode fn = nullptr;
    if (!fn) {
        void* h = dlopen("libcuda.so.1", RTLD_NOW | RTLD_GLOBAL);
        if (!h) h = dlopen("libcuda.so", RTLD_NOW | RTLD_GLOBAL);
        if (h) fn = (PFN_tmEncode)dlsym(h, "cuTensorMapEncodeTiled");
    }
    return fn;
}

static void make_map(CUtensorMap* m, void* base, long long cols, long long rows, long long ld)
{
    cuuint64_t dims[2]    = {(cuuint64_t)cols, (cuuint64_t)rows};
    cuuint64_t strides[1] = {(cuuint64_t)(ld * 4)};
    cuuint32_t box[2]     = {32u, 128u};
    cuuint32_t es[2]      = {1u, 1u};
    tm_encode()(m, CU_TENSOR_MAP_DATA_TYPE_FLOAT32, 2, base, dims, strides, box, es,
                CU_TENSOR_MAP_INTERLEAVE_NONE, CU_TENSOR_MAP_SWIZZLE_128B,
                CU_TENSOR_MAP_L2_PROMOTION_L2_128B, CU_TENSOR_MAP_FLOAT_OOB_FILL_NONE);
}

// ---------------------------------------------------------------------------
extern "C" void kernel_launch(void* const* d_in, const int* in_sizes, int n_in,
                              void* d_out, int out_size)
{
    (void)in_sizes; (void)n_in; (void)out_size;
    const float* x        = (const float*)d_in[0];
    const float* wq_a     = (const float*)d_in[1];
    const float* q_norm_w = (const float*)d_in[2];
    const float* wq_b     = (const float*)d_in[3];
    const float* wkv_a    = (const float*)d_in[4];
    const float* kv_norm_w= (const float*)d_in[5];
    const float* wkv_b    = (const float*)d_in[6];
    const float* wo       = (const float*)d_in[7];
    const float* cosp     = (const float*)d_in[8];
    const float* sinp     = (const float*)d_in[9];
    float* out = (float*)d_out;

    float *xr, *wqar, *wkvar, *wqbr, *wor, *wvr, *wnt;
    float *q1, *kvb, *kt, *q2, *qp, *pf, *oc, *ov;
    cudaGetSymbolAddress((void**)&xr,   g_xr);
    cudaGetSymbolAddress((void**)&wqar, g_wqar);
    cudaGetSymbolAddress((void**)&wkvar,g_wkvar);
    cudaGetSymbolAddress((void**)&wqbr, g_wqbr);
    cudaGetSymbolAddress((void**)&wor,  g_wor);
    cudaGetSymbolAddress((void**)&wvr,  g_wvr);
    cudaGetSymbolAddress((void**)&wnt,  g_wnt);
    cudaGetSymbolAddress((void**)&q1,   g_q1);
    cudaGetSymbolAddress((void**)&kvb,  g_kv);
    cudaGetSymbolAddress((void**)&kt,   g_kt);
    cudaGetSymbolAddress((void**)&q2,   g_q2);
    cudaGetSymbolAddress((void**)&qp,   g_qp);
    cudaGetSymbolAddress((void**)&pf,   g_pf);
    cudaGetSymbolAddress((void**)&oc,   g_oc);
    cudaGetSymbolAddress((void**)&ov,   g_ov);

    cudaFuncSetAttribute(gemm_tma, cudaFuncAttributeMaxDynamicSharedMemorySize, SMEM_TMA);

    dim3 t32(32, 8);
    // ---- prep: round everything to tf32 once ----
    round_copy<<<8192, 256>>>(x,     xr,    2097152);
    round_copy<<<3072, 256>>>(wq_a,  wqar,  786432);
    round_copy<<<1152, 256>>>(wkv_a, wkvar, 294912);
    round_copy<<<4608, 256>>>(wq_b,  wqbr,  1179648);
    round_copy<<<4096, 256>>>(wo,    wor,   1048576);
    round_wv<<<1024, 256>>>(wkv_b, wvr);
    transpose_round<<<dim3(16, 4, 16), t32>>>(wkv_b, wnt, 128, 512, 512, 131072, 65536);

    CUtensorMap mA, mB;

    // 1) q1 = x @ wq_a^T
    make_map(&mA, xr, 2048, 4096, 2048);
    make_map(&mB, wqar, 2048, 1536, 2048);
    gemm_tma<<<dim3(12, 32, 1), 256, SMEM_TMA>>>(mA, mB, 0, 0, 0, 0,
        q1, 1536, 0, 4096, 1536, 2048, 0, 0, 0);
    // 2) rmsnorm q1 (rounds)
    rmsnorm_rows<<<4096, 256>>>(q1, q_norm_w, 1536);
    // 3) kv = x @ wkv_a^T
    make_map(&mB, wkvar, 2048, 576, 2048);
    gemm_tma<<<dim3(5, 32, 1), 256, SMEM_TMA>>>(mA, mB, 0, 0, 0, 0,
        kvb, 576, 0, 4096, 576, 2048, 0, 0, 0);
    // 4) rmsnorm kv_c + rope k_pe (rounds)
    kv_process<<<4096, 128>>>(kvb, kv_norm_w, cosp, sinp);
    // 5) kv_c^T per batch -> kt [b][512][2048]
    transpose_round<<<dim3(16, 64, 2), t32>>>(kvb, kt, 2048, 512, 576,
        (long long)2048 * 576, (long long)512 * 2048);
    // 6) q2 = q1 @ wq_b^T (rounded out)
    make_map(&mA, q1, 1536, 4096, 1536);
    make_map(&mB, wqbr, 1536, 3072, 1536);
    gemm_tma<<<dim3(24, 32, 1), 256, SMEM_TMA>>>(mA, mB, 0, 0, 0, 0,
        q2, 3072, 0, 4096, 3072, 1536, 0, 0, 1);
    // 7) q_abs per head: q2[:, z*192 : +128] @ wnt[z] -> qp[:, z*576 : +512]
    make_map(&mA, q2, 3072, 4096, 3072);
    make_map(&mB, wnt, 128, 8192, 128);
    gemm_tma<<<dim3(4, 32, 16), 256, SMEM_TMA>>>(mA, mB, 192, 0, 0, 512,
        qp, 9216, 576, 4096, 512, 128, 0, 0, 1);
    // 8) rope q_pe -> qp[:, z*576+512 : +64] (rounded)
    rope_q<<<8192, 256>>>(q2, qp, cosp, sinp);
    // 9) scores per (b,z=h): P = Q' @ K'^T, causal tile skip
    for (int b = 0; b < 2; b++) {
        make_map(&mA, qp + (long long)b * CS * 9216, 9216, 2048, 9216);
        make_map(&mB, kvb + (long long)b * CS * 576, 576, 2048, 576);
        gemm_tma<<<dim3(16, 16, 16), 256, SMEM_TMA>>>(mA, mB, 576, 0, 0, 0,
            pf + (long long)b * CH * CS * CS, CS, (long long)CS * CS,
            2048, 2048, 576, 1, 0, 0);
    }
    // 10) softmax in-place (rounds)
    softmax_causal<<<2 * CH * CS, 256>>>(pf);
    // 11) O = P @ kv_c^T' (K clamped to m0+128, rounded out)
    for (int b = 0; b < 2; b++) {
        make_map(&mA, pf + (long long)b * CH * CS * CS, 2048, 32768, 2048);
        make_map(&mB, kt + (long long)b * 512 * 2048, 2048, 512, 2048);
        gemm_tma<<<dim3(4, 16, 16), 256, SMEM_TMA>>>(mA, mB, 0, 2048, 0, 0,
            oc + (long long)b * CS * 8192, 8192, 512,
            2048, 512, 2048, 0, 1, 1);
    }
    // 12) o_v per head: oc[:, z*512 : +512] @ wvr[z] -> ov[:, z*128 : +128]
    make_map(&mA, oc, 8192, 4096, 8192);
    make_map(&mB, wvr, 512, 2048, 512);
    gemm_tma<<<dim3(1, 32, 16), 256, SMEM_TMA>>>(mA, mB, 512, 0, 0, 128,
        ov, 2048, 128, 4096, 128, 512, 0, 0, 1);
    // 13) out = ov @ wo^T (full fp32 out)
    make_map(&mA, ov, 2048, 4096, 2048);
    make_map(&mB, wor, 2048, 2048, 2048);
    gemm_tma<<<dim3(16, 32, 1), 256, SMEM_TMA>>>(mA, mB, 0, 0, 0, 0,
        out, 2048, 0, 4096, 2048, 2048, 0, 0, 0);
}

// round 7
// speedup vs baseline: 2.3731x; 1.6776x over previous
#include <cuda_runtime.h>
#include <cuda_fp16.h>
#include <cuda.h>
#include <cstdint>
#include <dlfcn.h>

#define CS 2048
#define CH 16
#define ATT_SCALE 0.07216878364870323f   // 192^-0.5

// ---------------- scratch (device globals, fp16 operands) -------------------
__device__ __align__(256) __half g_xh [(size_t)4096*2048];
__device__ __align__(256) __half g_wqah[(size_t)1536*2048];
__device__ __align__(256) __half g_wkvah[(size_t)576*2048];
__device__ __align__(256) __half g_wqbh[(size_t)3072*1536];
__device__ __align__(256) __half g_woh[(size_t)2048*2048];
__device__ __align__(256) __half g_wvh[(size_t)16*128*512];
__device__ __align__(256) __half g_wnth[(size_t)16*512*128];
__device__ __align__(256) __half g_q1 [(size_t)4096*1536];
__device__ __align__(256) __half g_kv [(size_t)4096*576];
__device__ __align__(256) __half g_kt [(size_t)2*512*2048];
__device__ __align__(256) __half g_q2 [(size_t)4096*3072];
__device__ __align__(256) __half g_qp [(size_t)4096*9216];
__device__ __align__(256) float  g_pf [(size_t)2*CH*CS*CS];     // fp32 logits
__device__ __align__(256) __half g_ph [(size_t)2*CH*CS*CS];     // fp16 probs
__device__ __align__(256) __half g_oc [(size_t)4096*8192];
__device__ __align__(256) __half g_ov [(size_t)4096*2048];

// ---------------- ptx helpers ----------------
__device__ __forceinline__ void mma_fp16(float* c, const uint32_t* a, uint32_t b0, uint32_t b1) {
    asm volatile(
        "mma.sync.aligned.m16n8k16.row.col.f32.f16.f16.f32 "
        "{%0,%1,%2,%3},{%4,%5,%6,%7},{%8,%9},{%0,%1,%2,%3};"
        : "+f"(c[0]), "+f"(c[1]), "+f"(c[2]), "+f"(c[3])
        : "r"(a[0]), "r"(a[1]), "r"(a[2]), "r"(a[3]), "r"(b0), "r"(b1));
}
#define MBAR_INIT(a, c) \
    asm volatile("mbarrier.init.shared.b64 [%0], %1;" :: "r"(a), "r"(c) : "memory")
#define MBAR_EXPECT(a, tx) \
    asm volatile("mbarrier.arrive.expect_tx.shared.b64 _, [%0], %1;" :: "r"(a), "r"(tx) : "memory")
#define MBAR_WAIT(a, ph) do { \
    asm volatile("{\n\t.reg .pred P1;\n\tWL%=:\n\t" \
        "mbarrier.try_wait.parity.acquire.cta.shared::cta.b64 P1, [%0], %1, 0x989680;\n\t" \
        "@P1 bra.uni WD%=;\n\tbra.uni WL%=;\n\tWD%=:\n\t}" \
        :: "r"(a), "r"(ph) : "memory"); } while (0)
__device__ __forceinline__ void tma2d(uint32_t dst, const void* map, int x, int y, uint32_t mbar) {
    asm volatile(
        "cp.async.bulk.tensor.2d.shared::cta.global.tile.mbarrier::complete_tx::bytes "
        "[%0], [%1, {%2, %3}], [%4];"
        :: "r"(dst), "l"(map), "r"(x), "r"(y), "r"(mbar) : "memory");
}

// ---------------- TMA fp16 GEMM: C[m,n] = sum_k A[m,k]*B[n,k] ----------------
// A,B fp16 via 2D tensormaps (SW128, box [64,128] halves = 128B rows).
// 128x128x64 CTA k-chunk, 8 warps (4x2), warp tile 32x64, m16n8k16.
// 3-stage mbarrier pipeline. Output: fp32 (Cf) or fp16 (Ch).
#define NST 3
#define STAGE 32768
#define SMEM_TMA (1024 + NST * STAGE)

__global__ __launch_bounds__(256, 2) void gemm_h(
    const __grid_constant__ CUtensorMap mA,
    const __grid_constant__ CUtensorMap mB,
    int axz, int ayz, int bxz, int byz,
    float* __restrict__ Cf, __half* __restrict__ Chh,
    int ldc, long long strC,
    int M, int N, int K, int causal, int kclamp)
{
    int bm = blockIdx.y, bn = blockIdx.x;
    if (causal && bn > bm) return;
    int z = blockIdx.z;
    if (Cf) Cf += (long long)z * strC;
    else    Chh += (long long)z * strC;
    int m0 = bm * 128, n0 = bn * 128;
    int Keff = kclamp ? (K < m0 + 128 ? K : m0 + 128) : K;
    int ntk = Keff >> 6;

    extern __shared__ __align__(1024) char smem[];
    uint32_t sbase = (uint32_t)__cvta_generic_to_shared(smem);

    int tid = threadIdx.x;
    int wid = tid >> 5, lane = tid & 31;
    int wm = wid >> 1, wn = wid & 1;
    int g = lane >> 2, tg = lane & 3;

    if (tid == 0) {
#pragma unroll
        for (int s = 0; s < NST; s++) MBAR_INIT(sbase + s * 8, 1);
    }
    __syncthreads();

    int xa = z * axz, ya = m0 + z * ayz;
    int xb = z * bxz, yb = n0 + z * byz;

    auto issue = [&](int j, int jb) {
        uint32_t mb = sbase + jb * 8;
        uint32_t da = sbase + 1024 + jb * STAGE;
        int k0 = j * 64;
        MBAR_EXPECT(mb, STAGE);
        tma2d(da, &mA, xa + k0, ya, mb);
        tma2d(da + 16384, &mB, xb + k0, yb, mb);
    };

    if (tid == 0) {
        issue(0, 0);
        if (ntk > 1) issue(1, 1);
    }

    float acc[2][8][4];
#pragma unroll
    for (int mi = 0; mi < 2; mi++)
#pragma unroll
        for (int j = 0; j < 8; j++)
#pragma unroll
            for (int r = 0; r < 4; r++) acc[mi][j][r] = 0.f;

    uint32_t xorv = (uint32_t)g << 4;
    int buf = 0, ph = 0;
    int pj = NST - 1, pbuf = NST - 1;

    for (int kt = 0; kt < ntk; kt++) {
        MBAR_WAIT(sbase + buf * 8, ph);
        const char* As = smem + 1024 + buf * STAGE;
        const char* Bs = As + 16384;
#pragma unroll
        for (int ks = 0; ks < 4; ks++) {
            uint32_t kb = (uint32_t)(ks * 32 + tg * 4);
            uint32_t c0 = kb ^ xorv;
            uint32_t c1 = (kb + 16u) ^ xorv;
            uint32_t a[2][4];
#pragma unroll
            for (int mi = 0; mi < 2; mi++) {
                int r = wm * 32 + mi * 16 + g;
                a[mi][0] = *(const uint32_t*)(As + r * 128 + c0);
                a[mi][1] = *(const uint32_t*)(As + (r + 8) * 128 + c0);
                a[mi][2] = *(const uint32_t*)(As + r * 128 + c1);
                a[mi][3] = *(const uint32_t*)(As + (r + 8) * 128 + c1);
            }
#pragma unroll
            for (int j = 0; j < 8; j++) {
                int c = wn * 64 + j * 8 + g;
                uint32_t b0 = *(const uint32_t*)(Bs + c * 128 + c0);
                uint32_t b1 = *(const uint32_t*)(Bs + c * 128 + c1);
                mma_fp16(acc[0][j], a[0], b0, b1);
                mma_fp16(acc[1][j], a[1], b0, b1);
            }
        }
        __syncthreads();
        if (tid == 0 && pj < ntk) issue(pj, pbuf);
        pj++;
        if (++pbuf == NST) pbuf = 0;
        if (++buf == NST) { buf = 0; ph ^= 1; }
    }

    // epilogue
#pragma unroll
    for (int mi = 0; mi < 2; mi++) {
#pragma unroll
        for (int j = 0; j < 8; j++) {
            int row = m0 + wm * 32 + mi * 16 + g;
            int col = n0 + wn * 64 + j * 8 + 2 * tg;
            if (col < N) {
                float v0 = acc[mi][j][0], v1 = acc[mi][j][1];
                float v2 = acc[mi][j][2], v3 = acc[mi][j][3];
                if (Cf) {
                    *(float2*)&Cf[(long long)row * ldc + col] = make_float2(v0, v1);
                    *(float2*)&Cf[(long long)(row + 8) * ldc + col] = make_float2(v2, v3);
                } else {
                    *(__half2*)&Chh[(long long)row * ldc + col] = __floats2half2_rn(v0, v1);
                    *(__half2*)&Chh[(long long)(row + 8) * ldc + col] = __floats2half2_rn(v2, v3);
                }
            }
        }
    }
}

// ---------------- prep: fp32 -> fp16 copies / transposes ---------------------
__global__ void f2h_copy(const float* __restrict__ s, __half* __restrict__ d, long long n4)
{
    long long i = (long long)blockIdx.x * 256 + threadIdx.x;
    if (i >= n4) return;
    float4 v = ((const float4*)s)[i];
    __half2 h0 = __floats2half2_rn(v.x, v.y);
    __half2 h1 = __floats2half2_rn(v.z, v.w);
    ((uint2*)d)[i] = make_uint2(*(uint32_t*)&h0, *(uint32_t*)&h1);
}

__global__ void f2h_wv(const float* __restrict__ wkvb, __half* __restrict__ d)
{
    long long i4 = (long long)blockIdx.x * 256 + threadIdx.x;
    long long head = i4 >> 14, off = (i4 & 16383) * 4;
    float4 v = *(const float4*)(wkvb + head * 131072 + 65536 + off);
    __half2 h0 = __floats2half2_rn(v.x, v.y);
    __half2 h1 = __floats2half2_rn(v.z, v.w);
    ((uint2*)d)[i4] = make_uint2(*(uint32_t*)&h0, *(uint32_t*)&h1);
}

// fp32 src transpose -> fp16 dst: per z, src[R][sld] -> dst[C][R]
__global__ void transpose_f2h(const float* __restrict__ src, __half* __restrict__ dst,
                              int R, int C, int sld, long long sstr, long long dstr)
{
    __shared__ float tile[32][33];
    src += (long long)blockIdx.z * sstr;
    dst += (long long)blockIdx.z * dstr;
    int c0 = blockIdx.x * 32, r0 = blockIdx.y * 32;
    int x = threadIdx.x, y = threadIdx.y;
#pragma unroll
    for (int j = 0; j < 32; j += 8)
        tile[y + j][x] = src[(long long)(r0 + y + j) * sld + c0 + x];
    __syncthreads();
#pragma unroll
    for (int j = 0; j < 32; j += 8)
        dst[(long long)(c0 + y + j) * R + r0 + x] = __float2half_rn(tile[x][y + j]);
}

// fp16 transpose: per z, src[R][sld] (first C cols) -> dst[C][R]
__global__ void transpose_h(const __half* __restrict__ src, __half* __restrict__ dst,
                            int R, int C, int sld, long long sstr, long long dstr)
{
    __shared__ __half tile[32][34];
    src += (long long)blockIdx.z * sstr;
    dst += (long long)blockIdx.z * dstr;
    int c0 = blockIdx.x * 32, r0 = blockIdx.y * 32;
    int x = threadIdx.x, y = threadIdx.y;
#pragma unroll
    for (int j = 0; j < 32; j += 8)
        tile[y + j][x] = src[(long long)(r0 + y + j) * sld + c0 + x];
    __syncthreads();
#pragma unroll
    for (int j = 0; j < 32; j += 8)
        dst[(long long)(c0 + y + j) * R + r0 + x] = tile[x][y + j];
}

// ---------------- rmsnorm rows (fp16 data, fp32 math) ------------------------
__global__ void rmsnorm_h(__half* __restrict__ x, const float* __restrict__ w, int n)
{
    long long row = blockIdx.x;
    __half* r = x + row * n;
    float ss = 0.f;
    for (int i = threadIdx.x; i < n; i += 256) { float v = __half2float(r[i]); ss += v * v; }
    __shared__ float red[8];
#pragma unroll
    for (int o = 16; o; o >>= 1) ss += __shfl_xor_sync(0xffffffffu, ss, o);
    if ((threadIdx.x & 31) == 0) red[threadIdx.x >> 5] = ss;
    __syncthreads();
    float tot = 0.f;
#pragma unroll
    for (int wv = 0; wv < 8; wv++) tot += red[wv];
    float scale = rsqrtf(tot / (float)n + 1e-6f);
    for (int i = threadIdx.x; i < n; i += 256)
        r[i] = __float2half_rn(__half2float(r[i]) * scale * w[i]);
}

// -------- kv row: rmsnorm first 512 (+w), rope last 64 (fp16 data) -----------
__global__ void kv_process_h(__half* __restrict__ kv, const float* __restrict__ w,
                             const float* __restrict__ cosp, const float* __restrict__ sinp)
{
    int row = blockIdx.x;
    int s = row % CS;
    __half* r = kv + (long long)row * 576;
    float ss = 0.f;
    for (int i = threadIdx.x; i < 512; i += 128) { float v = __half2float(r[i]); ss += v * v; }
    __shared__ float red[4];
#pragma unroll
    for (int o = 16; o; o >>= 1) ss += __shfl_xor_sync(0xffffffffu, ss, o);
    if ((threadIdx.x & 31) == 0) red[threadIdx.x >> 5] = ss;
    __syncthreads();
    float tot = red[0] + red[1] + red[2] + red[3];
    float scale = rsqrtf(tot / 512.f + 1e-6f);
    for (int i = threadIdx.x; i < 512; i += 128)
        r[i] = __float2half_rn(__half2float(r[i]) * scale * w[i]);
    if (threadIdx.x < 32) {
        int i = threadIdx.x;
        float x0 = __half2float(r[512 + 2 * i]), x1 = __half2float(r[513 + 2 * i]);
        float c = cosp[s * 32 + i], sn = sinp[s * 32 + i];
        r[512 + 2 * i] = __float2half_rn(x0 * c - x1 * sn);
        r[513 + 2 * i] = __float2half_rn(x0 * sn + x1 * c);
    }
}

// ---------------- RoPE on q_pe: q2 -> qp (fp16) ------------------------------
__global__ void rope_q_h(const __half* __restrict__ q2, __half* __restrict__ qp,
                         const float* __restrict__ cosp, const float* __restrict__ sinp)
{
    int idx = blockIdx.x * 256 + threadIdx.x;
    if (idx >= 4096 * CH * 32) return;
    int i = idx & 31;
    int h = (idx >> 5) & 15;
    int row = idx >> 9;
    int s = row % CS;
    const __half* src = q2 + (long long)row * 3072 + h * 192 + 128 + 2 * i;
    float x0 = __half2float(src[0]), x1 = __half2float(src[1]);
    float c = cosp[s * 32 + i], sn = sinp[s * 32 + i];
    __half* dst = qp + (long long)row * 9216 + h * 576 + 512 + 2 * i;
    dst[0] = __float2half_rn(x0 * c - x1 * sn);
    dst[1] = __float2half_rn(x0 * sn + x1 * c);
}

// ---------------- causal softmax: fp32 logits -> fp16 probs ------------------
// writes only t < limit = next 128-boundary above s (PV never reads beyond).
__global__ __launch_bounds__(256) void softmax_h(
    const float* __restrict__ P, __half* __restrict__ Ph)
{
    int row = blockIdx.x;
    int s = row & (CS - 1);
    const float* pr = P + (long long)row * CS;
    __half* oh = Ph + (long long)row * CS;
    int tid = threadIdx.x;
    int limit = ((s >> 7) + 1) << 7;

    float v[8];
    float m = -1e30f;
#pragma unroll
    for (int i = 0; i < 8; i++) {
        int t = tid + i * 256;
        v[i] = (t <= s) ? pr[t] * ATT_SCALE : -1e30f;
        m = fmaxf(m, v[i]);
    }
    __shared__ float red[8];
#pragma unroll
    for (int o = 16; o; o >>= 1) m = fmaxf(m, __shfl_xor_sync(0xffffffffu, m, o));
    if ((tid & 31) == 0) red[tid >> 5] = m;
    __syncthreads();
    m = red[0];
#pragma unroll
    for (int w = 1; w < 8; w++) m = fmaxf(m, red[w]);

    float sum = 0.f;
#pragma unroll
    for (int i = 0; i < 8; i++) {
        int t = tid + i * 256;
        v[i] = (t <= s) ? __expf(v[i] - m) : 0.f;
        sum += v[i];
    }
    __syncthreads();
#pragma unroll
    for (int o = 16; o; o >>= 1) sum += __shfl_xor_sync(0xffffffffu, sum, o);
    if ((tid & 31) == 0) red[tid >> 5] = sum;
    __syncthreads();
    sum = 0.f;
#pragma unroll
    for (int w = 0; w < 8; w++) sum += red[w];
    float inv = 1.f / sum;
#pragma unroll
    for (int i = 0; i < 8; i++) {
        int t = tid + i * 256;
        if (t < limit) oh[t] = __float2half_rn(v[i] * inv);
    }
}

// ---------------- host: tensormap encode via dlopen(libcuda) -----------------
typedef CUresult (*PFN_tmEncode)(
    CUtensorMap*, CUtensorMapDataType, cuuint32_t, void*,
    const cuuint64_t*, const cuuint64_t*, const cuuint32_t*, const cuuint32_t*,
    CUtensorMapInterleave, CUtensorMapSwizzle, CUtensorMapL2promotion,
    CUtensorMapFloatOOBfill);

static PFN_tmEncode tm_encode()
{
    static PFN_tmEncode fn = nullptr;
    if (!fn) {
        void* h = dlopen("libcuda.so.1", RTLD_NOW | RTLD_GLOBAL);
        if (!h) h = dlopen("libcuda.so", RTLD_NOW | RTLD_GLOBAL);
        if (h) fn = (PFN_tmEncode)dlsym(h, "cuTensorMapEncodeTiled");
    }
    return fn;
}

static void make_map_h(CUtensorMap* m, void* base, long long cols, long long rows, long long ld)
{
    cuuint64_t dims[2]    = {(cuuint64_t)cols, (cuuint64_t)rows};
    cuuint64_t strides[1] = {(cuuint64_t)(ld * 2)};
    cuuint32_t box[2]     = {64u, 128u};
    cuuint32_t es[2]      = {1u, 1u};
    tm_encode()(m, CU_TENSOR_MAP_DATA_TYPE_FLOAT16, 2, base, dims, strides, box, es,
                CU_TENSOR_MAP_INTERLEAVE_NONE, CU_TENSOR_MAP_SWIZZLE_128B,
                CU_TENSOR_MAP_L2_PROMOTION_L2_128B, CU_TENSOR_MAP_FLOAT_OOB_FILL_NONE);
}

// ---------------------------------------------------------------------------
extern "C" void kernel_launch(void* const* d_in, const int* in_sizes, int n_in,
                              void* d_out, int out_size)
{
    (void)in_sizes; (void)n_in; (void)out_size;
    const float* x        = (const float*)d_in[0];
    const float* wq_a     = (const float*)d_in[1];
    const float* q_norm_w = (const float*)d_in[2];
    const float* wq_b     = (const float*)d_in[3];
    const float* wkv_a    = (const float*)d_in[4];
    const float* kv_norm_w= (const float*)d_in[5];
    const float* wkv_b    = (const float*)d_in[6];
    const float* wo       = (const float*)d_in[7];
    const float* cosp     = (const float*)d_in[8];
    const float* sinp     = (const float*)d_in[9];
    float* out = (float*)d_out;

    __half *xh, *wqah, *wkvah, *wqbh, *woh, *wvh, *wnth;
    __half *q1, *kvb, *kt, *q2, *qp, *phh, *oc, *ov;
    float* pf;
    cudaGetSymbolAddress((void**)&xh,   g_xh);
    cudaGetSymbolAddress((void**)&wqah, g_wqah);
    cudaGetSymbolAddress((void**)&wkvah,g_wkvah);
    cudaGetSymbolAddress((void**)&wqbh, g_wqbh);
    cudaGetSymbolAddress((void**)&woh,  g_woh);
    cudaGetSymbolAddress((void**)&wvh,  g_wvh);
    cudaGetSymbolAddress((void**)&wnth, g_wnth);
    cudaGetSymbolAddress((void**)&q1,   g_q1);
    cudaGetSymbolAddress((void**)&kvb,  g_kv);
    cudaGetSymbolAddress((void**)&kt,   g_kt);
    cudaGetSymbolAddress((void**)&q2,   g_q2);
    cudaGetSymbolAddress((void**)&qp,   g_qp);
    cudaGetSymbolAddress((void**)&pf,   g_pf);
    cudaGetSymbolAddress((void**)&phh,  g_ph);
    cudaGetSymbolAddress((void**)&oc,   g_oc);
    cudaGetSymbolAddress((void**)&ov,   g_ov);

    cudaFuncSetAttribute(gemm_h, cudaFuncAttributeMaxDynamicSharedMemorySize, SMEM_TMA);

    dim3 t32(32, 8);
    // ---- prep: convert inputs/weights to fp16 once ----
    f2h_copy<<<8192, 256>>>(x,     xh,    2097152);
    f2h_copy<<<3072, 256>>>(wq_a,  wqah,  786432);
    f2h_copy<<<1152, 256>>>(wkv_a, wkvah, 294912);
    f2h_copy<<<4608, 256>>>(wq_b,  wqbh,  1179648);
    f2h_copy<<<4096, 256>>>(wo,    woh,   1048576);
    f2h_wv<<<1024, 256>>>(wkv_b, wvh);
    transpose_f2h<<<dim3(16, 4, 16), t32>>>(wkv_b, wnth, 128, 512, 512, 131072, 65536);

    CUtensorMap mA, mB;

    // 1) q1 = x @ wq_a^T
    make_map_h(&mA, xh, 2048, 4096, 2048);
    make_map_h(&mB, wqah, 2048, 1536, 2048);
    gemm_h<<<dim3(12, 32, 1), 256, SMEM_TMA>>>(mA, mB, 0, 0, 0, 0,
        nullptr, q1, 1536, 0, 4096, 1536, 2048, 0, 0);
    // 2) rmsnorm q1
    rmsnorm_h<<<4096, 256>>>(q1, q_norm_w, 1536);
    // 3) kv = x @ wkv_a^T
    make_map_h(&mB, wkvah, 2048, 576, 2048);
    gemm_h<<<dim3(5, 32, 1), 256, SMEM_TMA>>>(mA, mB, 0, 0, 0, 0,
        nullptr, kvb, 576, 0, 4096, 576, 2048, 0, 0);
    // 4) rmsnorm kv_c + rope k_pe
    kv_process_h<<<4096, 128>>>(kvb, kv_norm_w, cosp, sinp);
    // 5) kv_c^T per batch -> kt [b][512][2048]
    transpose_h<<<dim3(16, 64, 2), t32>>>(kvb, kt, 2048, 512, 576,
        (long long)2048 * 576, (long long)512 * 2048);
    // 6) q2 = q1 @ wq_b^T
    make_map_h(&mA, q1, 1536, 4096, 1536);
    make_map_h(&mB, wqbh, 1536, 3072, 1536);
    gemm_h<<<dim3(24, 32, 1), 256, SMEM_TMA>>>(mA, mB, 0, 0, 0, 0,
        nullptr, q2, 3072, 0, 4096, 3072, 1536, 0, 0);
    // 7) q_abs per head: q2[:, z*192:+128] @ wnth[z] -> qp[:, z*576:+512]
    make_map_h(&mA, q2, 3072, 4096, 3072);
    make_map_h(&mB, wnth, 128, 8192, 128);
    gemm_h<<<dim3(4, 32, 16), 256, SMEM_TMA>>>(mA, mB, 192, 0, 0, 512,
        nullptr, qp, 9216, 576, 4096, 512, 128, 0, 0);
    // 8) rope q_pe -> qp[:, z*576+512:+64]
    rope_q_h<<<8192, 256>>>(q2, qp, cosp, sinp);
    // 9) scores per (b, z=h): P = Q' @ K'^T, causal tile skip (fp32 out)
    for (int b = 0; b < 2; b++) {
        make_map_h(&mA, qp + (long long)b * CS * 9216, 9216, 2048, 9216);
        make_map_h(&mB, kvb + (long long)b * CS * 576, 576, 2048, 576);
        gemm_h<<<dim3(16, 16, 16), 256, SMEM_TMA>>>(mA, mB, 576, 0, 0, 0,
            pf + (long long)b * CH * CS * CS, nullptr, CS, (long long)CS * CS,
            2048, 2048, 576, 1, 0);
    }
    // 10) softmax: fp32 logits -> fp16 probs (clamped writes)
    softmax_h<<<2 * CH * CS, 256>>>(pf, phh);
    // 11) O = P @ kv_c^T' (K clamped to m0+128)
    for (int b = 0; b < 2; b++) {
        make_map_h(&mA, phh + (long long)b * CH * CS * CS, 2048, 32768, 2048);
        make_map_h(&mB, kt + (long long)b * 512 * 2048, 2048, 512, 2048);
        gemm_h<<<dim3(4, 16, 16), 256, SMEM_TMA>>>(mA, mB, 0, 2048, 0, 0,
            nullptr, oc + (long long)b * CS * 8192, 8192, 512,
            2048, 512, 2048, 0, 1);
    }
    // 12) o_v per head: oc[:, z*512:+512] @ wvh[z] -> ov[:, z*128:+128]
    make_map_h(&mA, oc, 8192, 4096, 8192);
    make_map_h(&mB, wvh, 512, 2048, 512);
    gemm_h<<<dim3(1, 32, 16), 256, SMEM_TMA>>>(mA, mB, 512, 0, 0, 128,
        nullptr, ov, 2048, 128, 4096, 128, 512, 0, 0);
    // 13) out = ov @ wo^T (fp32 out)
    make_map_h(&mA, ov, 2048, 4096, 2048);
    make_map_h(&mB, woh, 2048, 2048, 2048);
    gemm_h<<<dim3(16, 32, 1), 256, SMEM_TMA>>>(mA, mB, 0, 0, 0, 0,
        out, nullptr, 2048, 0, 4096, 2048, 2048, 0, 0);
}

// round 8
// speedup vs baseline: 3.2909x; 1.3868x over previous
#include <cuda_runtime.h>
#include <cuda_fp16.h>
#include <cuda.h>
#include <cstdint>
#include <dlfcn.h>

#define CS 2048
#define CH 16
#define ATT_SCALE 0.07216878364870323f   // 192^-0.5

// ---------------- scratch (device globals, fp16 operands) -------------------
__device__ __align__(256) __half g_xh [(size_t)4096*2048];
__device__ __align__(256) __half g_wqah[(size_t)1536*2048];
__device__ __align__(256) __half g_wkvah[(size_t)576*2048];
__device__ __align__(256) __half g_wqbh[(size_t)3072*1536];
__device__ __align__(256) __half g_woh[(size_t)2048*2048];
__device__ __align__(256) __half g_wvh[(size_t)16*128*512];   // w_v per head [128][512]
__device__ __align__(256) __half g_wnh[(size_t)16*128*512];   // w_nope per head [128][512]
__device__ __align__(256) __half g_q1 [(size_t)4096*1536];
__device__ __align__(256) __half g_kv [(size_t)4096*576];
__device__ __align__(256) __half g_q2 [(size_t)4096*3072];    // rope applied in place
__device__ __align__(256) __half g_kp [(size_t)4096*3072];    // per-head K: [b*2048+t][h*192+d]
__device__ __align__(256) __half g_vt [(size_t)32*128*2048];  // per (b,h): V^T [128][2048]
__device__ __align__(256) float  g_pf [(size_t)2*CH*CS*CS];   // fp32 logits
__device__ __align__(256) __half g_ph [(size_t)2*CH*CS*CS];   // fp16 probs
__device__ __align__(256) __half g_ov [(size_t)4096*2048];

// ---------------- ptx helpers ----------------
__device__ __forceinline__ void mma_fp16(float* c, const uint32_t* a, uint32_t b0, uint32_t b1) {
    asm volatile(
        "mma.sync.aligned.m16n8k16.row.col.f32.f16.f16.f32 "
        "{%0,%1,%2,%3},{%4,%5,%6,%7},{%8,%9},{%0,%1,%2,%3};"
        : "+f"(c[0]), "+f"(c[1]), "+f"(c[2]), "+f"(c[3])
        : "r"(a[0]), "r"(a[1]), "r"(a[2]), "r"(a[3]), "r"(b0), "r"(b1));
}
#define MBAR_INIT(a, c) \
    asm volatile("mbarrier.init.shared.b64 [%0], %1;" :: "r"(a), "r"(c) : "memory")
#define MBAR_EXPECT(a, tx) \
    asm volatile("mbarrier.arrive.expect_tx.shared.b64 _, [%0], %1;" :: "r"(a), "r"(tx) : "memory")
#define MBAR_WAIT(a, ph) do { \
    asm volatile("{\n\t.reg .pred P1;\n\tWL%=:\n\t" \
        "mbarrier.try_wait.parity.acquire.cta.shared::cta.b64 P1, [%0], %1, 0x989680;\n\t" \
        "@P1 bra.uni WD%=;\n\tbra.uni WL%=;\n\tWD%=:\n\t}" \
        :: "r"(a), "r"(ph) : "memory"); } while (0)
__device__ __forceinline__ void tma2d(uint32_t dst, const void* map, int x, int y, uint32_t mbar) {
    asm volatile(
        "cp.async.bulk.tensor.2d.shared::cta.global.tile.mbarrier::complete_tx::bytes "
        "[%0], [%1, {%2, %3}], [%4];"
        :: "r"(dst), "l"(map), "r"(x), "r"(y), "r"(mbar) : "memory");
}

// ---------------- TMA fp16 GEMM: C[m,n] = sum_k A[m,k]*B[n,k] ----------------
// A,B fp16 via 2D tensormaps (SW128, box [64,128]). 128x128 tile, k-chunk 64,
// 8 warps (4x2), warp tile 32x64, m16n8k16, 3-stage mbarrier pipeline.
// z decomposed: zh = z&15, zb = z>>4; per-z coordinate offsets for A/B/C.
// causal: skip bn > bm. kclamp: Keff = min(K, m0+128), heavy tiles first.
#define NST 3
#define STAGE 32768
#define SMEM_TMA (1024 + NST * STAGE)

__global__ __launch_bounds__(256, 2) void gemm_h(
    const __grid_constant__ CUtensorMap mA,
    const __grid_constant__ CUtensorMap mB,
    int axh, int ayh, int axb, int ayb,
    int bxh, int byh, int bxb, int byb,
    float* __restrict__ Cf, __half* __restrict__ Chh,
    int ldc, long long strCh, long long strCb,
    int M, int N, int K, int causal, int kclamp)
{
    int bm = blockIdx.y, bn = blockIdx.x;
    if (kclamp) bm = gridDim.y - 1 - bm;      // heavy tiles first
    if (causal && bn > bm) return;
    int zh = blockIdx.z & 15, zb = blockIdx.z >> 4;
    if (Cf) Cf += (long long)zh * strCh + (long long)zb * strCb;
    else    Chh += (long long)zh * strCh + (long long)zb * strCb;
    int m0 = bm * 128, n0 = bn * 128;
    int Keff = kclamp ? (K < m0 + 128 ? K : m0 + 128) : K;
    int ntk = Keff >> 6;

    extern __shared__ __align__(1024) char smem[];
    uint32_t sbase = (uint32_t)__cvta_generic_to_shared(smem);

    int tid = threadIdx.x;
    int wid = tid >> 5, lane = tid & 31;
    int wm = wid >> 1, wn = wid & 1;
    int g = lane >> 2, tg = lane & 3;

    if (tid == 0) {
#pragma unroll
        for (int s = 0; s < NST; s++) MBAR_INIT(sbase + s * 8, 1);
    }
    __syncthreads();

    int xa = zh * axh + zb * axb, ya = m0 + zh * ayh + zb * ayb;
    int xb = zh * bxh + zb * bxb, yb = n0 + zh * byh + zb * byb;

    auto issue = [&](int j, int jb) {
        uint32_t mb = sbase + jb * 8;
        uint32_t da = sbase + 1024 + jb * STAGE;
        int k0 = j * 64;
        MBAR_EXPECT(mb, STAGE);
        tma2d(da, &mA, xa + k0, ya, mb);
        tma2d(da + 16384, &mB, xb + k0, yb, mb);
    };

    if (tid == 0) {
        issue(0, 0);
        if (ntk > 1) issue(1, 1);
    }

    float acc[2][8][4];
#pragma unroll
    for (int mi = 0; mi < 2; mi++)
#pragma unroll
        for (int j = 0; j < 8; j++)
#pragma unroll
            for (int r = 0; r < 4; r++) acc[mi][j][r] = 0.f;

    uint32_t xorv = (uint32_t)g << 4;
    int buf = 0, ph = 0;
    int pj = NST - 1, pbuf = NST - 1;

    for (int kt = 0; kt < ntk; kt++) {
        MBAR_WAIT(sbase + buf * 8, ph);
        const char* As = smem + 1024 + buf * STAGE;
        const char* Bs = As + 16384;
#pragma unroll
        for (int ks = 0; ks < 4; ks++) {
            uint32_t kb = (uint32_t)(ks * 32 + tg * 4);
            uint32_t c0 = kb ^ xorv;
            uint32_t c1 = (kb + 16u) ^ xorv;
            uint32_t a[2][4];
#pragma unroll
            for (int mi = 0; mi < 2; mi++) {
                int r = wm * 32 + mi * 16 + g;
                a[mi][0] = *(const uint32_t*)(As + r * 128 + c0);
                a[mi][1] = *(const uint32_t*)(As + (r + 8) * 128 + c0);
                a[mi][2] = *(const uint32_t*)(As + r * 128 + c1);
                a[mi][3] = *(const uint32_t*)(As + (r + 8) * 128 + c1);
            }
#pragma unroll
            for (int j = 0; j < 8; j++) {
                int c = wn * 64 + j * 8 + g;
                uint32_t b0 = *(const uint32_t*)(Bs + c * 128 + c0);
                uint32_t b1 = *(const uint32_t*)(Bs + c * 128 + c1);
                mma_fp16(acc[0][j], a[0], b0, b1);
                mma_fp16(acc[1][j], a[1], b0, b1);
            }
        }
        __syncthreads();
        if (tid == 0 && pj < ntk) issue(pj, pbuf);
        pj++;
        if (++pbuf == NST) pbuf = 0;
        if (++buf == NST) { buf = 0; ph ^= 1; }
    }

    // epilogue
#pragma unroll
    for (int mi = 0; mi < 2; mi++) {
#pragma unroll
        for (int j = 0; j < 8; j++) {
            int row = m0 + wm * 32 + mi * 16 + g;
            int col = n0 + wn * 64 + j * 8 + 2 * tg;
            if (col < N) {
                float v0 = acc[mi][j][0], v1 = acc[mi][j][1];
                float v2 = acc[mi][j][2], v3 = acc[mi][j][3];
                if (Cf) {
                    *(float2*)&Cf[(long long)row * ldc + col] = make_float2(v0, v1);
                    *(float2*)&Cf[(long long)(row + 8) * ldc + col] = make_float2(v2, v3);
                } else {
                    *(__half2*)&Chh[(long long)row * ldc + col] = __floats2half2_rn(v0, v1);
                    *(__half2*)&Chh[(long long)(row + 8) * ldc + col] = __floats2half2_rn(v2, v3);
                }
            }
        }
    }
}

// ---------------- prep: fp32 -> fp16 copies ----------------------------------
__global__ void f2h_copy(const float* __restrict__ s, __half* __restrict__ d, long long n4)
{
    long long i = (long long)blockIdx.x * 256 + threadIdx.x;
    if (i >= n4) return;
    float4 v = ((const float4*)s)[i];
    __half2 h0 = __floats2half2_rn(v.x, v.y);
    __half2 h1 = __floats2half2_rn(v.z, v.w);
    ((uint2*)d)[i] = make_uint2(*(uint32_t*)&h0, *(uint32_t*)&h1);
}

// per-head slice of wkv_b: head h, 65536 floats at h*131072 + srcOff
__global__ void f2h_head(const float* __restrict__ wkvb, __half* __restrict__ d, int srcOff)
{
    long long i4 = (long long)blockIdx.x * 256 + threadIdx.x;
    long long head = i4 >> 14, off = (i4 & 16383) * 4;
    float4 v = *(const float4*)(wkvb + head * 131072 + srcOff + off);
    __half2 h0 = __floats2half2_rn(v.x, v.y);
    __half2 h1 = __floats2half2_rn(v.z, v.w);
    ((uint2*)d)[i4] = make_uint2(*(uint32_t*)&h0, *(uint32_t*)&h1);
}

// ---------------- rmsnorm rows (fp16 data, fp32 math) ------------------------
__global__ void rmsnorm_h(__half* __restrict__ x, const float* __restrict__ w, int n)
{
    long long row = blockIdx.x;
    __half* r = x + row * n;
    float ss = 0.f;
    for (int i = threadIdx.x; i < n; i += 256) { float v = __half2float(r[i]); ss += v * v; }
    __shared__ float red[8];
#pragma unroll
    for (int o = 16; o; o >>= 1) ss += __shfl_xor_sync(0xffffffffu, ss, o);
    if ((threadIdx.x & 31) == 0) red[threadIdx.x >> 5] = ss;
    __syncthreads();
    float tot = 0.f;
#pragma unroll
    for (int wv = 0; wv < 8; wv++) tot += red[wv];
    float scale = rsqrtf(tot / (float)n + 1e-6f);
    for (int i = threadIdx.x; i < n; i += 256)
        r[i] = __float2half_rn(__half2float(r[i]) * scale * w[i]);
}

// -------- kv row: rmsnorm first 512 (+w), rope last 64 (fp16 data) -----------
__global__ void kv_process_h(__half* __restrict__ kv, const float* __restrict__ w,
                             const float* __restrict__ cosp, const float* __restrict__ sinp)
{
    int row = blockIdx.x;
    int s = row % CS;
    __half* r = kv + (long long)row * 576;
    float ss = 0.f;
    for (int i = threadIdx.x; i < 512; i += 128) { float v = __half2float(r[i]); ss += v * v; }
    __shared__ float red[4];
#pragma unroll
    for (int o = 16; o; o >>= 1) ss += __shfl_xor_sync(0xffffffffu, ss, o);
    if ((threadIdx.x & 31) == 0) red[threadIdx.x >> 5] = ss;
    __syncthreads();
    float tot = red[0] + red[1] + red[2] + red[3];
    float scale = rsqrtf(tot / 512.f + 1e-6f);
    for (int i = threadIdx.x; i < 512; i += 128)
        r[i] = __float2half_rn(__half2float(r[i]) * scale * w[i]);
    if (threadIdx.x < 32) {
        int i = threadIdx.x;
        float x0 = __half2float(r[512 + 2 * i]), x1 = __half2float(r[513 + 2 * i]);
        float c = cosp[s * 32 + i], sn = sinp[s * 32 + i];
        r[512 + 2 * i] = __float2half_rn(x0 * c - x1 * sn);
        r[513 + 2 * i] = __float2half_rn(x0 * sn + x1 * c);
    }
}

// ---------------- RoPE on q2 in place (cols h*192+128 .. +192) ---------------
__global__ void rope_q2(__half* __restrict__ q2,
                        const float* __restrict__ cosp, const float* __restrict__ sinp)
{
    int idx = blockIdx.x * 256 + threadIdx.x;
    if (idx >= 4096 * CH * 32) return;
    int i = idx & 31;
    int h = (idx >> 5) & 15;
    int row = idx >> 9;
    int s = row % CS;
    __half* p = q2 + (long long)row * 3072 + h * 192 + 128 + 2 * i;
    float x0 = __half2float(p[0]), x1 = __half2float(p[1]);
    float c = cosp[s * 32 + i], sn = sinp[s * 32 + i];
    p[0] = __float2half_rn(x0 * c - x1 * sn);
    p[1] = __float2half_rn(x0 * sn + x1 * c);
}

// ---------------- duplicate roped k_pe into Kp per head (uint32 pairs) -------
__global__ void kpe_dup(const __half* __restrict__ kv, __half* __restrict__ kp)
{
    int idx = blockIdx.x * 256 + threadIdx.x;   // 2*2048*16*32 uint32 copies
    if (idx >= 2 * 2048 * 16 * 32) return;
    int j2 = idx & 31;
    int h = (idx >> 5) & 15;
    int row = idx >> 9;                         // b*2048 + t
    uint32_t v = *(const uint32_t*)(kv + (long long)row * 576 + 512 + 2 * j2);
    *(uint32_t*)(kp + (long long)row * 3072 + h * 192 + 128 + 2 * j2) = v;
}

// ---------------- causal softmax: fp32 logits -> fp16 probs ------------------
__global__ __launch_bounds__(256) void softmax_h(
    const float* __restrict__ P, __half* __restrict__ Ph)
{
    int row = blockIdx.x;
    int s = row & (CS - 1);
    const float* pr = P + (long long)row * CS;
    __half* oh = Ph + (long long)row * CS;
    int tid = threadIdx.x;
    int limit = ((s >> 7) + 1) << 7;

    float v[8];
    float m = -1e30f;
#pragma unroll
    for (int i = 0; i < 8; i++) {
        int t = tid + i * 256;
        v[i] = (t <= s) ? pr[t] * ATT_SCALE : -1e30f;
        m = fmaxf(m, v[i]);
    }
    __shared__ float red[8];
#pragma unroll
    for (int o = 16; o; o >>= 1) m = fmaxf(m, __shfl_xor_sync(0xffffffffu, m, o));
    if ((tid & 31) == 0) red[tid >> 5] = m;
    __syncthreads();
    m = red[0];
#pragma unroll
    for (int w = 1; w < 8; w++) m = fmaxf(m, red[w]);

    float sum = 0.f;
#pragma unroll
    for (int i = 0; i < 8; i++) {
        int t = tid + i * 256;
        v[i] = (t <= s) ? __expf(v[i] - m) : 0.f;
        sum += v[i];
    }
    __syncthreads();
#pragma unroll
    for (int o = 16; o; o >>= 1) sum += __shfl_xor_sync(0xffffffffu, sum, o);
    if ((tid & 31) == 0) red[tid >> 5] = sum;
    __syncthreads();
    sum = 0.f;
#pragma unroll
    for (int w = 0; w < 8; w++) sum += red[w];
    float inv = 1.f / sum;
#pragma unroll
    for (int i = 0; i < 8; i++) {
        int t = tid + i * 256;
        if (t < limit) oh[t] = __float2half_rn(v[i] * inv);
    }
}

// ---------------- host: tensormap encode via dlopen(libcuda) -----------------
typedef CUresult (*PFN_tmEncode)(
    CUtensorMap*, CUtensorMapDataType, cuuint32_t, void*,
    const cuuint64_t*, const cuuint64_t*, const cuuint32_t*, const cuuint32_t*,
    CUtensorMapInterleave, CUtensorMapSwizzle, CUtensorMapL2promotion,
    CUtensorMapFloatOOBfill);

static PFN_tmEncode tm_encode()
{
    static PFN_tmEncode fn = nullptr;
    if (!fn) {
        void* h = dlopen("libcuda.so.1", RTLD_NOW | RTLD_GLOBAL);
        if (!h) h = dlopen("libcuda.so", RTLD_NOW | RTLD_GLOBAL);
        if (h) fn = (PFN_tmEncode)dlsym(h, "cuTensorMapEncodeTiled");
    }
    return fn;
}

static void make_map_h(CUtensorMap* m, void* base, long long cols, long long rows, long long ld)
{
    cuuint64_t dims[2]    = {(cuuint64_t)cols, (cuuint64_t)rows};
    cuuint64_t strides[1] = {(cuuint64_t)(ld * 2)};
    cuuint32_t box[2]     = {64u, 128u};
    cuuint32_t es[2]      = {1u, 1u};
    tm_encode()(m, CU_TENSOR_MAP_DATA_TYPE_FLOAT16, 2, base, dims, strides, box, es,
                CU_TENSOR_MAP_INTERLEAVE_NONE, CU_TENSOR_MAP_SWIZZLE_128B,
                CU_TENSOR_MAP_L2_PROMOTION_L2_128B, CU_TENSOR_MAP_FLOAT_OOB_FILL_NONE);
}

// ---------------------------------------------------------------------------
extern "C" void kernel_launch(void* const* d_in, const int* in_sizes, int n_in,
                              void* d_out, int out_size)
{
    (void)in_sizes; (void)n_in; (void)out_size;
    const float* x        = (const float*)d_in[0];
    const float* wq_a     = (const float*)d_in[1];
    const float* q_norm_w = (const float*)d_in[2];
    const float* wq_b     = (const float*)d_in[3];
    const float* wkv_a    = (const float*)d_in[4];
    const float* kv_norm_w= (const float*)d_in[5];
    const float* wkv_b    = (const float*)d_in[6];
    const float* wo       = (const float*)d_in[7];
    const float* cosp     = (const float*)d_in[8];
    const float* sinp     = (const float*)d_in[9];
    float* out = (float*)d_out;

    __half *xh, *wqah, *wkvah, *wqbh, *woh, *wvh, *wnh;
    __half *q1, *kvb, *q2, *kp, *vt, *phh, *ov;
    float* pf;
    cudaGetSymbolAddress((void**)&xh,   g_xh);
    cudaGetSymbolAddress((void**)&wqah, g_wqah);
    cudaGetSymbolAddress((void**)&wkvah,g_wkvah);
    cudaGetSymbolAddress((void**)&wqbh, g_wqbh);
    cudaGetSymbolAddress((void**)&woh,  g_woh);
    cudaGetSymbolAddress((void**)&wvh,  g_wvh);
    cudaGetSymbolAddress((void**)&wnh,  g_wnh);
    cudaGetSymbolAddress((void**)&q1,   g_q1);
    cudaGetSymbolAddress((void**)&kvb,  g_kv);
    cudaGetSymbolAddress((void**)&q2,   g_q2);
    cudaGetSymbolAddress((void**)&kp,   g_kp);
    cudaGetSymbolAddress((void**)&vt,   g_vt);
    cudaGetSymbolAddress((void**)&pf,   g_pf);
    cudaGetSymbolAddress((void**)&phh,  g_ph);
    cudaGetSymbolAddress((void**)&ov,   g_ov);

    cudaFuncSetAttribute(gemm_h, cudaFuncAttributeMaxDynamicSharedMemorySize, SMEM_TMA);

    // ---- prep: convert inputs/weights to fp16 once ----
    f2h_copy<<<8192, 256>>>(x,     xh,    2097152);
    f2h_copy<<<3072, 256>>>(wq_a,  wqah,  786432);
    f2h_copy<<<1152, 256>>>(wkv_a, wkvah, 294912);
    f2h_copy<<<4608, 256>>>(wq_b,  wqbh,  1179648);
    f2h_copy<<<4096, 256>>>(wo,    woh,   1048576);
    f2h_head<<<1024, 256>>>(wkv_b, wnh, 0);       // w_nope slices
    f2h_head<<<1024, 256>>>(wkv_b, wvh, 65536);   // w_v slices

    CUtensorMap mXH, mWQA, mWKVA, mWQB, mWO, mWNH, mWVH;
    CUtensorMap mQ1, mKV, mQ2, mKP, mPH, mVT, mOV;
    make_map_h(&mXH,  xh,   2048, 4096, 2048);
    make_map_h(&mWQA, wqah, 2048, 1536, 2048);
    make_map_h(&mWKVA,wkvah,2048, 576,  2048);
    make_map_h(&mWQB, wqbh, 1536, 3072, 1536);
    make_map_h(&mWO,  woh,  2048, 2048, 2048);
    make_map_h(&mWNH, wnh,  512,  2048, 512);
    make_map_h(&mWVH, wvh,  512,  2048, 512);
    make_map_h(&mQ1,  q1,   1536, 4096, 1536);
    make_map_h(&mKV,  kvb,  576,  4096, 576);
    make_map_h(&mQ2,  q2,   3072, 4096, 3072);
    make_map_h(&mKP,  kp,   3072, 4096, 3072);
    make_map_h(&mPH,  phh,  2048, 65536, 2048);
    make_map_h(&mVT,  vt,   2048, 4096, 2048);
    make_map_h(&mOV,  ov,   2048, 4096, 2048);

    // 1) q1 = x @ wq_a^T   [4096,1536]
    gemm_h<<<dim3(12, 32, 1), 256, SMEM_TMA>>>(mXH, mWQA, 0,0,0,0, 0,0,0,0,
        nullptr, q1, 1536, 0, 0, 4096, 1536, 2048, 0, 0);
    // 2) rmsnorm q1
    rmsnorm_h<<<4096, 256>>>(q1, q_norm_w, 1536);
    // 3) kv = x @ wkv_a^T  [4096,576]
    gemm_h<<<dim3(5, 32, 1), 256, SMEM_TMA>>>(mXH, mWKVA, 0,0,0,0, 0,0,0,0,
        nullptr, kvb, 576, 0, 0, 4096, 576, 2048, 0, 0);
    // 4) rmsnorm kv_c + rope k_pe
    kv_process_h<<<4096, 128>>>(kvb, kv_norm_w, cosp, sinp);
    // 5) K_h per (b,h): kv_c[b] @ w_nope[h]^T -> Kp[b][:, h*192:+128]
    gemm_h<<<dim3(1, 16, 32), 256, SMEM_TMA>>>(mKV, mWNH, 0,0,0,2048, 0,128,0,0,
        nullptr, kp, 3072, 192, (long long)2048*3072, 2048, 128, 512, 0, 0);
    // 6) duplicate roped k_pe into Kp[..., h*192+128:+64]
    kpe_dup<<<8192, 256>>>(kvb, kp);
    // 7) V_h^T per (b,h): w_v[h] @ kv_c[b]^T -> Vt[(b*16+h)][128][2048]
    gemm_h<<<dim3(16, 1, 32), 256, SMEM_TMA>>>(mWVH, mKV, 0,128,0,0, 0,0,0,2048,
        nullptr, vt, 2048, (long long)128*2048, (long long)16*128*2048,
        128, 2048, 512, 0, 0);
    // 8) q2 = q1 @ wq_b^T  [4096,3072]
    gemm_h<<<dim3(24, 32, 1), 256, SMEM_TMA>>>(mQ1, mWQB, 0,0,0,0, 0,0,0,0,
        nullptr, q2, 3072, 0, 0, 4096, 3072, 1536, 0, 0);
    // 9) rope q_pe in place on q2
    rope_q2<<<8192, 256>>>(q2, cosp, sinp);
    // 10) scores per (b,h): q2[b][:,h*192:+192] @ Kp[b][:,h*192:+192]^T (causal)
    gemm_h<<<dim3(16, 16, 32), 256, SMEM_TMA>>>(mQ2, mKP,
        192,0,0,2048, 192,0,0,2048,
        pf, nullptr, CS, (long long)CS*CS, (long long)CH*CS*CS,
        2048, 2048, 192, 1, 0);
    // 11) softmax: fp32 logits -> fp16 probs (clamped writes)
    softmax_h<<<2 * CH * CS, 256>>>(pf, phh);
    // 12) O = P @ V_h (K clamped, heavy-first) -> ov[b][:, h*128:+128]
    gemm_h<<<dim3(1, 16, 32), 256, SMEM_TMA>>>(mPH, mVT,
        0,2048,0,32768, 0,128,0,2048,
        nullptr, ov, 2048, 128, (long long)2048*2048,
        2048, 128, 2048, 0, 1);
    // 13) out = ov @ wo^T (fp32 out)
    gemm_h<<<dim3(16, 32, 1), 256, SMEM_TMA>>>(mOV, mWO, 0,0,0,0, 0,0,0,0,
        out, nullptr, 2048, 0, 0, 4096, 2048, 2048, 0, 0);
}

// round 9
// speedup vs baseline: 4.1324x; 1.2557x over previous
#include <cuda_runtime.h>
#include <cuda_fp16.h>
#include <cuda.h>
#include <cstdint>
#include <dlfcn.h>

#define CS 2048
#define CH 16
#define FA_C 0.10411754f   // 192^-0.5 * log2(e)

// ---------------- scratch (device globals, fp16 operands) -------------------
__device__ __align__(256) __half g_xh [(size_t)4096*2048];
__device__ __align__(256) __half g_wqah[(size_t)1536*2048];
__device__ __align__(256) __half g_wkvah[(size_t)576*2048];
__device__ __align__(256) __half g_wqbh[(size_t)3072*1536];
__device__ __align__(256) __half g_woh[(size_t)2048*2048];
__device__ __align__(256) __half g_wvh[(size_t)16*128*512];   // w_v per head [128][512]
__device__ __align__(256) __half g_wnh[(size_t)16*128*512];   // w_nope per head [128][512]
__device__ __align__(256) __half g_q1 [(size_t)4096*1536];
__device__ __align__(256) __half g_kv [(size_t)4096*576];
__device__ __align__(256) __half g_q2 [(size_t)4096*3072];    // rope applied in place
__device__ __align__(256) __half g_kp [(size_t)4096*3072];    // per-head K
__device__ __align__(256) __half g_vt [(size_t)32*128*2048];  // per (b,h): V^T [128][2048]
__device__ __align__(256) __half g_ov [(size_t)4096*2048];

// ---------------- ptx helpers ----------------
__device__ __forceinline__ void mma_fp16(float* c, const uint32_t* a, uint32_t b0, uint32_t b1) {
    asm volatile(
        "mma.sync.aligned.m16n8k16.row.col.f32.f16.f16.f32 "
        "{%0,%1,%2,%3},{%4,%5,%6,%7},{%8,%9},{%0,%1,%2,%3};"
        : "+f"(c[0]), "+f"(c[1]), "+f"(c[2]), "+f"(c[3])
        : "r"(a[0]), "r"(a[1]), "r"(a[2]), "r"(a[3]), "r"(b0), "r"(b1));
}
#define MBAR_INIT(a, c) \
    asm volatile("mbarrier.init.shared.b64 [%0], %1;" :: "r"(a), "r"(c) : "memory")
#define MBAR_EXPECT(a, tx) \
    asm volatile("mbarrier.arrive.expect_tx.shared.b64 _, [%0], %1;" :: "r"(a), "r"(tx) : "memory")
#define MBAR_WAIT(a, ph) do { \
    asm volatile("{\n\t.reg .pred P1;\n\tWL%=:\n\t" \
        "mbarrier.try_wait.parity.acquire.cta.shared::cta.b64 P1, [%0], %1, 0x989680;\n\t" \
        "@P1 bra.uni WD%=;\n\tbra.uni WL%=;\n\tWD%=:\n\t}" \
        :: "r"(a), "r"(ph) : "memory"); } while (0)
__device__ __forceinline__ void tma2d(uint32_t dst, const void* map, int x, int y, uint32_t mbar) {
    asm volatile(
        "cp.async.bulk.tensor.2d.shared::cta.global.tile.mbarrier::complete_tx::bytes "
        "[%0], [%1, {%2, %3}], [%4];"
        :: "r"(dst), "l"(map), "r"(x), "r"(y), "r"(mbar) : "memory");
}
__device__ __forceinline__ uint32_t lds32(uint32_t a) {
    uint32_t v; asm("ld.shared.b32 %0, [%1];" : "=r"(v) : "r"(a)); return v;
}
__device__ __forceinline__ float ex2(float x) {
    float y; asm("ex2.approx.f32 %0, %1;" : "=f"(y) : "f"(x)); return y;
}

// ---------------- TMA fp16 GEMM (unchanged core from R8) ---------------------
#define NST 3
#define STAGE 32768
#define SMEM_TMA (1024 + NST * STAGE)

__global__ __launch_bounds__(256, 2) void gemm_h(
    const __grid_constant__ CUtensorMap mA,
    const __grid_constant__ CUtensorMap mB,
    int axh, int ayh, int axb, int ayb,
    int bxh, int byh, int bxb, int byb,
    float* __restrict__ Cf, __half* __restrict__ Chh,
    int ldc, long long strCh, long long strCb,
    int M, int N, int K, int causal, int kclamp)
{
    int bm = blockIdx.y, bn = blockIdx.x;
    if (kclamp) bm = gridDim.y - 1 - bm;
    if (causal && bn > bm) return;
    int zh = blockIdx.z & 15, zb = blockIdx.z >> 4;
    if (Cf) Cf += (long long)zh * strCh + (long long)zb * strCb;
    else    Chh += (long long)zh * strCh + (long long)zb * strCb;
    int m0 = bm * 128, n0 = bn * 128;
    int Keff = kclamp ? (K < m0 + 128 ? K : m0 + 128) : K;
    int ntk = Keff >> 6;

    extern __shared__ __align__(1024) char smem[];
    uint32_t sbase = (uint32_t)__cvta_generic_to_shared(smem);

    int tid = threadIdx.x;
    int wid = tid >> 5, lane = tid & 31;
    int wm = wid >> 1, wn = wid & 1;
    int g = lane >> 2, tg = lane & 3;

    if (tid == 0) {
#pragma unroll
        for (int s = 0; s < NST; s++) MBAR_INIT(sbase + s * 8, 1);
    }
    __syncthreads();

    int xa = zh * axh + zb * axb, ya = m0 + zh * ayh + zb * ayb;
    int xb = zh * bxh + zb * bxb, yb = n0 + zh * byh + zb * byb;

    auto issue = [&](int j, int jb) {
        uint32_t mb = sbase + jb * 8;
        uint32_t da = sbase + 1024 + jb * STAGE;
        int k0 = j * 64;
        MBAR_EXPECT(mb, STAGE);
        tma2d(da, &mA, xa + k0, ya, mb);
        tma2d(da + 16384, &mB, xb + k0, yb, mb);
    };

    if (tid == 0) {
        issue(0, 0);
        if (ntk > 1) issue(1, 1);
    }

    float acc[2][8][4];
#pragma unroll
    for (int mi = 0; mi < 2; mi++)
#pragma unroll
        for (int j = 0; j < 8; j++)
#pragma unroll
            for (int r = 0; r < 4; r++) acc[mi][j][r] = 0.f;

    uint32_t xorv = (uint32_t)g << 4;
    int buf = 0, ph = 0;
    int pj = NST - 1, pbuf = NST - 1;

    for (int kt = 0; kt < ntk; kt++) {
        MBAR_WAIT(sbase + buf * 8, ph);
        const char* As = smem + 1024 + buf * STAGE;
        const char* Bs = As + 16384;
#pragma unroll
        for (int ks = 0; ks < 4; ks++) {
            uint32_t kb = (uint32_t)(ks * 32 + tg * 4);
            uint32_t c0 = kb ^ xorv;
            uint32_t c1 = (kb + 16u) ^ xorv;
            uint32_t a[2][4];
#pragma unroll
            for (int mi = 0; mi < 2; mi++) {
                int r = wm * 32 + mi * 16 + g;
                a[mi][0] = *(const uint32_t*)(As + r * 128 + c0);
                a[mi][1] = *(const uint32_t*)(As + (r + 8) * 128 + c0);
                a[mi][2] = *(const uint32_t*)(As + r * 128 + c1);
                a[mi][3] = *(const uint32_t*)(As + (r + 8) * 128 + c1);
            }
#pragma unroll
            for (int j = 0; j < 8; j++) {
                int c = wn * 64 + j * 8 + g;
                uint32_t b0 = *(const uint32_t*)(Bs + c * 128 + c0);
                uint32_t b1 = *(const uint32_t*)(Bs + c * 128 + c1);
                mma_fp16(acc[0][j], a[0], b0, b1);
                mma_fp16(acc[1][j], a[1], b0, b1);
            }
        }
        __syncthreads();
        if (tid == 0 && pj < ntk) issue(pj, pbuf);
        pj++;
        if (++pbuf == NST) pbuf = 0;
        if (++buf == NST) { buf = 0; ph ^= 1; }
    }

#pragma unroll
    for (int mi = 0; mi < 2; mi++) {
#pragma unroll
        for (int j = 0; j < 8; j++) {
            int row = m0 + wm * 32 + mi * 16 + g;
            int col = n0 + wn * 64 + j * 8 + 2 * tg;
            if (col < N) {
                float v0 = acc[mi][j][0], v1 = acc[mi][j][1];
                float v2 = acc[mi][j][2], v3 = acc[mi][j][3];
                if (Cf) {
                    *(float2*)&Cf[(long long)row * ldc + col] = make_float2(v0, v1);
                    *(float2*)&Cf[(long long)(row + 8) * ldc + col] = make_float2(v2, v3);
                } else {
                    *(__half2*)&Chh[(long long)row * ldc + col] = __floats2half2_rn(v0, v1);
                    *(__half2*)&Chh[(long long)(row + 8) * ldc + col] = __floats2half2_rn(v2, v3);
                }
            }
        }
    }
}

// ---------------- fused flash attention --------------------------------------
// Per CTA: one (b,h) and one 128-query tile. Q[128,192] in regs, K/V tiles via
// 2-stage TMA ring. S in C-frags -> online softmax -> lane-local repack to
// A-frags -> PV accumulate. Writes ov[b*2048+s][h*128+d] fp16.
#define SMQ_OFF 1024
#define RING_OFF (SMQ_OFF + 49152)
#define KVSTG 81920
#define SMEM_FA (RING_OFF + 2 * KVSTG)   // 214016

__global__ __launch_bounds__(256, 1) void flash_h(
    const __grid_constant__ CUtensorMap mQ,
    const __grid_constant__ CUtensorMap mK,
    const __grid_constant__ CUtensorMap mV,
    __half* __restrict__ ov)
{
    int qt = (int)gridDim.x - 1 - (int)blockIdx.x;   // heavy tiles first
    int bh = blockIdx.y;
    int b = bh >> 4, h = bh & 15;
    int ntk = qt + 1;

    extern __shared__ __align__(1024) char smem[];
    uint32_t sbase = (uint32_t)__cvta_generic_to_shared(smem);

    int tid = threadIdx.x;
    int wid = tid >> 5, lane = tid & 31;
    int g = lane >> 2, tg = lane & 3;
    uint32_t swz = (uint32_t)g << 4;

    if (tid == 0) {
        MBAR_INIT(sbase + 0, 1);
        MBAR_INIT(sbase + 8, 1);
        MBAR_INIT(sbase + 16, 1);
    }
    __syncthreads();

    auto issueKV = [&](int kt, int st) {
        uint32_t mb = sbase + 8 + st * 8;
        uint32_t base = sbase + RING_OFF + st * KVSTG;
        MBAR_EXPECT(mb, KVSTG);
#pragma unroll
        for (int c = 0; c < 3; c++)
            tma2d(base + c * 16384, &mK, h * 192 + c * 64, b * 2048 + kt * 128, mb);
#pragma unroll
        for (int c = 0; c < 2; c++)
            tma2d(base + 49152 + c * 16384, &mV, kt * 128 + c * 64, bh * 128, mb);
    };

    if (tid == 0) {
        MBAR_EXPECT(sbase + 0, 49152);
#pragma unroll
        for (int c = 0; c < 3; c++)
            tma2d(sbase + SMQ_OFF + c * 16384, &mQ, h * 192 + c * 64, b * 2048 + qt * 128, sbase + 0);
        issueKV(0, 0);
        if (ntk > 1) issueKV(1, 1);
    }

    // Q fragments to registers
    MBAR_WAIT(sbase + 0, 0);
    uint32_t qf[12][4];
    {
        int r0 = wid * 16 + g;
#pragma unroll
        for (int kk = 0; kk < 12; kk++) {
            uint32_t ch = sbase + SMQ_OFF + (kk >> 2) * 16384;
            uint32_t cb = (uint32_t)((kk & 3) * 32 + tg * 4);
            uint32_t o0 = cb ^ swz, o1 = (cb + 16u) ^ swz;
            qf[kk][0] = lds32(ch + r0 * 128 + o0);
            qf[kk][1] = lds32(ch + (r0 + 8) * 128 + o0);
            qf[kk][2] = lds32(ch + r0 * 128 + o1);
            qf[kk][3] = lds32(ch + (r0 + 8) * 128 + o1);
        }
    }

    float of[16][4];
#pragma unroll
    for (int j = 0; j < 16; j++)
#pragma unroll
        for (int r = 0; r < 4; r++) of[j][r] = 0.f;
    float m0r = -1e30f, m1r = -1e30f, l0r = 0.f, l1r = 0.f;

    for (int kt = 0; kt < ntk; kt++) {
        int st = kt & 1;
        MBAR_WAIT(sbase + 8 + st * 8, (kt >> 1) & 1);
        uint32_t kbs = sbase + RING_OFF + st * KVSTG;
        uint32_t vbs = kbs + 49152;

        // S = Q @ K^T   (16 n-tiles of 8 keys)
        float sj[16][4];
#pragma unroll
        for (int j = 0; j < 16; j++)
#pragma unroll
            for (int r = 0; r < 4; r++) sj[j][r] = 0.f;
#pragma unroll
        for (int kk = 0; kk < 12; kk++) {
            uint32_t ch = kbs + (kk >> 2) * 16384;
            uint32_t cb = (uint32_t)((kk & 3) * 32 + tg * 4);
            uint32_t o0 = cb ^ swz, o1 = (cb + 16u) ^ swz;
#pragma unroll
            for (int jn = 0; jn < 16; jn++) {
                uint32_t rb = ch + (jn * 8 + g) * 128;
                mma_fp16(sj[jn], qf[kk], lds32(rb + o0), lds32(rb + o1));
            }
        }

        // causal mask on diagonal tile
        if (kt == qt) {
            int r0 = wid * 16 + g, r1 = r0 + 8;
#pragma unroll
            for (int jn = 0; jn < 16; jn++) {
                int c0 = jn * 8 + 2 * tg, c1 = c0 + 1;
                if (c0 > r0) sj[jn][0] = -1e30f;
                if (c1 > r0) sj[jn][1] = -1e30f;
                if (c0 > r1) sj[jn][2] = -1e30f;
                if (c1 > r1) sj[jn][3] = -1e30f;
            }
        }

        // online softmax: row max (quad reduce), rescale, exp, pack
        float mx0 = -1e30f, mx1 = -1e30f;
#pragma unroll
        for (int jn = 0; jn < 16; jn++) {
            mx0 = fmaxf(mx0, fmaxf(sj[jn][0], sj[jn][1]));
            mx1 = fmaxf(mx1, fmaxf(sj[jn][2], sj[jn][3]));
        }
        mx0 = fmaxf(mx0, __shfl_xor_sync(0xffffffffu, mx0, 1));
        mx0 = fmaxf(mx0, __shfl_xor_sync(0xffffffffu, mx0, 2));
        mx1 = fmaxf(mx1, __shfl_xor_sync(0xffffffffu, mx1, 1));
        mx1 = fmaxf(mx1, __shfl_xor_sync(0xffffffffu, mx1, 2));
        float mn0 = fmaxf(m0r, mx0), mn1 = fmaxf(m1r, mx1);
        float f0 = ex2((m0r - mn0) * FA_C), f1 = ex2((m1r - mn1) * FA_C);
        m0r = mn0; m1r = mn1;

        float s0 = 0.f, s1 = 0.f;
        uint32_t pj[8][4];
#pragma unroll
        for (int u = 0; u < 8; u++) {
            float e00 = ex2((sj[2*u][0] - mn0) * FA_C);
            float e01 = ex2((sj[2*u][1] - mn0) * FA_C);
            float e02 = ex2((sj[2*u][2] - mn1) * FA_C);
            float e03 = ex2((sj[2*u][3] - mn1) * FA_C);
            float e10 = ex2((sj[2*u+1][0] - mn0) * FA_C);
            float e11 = ex2((sj[2*u+1][1] - mn0) * FA_C);
            float e12 = ex2((sj[2*u+1][2] - mn1) * FA_C);
            float e13 = ex2((sj[2*u+1][3] - mn1) * FA_C);
            s0 += e00 + e01 + e10 + e11;
            s1 += e02 + e03 + e12 + e13;
            __half2 h0 = __floats2half2_rn(e00, e01);
            __half2 h1 = __floats2half2_rn(e02, e03);
            __half2 h2 = __floats2half2_rn(e10, e11);
            __half2 h3 = __floats2half2_rn(e12, e13);
            pj[u][0] = *(uint32_t*)&h0;
            pj[u][1] = *(uint32_t*)&h1;
            pj[u][2] = *(uint32_t*)&h2;
            pj[u][3] = *(uint32_t*)&h3;
        }
        s0 += __shfl_xor_sync(0xffffffffu, s0, 1);
        s0 += __shfl_xor_sync(0xffffffffu, s0, 2);
        s1 += __shfl_xor_sync(0xffffffffu, s1, 1);
        s1 += __shfl_xor_sync(0xffffffffu, s1, 2);
        l0r = l0r * f0 + s0;
        l1r = l1r * f1 + s1;

#pragma unroll
        for (int j = 0; j < 16; j++) {
            of[j][0] *= f0; of[j][1] *= f0;
            of[j][2] *= f1; of[j][3] *= f1;
        }

        // O += P @ V  (V^T tiles: rows = dv, cols = keys)
#pragma unroll
        for (int u = 0; u < 8; u++) {
            uint32_t ch = vbs + (u >> 2) * 16384;
            uint32_t cb = (uint32_t)((u & 3) * 32 + tg * 4);
            uint32_t o0 = cb ^ swz, o1 = (cb + 16u) ^ swz;
#pragma unroll
            for (int jn = 0; jn < 16; jn++) {
                uint32_t rb = ch + (jn * 8 + g) * 128;
                mma_fp16(of[jn], pj[u], lds32(rb + o0), lds32(rb + o1));
            }
        }

        __syncthreads();
        if (tid == 0 && kt + 2 < ntk) issueKV(kt + 2, st);
    }

    // epilogue: normalize and store
    float inv0 = 1.f / l0r, inv1 = 1.f / l1r;
    long long row0 = (long long)b * 2048 + qt * 128 + wid * 16 + g;
#pragma unroll
    for (int jn = 0; jn < 16; jn++) {
        int d = h * 128 + jn * 8 + 2 * tg;
        __half2 h0 = __floats2half2_rn(of[jn][0] * inv0, of[jn][1] * inv0);
        __half2 h1 = __floats2half2_rn(of[jn][2] * inv1, of[jn][3] * inv1);
        *(__half2*)&ov[row0 * 2048 + d] = h0;
        *(__half2*)&ov[(row0 + 8) * 2048 + d] = h1;
    }
}

// ---------------- prep: fp32 -> fp16 copies ----------------------------------
__global__ void f2h_copy(const float* __restrict__ s, __half* __restrict__ d, long long n4)
{
    long long i = (long long)blockIdx.x * 256 + threadIdx.x;
    if (i >= n4) return;
    float4 v = ((const float4*)s)[i];
    __half2 h0 = __floats2half2_rn(v.x, v.y);
    __half2 h1 = __floats2half2_rn(v.z, v.w);
    ((uint2*)d)[i] = make_uint2(*(uint32_t*)&h0, *(uint32_t*)&h1);
}

__global__ void f2h_head(const float* __restrict__ wkvb, __half* __restrict__ d, int srcOff)
{
    long long i4 = (long long)blockIdx.x * 256 + threadIdx.x;
    long long head = i4 >> 14, off = (i4 & 16383) * 4;
    float4 v = *(const float4*)(wkvb + head * 131072 + srcOff + off);
    __half2 h0 = __floats2half2_rn(v.x, v.y);
    __half2 h1 = __floats2half2_rn(v.z, v.w);
    ((uint2*)d)[i4] = make_uint2(*(uint32_t*)&h0, *(uint32_t*)&h1);
}

// ---------------- rmsnorm rows (fp16 data, fp32 math) ------------------------
__global__ void rmsnorm_h(__half* __restrict__ x, const float* __restrict__ w, int n)
{
    long long row = blockIdx.x;
    __half* r = x + row * n;
    float ss = 0.f;
    for (int i = threadIdx.x; i < n; i += 256) { float v = __half2float(r[i]); ss += v * v; }
    __shared__ float red[8];
#pragma unroll
    for (int o = 16; o; o >>= 1) ss += __shfl_xor_sync(0xffffffffu, ss, o);
    if ((threadIdx.x & 31) == 0) red[threadIdx.x >> 5] = ss;
    __syncthreads();
    float tot = 0.f;
#pragma unroll
    for (int wv = 0; wv < 8; wv++) tot += red[wv];
    float scale = rsqrtf(tot / (float)n + 1e-6f);
    for (int i = threadIdx.x; i < n; i += 256)
        r[i] = __float2half_rn(__half2float(r[i]) * scale * w[i]);
}

// -------- kv row: rmsnorm first 512 (+w), rope last 64 (fp16 data) -----------
__global__ void kv_process_h(__half* __restrict__ kv, const float* __restrict__ w,
                             const float* __restrict__ cosp, const float* __restrict__ sinp)
{
    int row = blockIdx.x;
    int s = row % CS;
    __half* r = kv + (long long)row * 576;
    float ss = 0.f;
    for (int i = threadIdx.x; i < 512; i += 128) { float v = __half2float(r[i]); ss += v * v; }
    __shared__ float red[4];
#pragma unroll
    for (int o = 16; o; o >>= 1) ss += __shfl_xor_sync(0xffffffffu, ss, o);
    if ((threadIdx.x & 31) == 0) red[threadIdx.x >> 5] = ss;
    __syncthreads();
    float tot = red[0] + red[1] + red[2] + red[3];
    float scale = rsqrtf(tot / 512.f + 1e-6f);
    for (int i = threadIdx.x; i < 512; i += 128)
        r[i] = __float2half_rn(__half2float(r[i]) * scale * w[i]);
    if (threadIdx.x < 32) {
        int i = threadIdx.x;
        float x0 = __half2float(r[512 + 2 * i]), x1 = __half2float(r[513 + 2 * i]);
        float c = cosp[s * 32 + i], sn = sinp[s * 32 + i];
        r[512 + 2 * i] = __float2half_rn(x0 * c - x1 * sn);
        r[513 + 2 * i] = __float2half_rn(x0 * sn + x1 * c);
    }
}

// ---------------- RoPE on q2 in place ----------------------------------------
__global__ void rope_q2(__half* __restrict__ q2,
                        const float* __restrict__ cosp, const float* __restrict__ sinp)
{
    int idx = blockIdx.x * 256 + threadIdx.x;
    if (idx >= 4096 * CH * 32) return;
    int i = idx & 31;
    int h = (idx >> 5) & 15;
    int row = idx >> 9;
    int s = row % CS;
    __half* p = q2 + (long long)row * 3072 + h * 192 + 128 + 2 * i;
    float x0 = __half2float(p[0]), x1 = __half2float(p[1]);
    float c = cosp[s * 32 + i], sn = sinp[s * 32 + i];
    p[0] = __float2half_rn(x0 * c - x1 * sn);
    p[1] = __float2half_rn(x0 * sn + x1 * c);
}

// ---------------- duplicate roped k_pe into Kp per head -----------------------
__global__ void kpe_dup(const __half* __restrict__ kv, __half* __restrict__ kp)
{
    int idx = blockIdx.x * 256 + threadIdx.x;
    if (idx >= 2 * 2048 * 16 * 32) return;
    int j2 = idx & 31;
    int h = (idx >> 5) & 15;
    int row = idx >> 9;
    uint32_t v = *(const uint32_t*)(kv + (long long)row * 576 + 512 + 2 * j2);
    *(uint32_t*)(kp + (long long)row * 3072 + h * 192 + 128 + 2 * j2) = v;
}

// ---------------- host: tensormap encode via dlopen(libcuda) -----------------
typedef CUresult (*PFN_tmEncode)(
    CUtensorMap*, CUtensorMapDataType, cuuint32_t, void*,
    const cuuint64_t*, const cuuint64_t*, const cuuint32_t*, const cuuint32_t*,
    CUtensorMapInterleave, CUtensorMapSwizzle, CUtensorMapL2promotion,
    CUtensorMapFloatOOBfill);

static PFN_tmEncode tm_encode()
{
    static PFN_tmEncode fn = nullptr;
    if (!fn) {
        void* h = dlopen("libcuda.so.1", RTLD_NOW | RTLD_GLOBAL);
        if (!h) h = dlopen("libcuda.so", RTLD_NOW | RTLD_GLOBAL);
        if (h) fn = (PFN_tmEncode)dlsym(h, "cuTensorMapEncodeTiled");
    }
    return fn;
}

static void make_map_h(CUtensorMap* m, void* base, long long cols, long long rows, long long ld)
{
    cuuint64_t dims[2]    = {(cuuint64_t)cols, (cuuint64_t)rows};
    cuuint64_t strides[1] = {(cuuint64_t)(ld * 2)};
    cuuint32_t box[2]     = {64u, 128u};
    cuuint32_t es[2]      = {1u, 1u};
    tm_encode()(m, CU_TENSOR_MAP_DATA_TYPE_FLOAT16, 2, base, dims, strides, box, es,
                CU_TENSOR_MAP_INTERLEAVE_NONE, CU_TENSOR_MAP_SWIZZLE_128B,
                CU_TENSOR_MAP_L2_PROMOTION_L2_128B, CU_TENSOR_MAP_FLOAT_OOB_FILL_NONE);
}

// ---------------------------------------------------------------------------
extern "C" void kernel_launch(void* const* d_in, const int* in_sizes, int n_in,
                              void* d_out, int out_size)
{
    (void)in_sizes; (void)n_in; (void)out_size;
    const float* x        = (const float*)d_in[0];
    const float* wq_a     = (const float*)d_in[1];
    const float* q_norm_w = (const float*)d_in[2];
    const float* wq_b     = (const float*)d_in[3];
    const float* wkv_a    = (const float*)d_in[4];
    const float* kv_norm_w= (const float*)d_in[5];
    const float* wkv_b    = (const float*)d_in[6];
    const float* wo       = (const float*)d_in[7];
    const float* cosp     = (const float*)d_in[8];
    const float* sinp     = (const float*)d_in[9];
    float* out = (float*)d_out;

    __half *xh, *wqah, *wkvah, *wqbh, *woh, *wvh, *wnh;
    __half *q1, *kvb, *q2, *kp, *vt, *ov;
    cudaGetSymbolAddress((void**)&xh,   g_xh);
    cudaGetSymbolAddress((void**)&wqah, g_wqah);
    cudaGetSymbolAddress((void**)&wkvah,g_wkvah);
    cudaGetSymbolAddress((void**)&wqbh, g_wqbh);
    cudaGetSymbolAddress((void**)&woh,  g_woh);
    cudaGetSymbolAddress((void**)&wvh,  g_wvh);
    cudaGetSymbolAddress((void**)&wnh,  g_wnh);
    cudaGetSymbolAddress((void**)&q1,   g_q1);
    cudaGetSymbolAddress((void**)&kvb,  g_kv);
    cudaGetSymbolAddress((void**)&q2,   g_q2);
    cudaGetSymbolAddress((void**)&kp,   g_kp);
    cudaGetSymbolAddress((void**)&vt,   g_vt);
    cudaGetSymbolAddress((void**)&ov,   g_ov);

    cudaFuncSetAttribute(gemm_h, cudaFuncAttributeMaxDynamicSharedMemorySize, SMEM_TMA);
    cudaFuncSetAttribute(flash_h, cudaFuncAttributeMaxDynamicSharedMemorySize, SMEM_FA);

    // ---- prep: convert inputs/weights to fp16 once ----
    f2h_copy<<<8192, 256>>>(x,     xh,    2097152);
    f2h_copy<<<3072, 256>>>(wq_a,  wqah,  786432);
    f2h_copy<<<1152, 256>>>(wkv_a, wkvah, 294912);
    f2h_copy<<<4608, 256>>>(wq_b,  wqbh,  1179648);
    f2h_copy<<<4096, 256>>>(wo,    woh,   1048576);
    f2h_head<<<1024, 256>>>(wkv_b, wnh, 0);
    f2h_head<<<1024, 256>>>(wkv_b, wvh, 65536);

    CUtensorMap mXH, mWQA, mWKVA, mWQB, mWO, mWNH, mWVH;
    CUtensorMap mQ1, mKV, mQ2, mKP, mVT, mOV;
    make_map_h(&mXH,  xh,   2048, 4096, 2048);
    make_map_h(&mWQA, wqah, 2048, 1536, 2048);
    make_map_h(&mWKVA,wkvah,2048, 576,  2048);
    make_map_h(&mWQB, wqbh, 1536, 3072, 1536);
    make_map_h(&mWO,  woh,  2048, 2048, 2048);
    make_map_h(&mWNH, wnh,  512,  2048, 512);
    make_map_h(&mWVH, wvh,  512,  2048, 512);
    make_map_h(&mQ1,  q1,   1536, 4096, 1536);
    make_map_h(&mKV,  kvb,  576,  4096, 576);
    make_map_h(&mQ2,  q2,   3072, 4096, 3072);
    make_map_h(&mKP,  kp,   3072, 4096, 3072);
    make_map_h(&mVT,  vt,   2048, 4096, 2048);
    make_map_h(&mOV,  ov,   2048, 4096, 2048);

    // 1) q1 = x @ wq_a^T
    gemm_h<<<dim3(12, 32, 1), 256, SMEM_TMA>>>(mXH, mWQA, 0,0,0,0, 0,0,0,0,
        nullptr, q1, 1536, 0, 0, 4096, 1536, 2048, 0, 0);
    // 2) rmsnorm q1
    rmsnorm_h<<<4096, 256>>>(q1, q_norm_w, 1536);
    // 3) kv = x @ wkv_a^T
    gemm_h<<<dim3(5, 32, 1), 256, SMEM_TMA>>>(mXH, mWKVA, 0,0,0,0, 0,0,0,0,
        nullptr, kvb, 576, 0, 0, 4096, 576, 2048, 0, 0);
    // 4) rmsnorm kv_c + rope k_pe
    kv_process_h<<<4096, 128>>>(kvb, kv_norm_w, cosp, sinp);
    // 5) K_h per (b,h): kv_c[b] @ w_nope[h]^T -> Kp[b][:, h*192:+128]
    gemm_h<<<dim3(1, 16, 32), 256, SMEM_TMA>>>(mKV, mWNH, 0,0,0,2048, 0,128,0,0,
        nullptr, kp, 3072, 192, (long long)2048*3072, 2048, 128, 512, 0, 0);
    // 6) duplicate roped k_pe into Kp
    kpe_dup<<<8192, 256>>>(kvb, kp);
    // 7) V_h^T per (b,h): w_v[h] @ kv_c[b]^T -> Vt[(b*16+h)][128][2048]
    gemm_h<<<dim3(16, 1, 32), 256, SMEM_TMA>>>(mWVH, mKV, 0,128,0,0, 0,0,0,2048,
        nullptr, vt, 2048, (long long)128*2048, (long long)16*128*2048,
        128, 2048, 512, 0, 0);
    // 8) q2 = q1 @ wq_b^T
    gemm_h<<<dim3(24, 32, 1), 256, SMEM_TMA>>>(mQ1, mWQB, 0,0,0,0, 0,0,0,0,
        nullptr, q2, 3072, 0, 0, 4096, 3072, 1536, 0, 0);
    // 9) rope q_pe in place on q2
    rope_q2<<<8192, 256>>>(q2, cosp, sinp);
    // 10) fused flash attention -> ov
    flash_h<<<dim3(16, 32, 1), 256, SMEM_FA>>>(mQ2, mKP, mVT, ov);
    // 11) out = ov @ wo^T (fp32 out)
    gemm_h<<<dim3(16, 32, 1), 256, SMEM_TMA>>>(mOV, mWO, 0,0,0,0, 0,0,0,0,
        out, nullptr, 2048, 0, 0, 4096, 2048, 2048, 0, 0);
}

// round 12
// speedup vs baseline: 4.6315x; 1.1208x over previous
#include <cuda_runtime.h>
#include <cuda_fp16.h>
#include <cuda.h>
#include <cstdint>
#include <dlfcn.h>

#define CS 2048
#define CH 16
#define FA_C 0.10411754f   // 192^-0.5 * log2(e)

// ---------------- scratch (device globals, fp16 operands) -------------------
__device__ __align__(256) __half g_xh [(size_t)4096*2048];
__device__ __align__(256) __half g_wqah[(size_t)1536*2048];
__device__ __align__(256) __half g_wkvah[(size_t)576*2048];
__device__ __align__(256) __half g_wqbh[(size_t)3072*1536];
__device__ __align__(256) __half g_woh[(size_t)2048*2048];
__device__ __align__(256) __half g_wvh[(size_t)16*128*512];   // w_v per head [128][512]
__device__ __align__(256) __half g_wnh[(size_t)16*128*512];   // w_nope per head [128][512]
__device__ __align__(256) __half g_q1 [(size_t)4096*1536];
__device__ __align__(256) __half g_kv [(size_t)4096*576];
__device__ __align__(256) __half g_q2 [(size_t)4096*3072];    // rope applied in place
__device__ __align__(256) __half g_kp [(size_t)4096*3072];    // per-head K
__device__ __align__(256) __half g_vt [(size_t)32*128*2048];  // per (b,h): V^T [128][2048]
__device__ __align__(256) __half g_ov [(size_t)4096*2048];

// ---------------- ptx helpers ----------------
__device__ __forceinline__ void mma_fp16(float* c, const uint32_t* a, uint32_t b0, uint32_t b1) {
    asm volatile(
        "mma.sync.aligned.m16n8k16.row.col.f32.f16.f16.f32 "
        "{%0,%1,%2,%3},{%4,%5,%6,%7},{%8,%9},{%0,%1,%2,%3};"
        : "+f"(c[0]), "+f"(c[1]), "+f"(c[2]), "+f"(c[3])
        : "r"(a[0]), "r"(a[1]), "r"(a[2]), "r"(a[3]), "r"(b0), "r"(b1));
}
#define MBAR_INIT(a, c) \
    asm volatile("mbarrier.init.shared.b64 [%0], %1;" :: "r"(a), "r"(c) : "memory")
#define MBAR_EXPECT(a, tx) \
    asm volatile("mbarrier.arrive.expect_tx.shared.b64 _, [%0], %1;" :: "r"(a), "r"(tx) : "memory")
#define MBAR_WAIT(a, ph) do { \
    asm volatile("{\n\t.reg .pred P1;\n\tWL%=:\n\t" \
        "mbarrier.try_wait.parity.acquire.cta.shared::cta.b64 P1, [%0], %1, 0x989680;\n\t" \
        "@P1 bra.uni WD%=;\n\tbra.uni WL%=;\n\tWD%=:\n\t}" \
        :: "r"(a), "r"(ph) : "memory"); } while (0)
__device__ __forceinline__ void tma2d(uint32_t dst, const void* map, int x, int y, uint32_t mbar) {
    asm volatile(
        "cp.async.bulk.tensor.2d.shared::cta.global.tile.mbarrier::complete_tx::bytes "
        "[%0], [%1, {%2, %3}], [%4];"
        :: "r"(dst), "l"(map), "r"(x), "r"(y), "r"(mbar) : "memory");
}
__device__ __forceinline__ uint32_t lds32(uint32_t a) {
    uint32_t v; asm("ld.shared.b32 %0, [%1];" : "=r"(v) : "r"(a)); return v;
}
__device__ __forceinline__ float ex2(float x) {
    float y; asm("ex2.approx.f32 %0, %1;" : "=f"(y) : "f"(x)); return y;
}

// ---------------- TMA fp16 GEMM (core unchanged from R8/R9) ------------------
#define NST 3
#define STAGE 32768
#define SMEM_TMA (1024 + NST * STAGE)

__global__ __launch_bounds__(256, 2) void gemm_h(
    const __grid_constant__ CUtensorMap mA,
    const __grid_constant__ CUtensorMap mB,
    int axh, int ayh, int axb, int ayb,
    int bxh, int byh, int bxb, int byb,
    float* __restrict__ Cf, __half* __restrict__ Chh,
    int ldc, long long strCh, long long strCb,
    int M, int N, int K, int causal, int kclamp)
{
    int bm = blockIdx.y, bn = blockIdx.x;
    if (kclamp) bm = gridDim.y - 1 - bm;
    if (causal && bn > bm) return;
    int zh = blockIdx.z & 15, zb = blockIdx.z >> 4;
    if (Cf) Cf += (long long)zh * strCh + (long long)zb * strCb;
    else    Chh += (long long)zh * strCh + (long long)zb * strCb;
    int m0 = bm * 128, n0 = bn * 128;
    int Keff = kclamp ? (K < m0 + 128 ? K : m0 + 128) : K;
    int ntk = Keff >> 6;

    extern __shared__ __align__(1024) char smem[];
    uint32_t sbase = (uint32_t)__cvta_generic_to_shared(smem);

    int tid = threadIdx.x;
    int wid = tid >> 5, lane = tid & 31;
    int wm = wid >> 1, wn = wid & 1;
    int g = lane >> 2, tg = lane & 3;

    if (tid == 0) {
#pragma unroll
        for (int s = 0; s < NST; s++) MBAR_INIT(sbase + s * 8, 1);
    }
    __syncthreads();

    int xa = zh * axh + zb * axb, ya = m0 + zh * ayh + zb * ayb;
    int xb = zh * bxh + zb * bxb, yb = n0 + zh * byh + zb * byb;

    auto issue = [&](int j, int jb) {
        uint32_t mb = sbase + jb * 8;
        uint32_t da = sbase + 1024 + jb * STAGE;
        int k0 = j * 64;
        MBAR_EXPECT(mb, STAGE);
        tma2d(da, &mA, xa + k0, ya, mb);
        tma2d(da + 16384, &mB, xb + k0, yb, mb);
    };

    if (tid == 0) {
        issue(0, 0);
        if (ntk > 1) issue(1, 1);
    }

    float acc[2][8][4];
#pragma unroll
    for (int mi = 0; mi < 2; mi++)
#pragma unroll
        for (int j = 0; j < 8; j++)
#pragma unroll
            for (int r = 0; r < 4; r++) acc[mi][j][r] = 0.f;

    uint32_t xorv = (uint32_t)g << 4;
    int buf = 0, ph = 0;
    int pj = NST - 1, pbuf = NST - 1;

    for (int kt = 0; kt < ntk; kt++) {
        MBAR_WAIT(sbase + buf * 8, ph);
        const char* As = smem + 1024 + buf * STAGE;
        const char* Bs = As + 16384;
#pragma unroll
        for (int ks = 0; ks < 4; ks++) {
            uint32_t kb = (uint32_t)(ks * 32 + tg * 4);
            uint32_t c0 = kb ^ xorv;
            uint32_t c1 = (kb + 16u) ^ xorv;
            uint32_t a[2][4];
#pragma unroll
            for (int mi = 0; mi < 2; mi++) {
                int r = wm * 32 + mi * 16 + g;
                a[mi][0] = *(const uint32_t*)(As + r * 128 + c0);
                a[mi][1] = *(const uint32_t*)(As + (r + 8) * 128 + c0);
                a[mi][2] = *(const uint32_t*)(As + r * 128 + c1);
                a[mi][3] = *(const uint32_t*)(As + (r + 8) * 128 + c1);
            }
#pragma unroll
            for (int j = 0; j < 8; j++) {
                int c = wn * 64 + j * 8 + g;
                uint32_t b0 = *(const uint32_t*)(Bs + c * 128 + c0);
                uint32_t b1 = *(const uint32_t*)(Bs + c * 128 + c1);
                mma_fp16(acc[0][j], a[0], b0, b1);
                mma_fp16(acc[1][j], a[1], b0, b1);
            }
        }
        __syncthreads();
        if (tid == 0 && pj < ntk) issue(pj, pbuf);
        pj++;
        if (++pbuf == NST) pbuf = 0;
        if (++buf == NST) { buf = 0; ph ^= 1; }
    }

#pragma unroll
    for (int mi = 0; mi < 2; mi++) {
#pragma unroll
        for (int j = 0; j < 8; j++) {
            int row = m0 + wm * 32 + mi * 16 + g;
            int col = n0 + wn * 64 + j * 8 + 2 * tg;
            if (col < N) {
                float v0 = acc[mi][j][0], v1 = acc[mi][j][1];
                float v2 = acc[mi][j][2], v3 = acc[mi][j][3];
                if (Cf) {
                    *(float2*)&Cf[(long long)row * ldc + col] = make_float2(v0, v1);
                    *(float2*)&Cf[(long long)(row + 8) * ldc + col] = make_float2(v2, v3);
                } else {
                    *(__half2*)&Chh[(long long)row * ldc + col] = __floats2half2_rn(v0, v1);
                    *(__half2*)&Chh[(long long)(row + 8) * ldc + col] = __floats2half2_rn(v2, v3);
                }
            }
        }
    }
}

// ---------------- fused flash attention (unchanged from R9) ------------------
#define SMQ_OFF 1024
#define RING_OFF (SMQ_OFF + 49152)
#define KVSTG 81920
#define SMEM_FA (RING_OFF + 2 * KVSTG)   // 214016

__global__ __launch_bounds__(256, 1) void flash_h(
    const __grid_constant__ CUtensorMap mQ,
    const __grid_constant__ CUtensorMap mK,
    const __grid_constant__ CUtensorMap mV,
    __half* __restrict__ ov)
{
    int qt = (int)gridDim.x - 1 - (int)blockIdx.x;   // heavy tiles first
    int bh = blockIdx.y;
    int b = bh >> 4, h = bh & 15;
    int ntk = qt + 1;

    extern __shared__ __align__(1024) char smem[];
    uint32_t sbase = (uint32_t)__cvta_generic_to_shared(smem);

    int tid = threadIdx.x;
    int wid = tid >> 5, lane = tid & 31;
    int g = lane >> 2, tg = lane & 3;
    uint32_t swz = (uint32_t)g << 4;

    if (tid == 0) {
        MBAR_INIT(sbase + 0, 1);
        MBAR_INIT(sbase + 8, 1);
        MBAR_INIT(sbase + 16, 1);
    }
    __syncthreads();

    auto issueKV = [&](int kt, int st) {
        uint32_t mb = sbase + 8 + st * 8;
        uint32_t base = sbase + RING_OFF + st * KVSTG;
        MBAR_EXPECT(mb, KVSTG);
#pragma unroll
        for (int c = 0; c < 3; c++)
            tma2d(base + c * 16384, &mK, h * 192 + c * 64, b * 2048 + kt * 128, mb);
#pragma unroll
        for (int c = 0; c < 2; c++)
            tma2d(base + 49152 + c * 16384, &mV, kt * 128 + c * 64, bh * 128, mb);
    };

    if (tid == 0) {
        MBAR_EXPECT(sbase + 0, 49152);
#pragma unroll
        for (int c = 0; c < 3; c++)
            tma2d(sbase + SMQ_OFF + c * 16384, &mQ, h * 192 + c * 64, b * 2048 + qt * 128, sbase + 0);
        issueKV(0, 0);
        if (ntk > 1) issueKV(1, 1);
    }

    MBAR_WAIT(sbase + 0, 0);
    uint32_t qf[12][4];
    {
        int r0 = wid * 16 + g;
#pragma unroll
        for (int kk = 0; kk < 12; kk++) {
            uint32_t ch = sbase + SMQ_OFF + (kk >> 2) * 16384;
            uint32_t cb = (uint32_t)((kk & 3) * 32 + tg * 4);
            uint32_t o0 = cb ^ swz, o1 = (cb + 16u) ^ swz;
            qf[kk][0] = lds32(ch + r0 * 128 + o0);
            qf[kk][1] = lds32(ch + (r0 + 8) * 128 + o0);
            qf[kk][2] = lds32(ch + r0 * 128 + o1);
            qf[kk][3] = lds32(ch + (r0 + 8) * 128 + o1);
        }
    }

    float of[16][4];
#pragma unroll
    for (int j = 0; j < 16; j++)
#pragma unroll
        for (int r = 0; r < 4; r++) of[j][r] = 0.f;
    float m0r = -1e30f, m1r = -1e30f, l0r = 0.f, l1r = 0.f;

    for (int kt = 0; kt < ntk; kt++) {
        int st = kt & 1;
        MBAR_WAIT(sbase + 8 + st * 8, (kt >> 1) & 1);
        uint32_t kbs = sbase + RING_OFF + st * KVSTG;
        uint32_t vbs = kbs + 49152;

        float sj[16][4];
#pragma unroll
        for (int j = 0; j < 16; j++)
#pragma unroll
            for (int r = 0; r < 4; r++) sj[j][r] = 0.f;
#pragma unroll
        for (int kk = 0; kk < 12; kk++) {
            uint32_t ch = kbs + (kk >> 2) * 16384;
            uint32_t cb = (uint32_t)((kk & 3) * 32 + tg * 4);
            uint32_t o0 = cb ^ swz, o1 = (cb + 16u) ^ swz;
#pragma unroll
            for (int jn = 0; jn < 16; jn++) {
                uint32_t rb = ch + (jn * 8 + g) * 128;
                mma_fp16(sj[jn], qf[kk], lds32(rb + o0), lds32(rb + o1));
            }
        }

        if (kt == qt) {
            int r0 = wid * 16 + g, r1 = r0 + 8;
#pragma unroll
            for (int jn = 0; jn < 16; jn++) {
                int c0 = jn * 8 + 2 * tg, c1 = c0 + 1;
                if (c0 > r0) sj[jn][0] = -1e30f;
                if (c1 > r0) sj[jn][1] = -1e30f;
                if (c0 > r1) sj[jn][2] = -1e30f;
                if (c1 > r1) sj[jn][3] = -1e30f;
            }
        }

        float mx0 = -1e30f, mx1 = -1e30f;
#pragma unroll
        for (int jn = 0; jn < 16; jn++) {
            mx0 = fmaxf(mx0, fmaxf(sj[jn][0], sj[jn][1]));
            mx1 = fmaxf(mx1, fmaxf(sj[jn][2], sj[jn][3]));
        }
        mx0 = fmaxf(mx0, __shfl_xor_sync(0xffffffffu, mx0, 1));
        mx0 = fmaxf(mx0, __shfl_xor_sync(0xffffffffu, mx0, 2));
        mx1 = fmaxf(mx1, __shfl_xor_sync(0xffffffffu, mx1, 1));
        mx1 = fmaxf(mx1, __shfl_xor_sync(0xffffffffu, mx1, 2));
        float mn0 = fmaxf(m0r, mx0), mn1 = fmaxf(m1r, mx1);
        float f0 = ex2((m0r - mn0) * FA_C), f1 = ex2((m1r - mn1) * FA_C);
        m0r = mn0; m1r = mn1;

        float s0 = 0.f, s1 = 0.f;
        uint32_t pj[8][4];
#pragma unroll
        for (int u = 0; u < 8; u++) {
            float e00 = ex2((sj[2*u][0] - mn0) * FA_C);
            float e01 = ex2((sj[2*u][1] - mn0) * FA_C);
            float e02 = ex2((sj[2*u][2] - mn1) * FA_C);
            float e03 = ex2((sj[2*u][3] - mn1) * FA_C);
            float e10 = ex2((sj[2*u+1][0] - mn0) * FA_C);
            float e11 = ex2((sj[2*u+1][1] - mn0) * FA_C);
            float e12 = ex2((sj[2*u+1][2] - mn1) * FA_C);
            float e13 = ex2((sj[2*u+1][3] - mn1) * FA_C);
            s0 += e00 + e01 + e10 + e11;
            s1 += e02 + e03 + e12 + e13;
            __half2 h0 = __floats2half2_rn(e00, e01);
            __half2 h1 = __floats2half2_rn(e02, e03);
            __half2 h2 = __floats2half2_rn(e10, e11);
            __half2 h3 = __floats2half2_rn(e12, e13);
            pj[u][0] = *(uint32_t*)&h0;
            pj[u][1] = *(uint32_t*)&h1;
            pj[u][2] = *(uint32_t*)&h2;
            pj[u][3] = *(uint32_t*)&h3;
        }
        s0 += __shfl_xor_sync(0xffffffffu, s0, 1);
        s0 += __shfl_xor_sync(0xffffffffu, s0, 2);
        s1 += __shfl_xor_sync(0xffffffffu, s1, 1);
        s1 += __shfl_xor_sync(0xffffffffu, s1, 2);
        l0r = l0r * f0 + s0;
        l1r = l1r * f1 + s1;

#pragma unroll
        for (int j = 0; j < 16; j++) {
            of[j][0] *= f0; of[j][1] *= f0;
            of[j][2] *= f1; of[j][3] *= f1;
        }

#pragma unroll
        for (int u = 0; u < 8; u++) {
            uint32_t ch = vbs + (u >> 2) * 16384;
            uint32_t cb = (uint32_t)((u & 3) * 32 + tg * 4);
            uint32_t o0 = cb ^ swz, o1 = (cb + 16u) ^ swz;
#pragma unroll
            for (int jn = 0; jn < 16; jn++) {
                uint32_t rb = ch + (jn * 8 + g) * 128;
                mma_fp16(of[jn], pj[u], lds32(rb + o0), lds32(rb + o1));
            }
        }

        __syncthreads();
        if (tid == 0 && kt + 2 < ntk) issueKV(kt + 2, st);
    }

    float inv0 = 1.f / l0r, inv1 = 1.f / l1r;
    long long row0 = (long long)b * 2048 + qt * 128 + wid * 16 + g;
#pragma unroll
    for (int jn = 0; jn < 16; jn++) {
        int d = h * 128 + jn * 8 + 2 * tg;
        __half2 h0 = __floats2half2_rn(of[jn][0] * inv0, of[jn][1] * inv0);
        __half2 h1 = __floats2half2_rn(of[jn][2] * inv1, of[jn][3] * inv1);
        *(__half2*)&ov[row0 * 2048 + d] = h0;
        *(__half2*)&ov[(row0 + 8) * 2048 + d] = h1;
    }
}

// ---------------- prep: fp32 -> fp16 copies ----------------------------------
__global__ void f2h_copy(const float* __restrict__ s, __half* __restrict__ d, long long n4)
{
    long long i = (long long)blockIdx.x * 256 + threadIdx.x;
    if (i >= n4) return;
    float4 v = ((const float4*)s)[i];
    __half2 h0 = __floats2half2_rn(v.x, v.y);
    __half2 h1 = __floats2half2_rn(v.z, v.w);
    ((uint2*)d)[i] = make_uint2(*(uint32_t*)&h0, *(uint32_t*)&h1);
}

__global__ void f2h_head(const float* __restrict__ wkvb, __half* __restrict__ d, int srcOff)
{
    long long i4 = (long long)blockIdx.x * 256 + threadIdx.x;
    long long head = i4 >> 14, off = (i4 & 16383) * 4;
    float4 v = *(const float4*)(wkvb + head * 131072 + srcOff + off);
    __half2 h0 = __floats2half2_rn(v.x, v.y);
    __half2 h1 = __floats2half2_rn(v.z, v.w);
    ((uint2*)d)[i4] = make_uint2(*(uint32_t*)&h0, *(uint32_t*)&h1);
}

// ---------------- rmsnorm rows (fp16 data, fp32 math) ------------------------
__global__ void rmsnorm_h(__half* __restrict__ x, const float* __restrict__ w, int n)
{
    long long row = blockIdx.x;
    __half* r = x + row * n;
    float ss = 0.f;
    for (int i = threadIdx.x; i < n; i += 256) { float v = __half2float(r[i]); ss += v * v; }
    __shared__ float red[8];
#pragma unroll
    for (int o = 16; o; o >>= 1) ss += __shfl_xor_sync(0xffffffffu, ss, o);
    if ((threadIdx.x & 31) == 0) red[threadIdx.x >> 5] = ss;
    __syncthreads();
    float tot = 0.f;
#pragma unroll
    for (int wv = 0; wv < 8; wv++) tot += red[wv];
    float scale = rsqrtf(tot / (float)n + 1e-6f);
    for (int i = threadIdx.x; i < n; i += 256)
        r[i] = __float2half_rn(__half2float(r[i]) * scale * w[i]);
}

// -------- kv row: rmsnorm first 512 (+w), rope last 64 (fp16 data) -----------
__global__ void kv_process_h(__half* __restrict__ kv, const float* __restrict__ w,
                             const float* __restrict__ cosp, const float* __restrict__ sinp)
{
    int row = blockIdx.x;
    int s = row % CS;
    __half* r = kv + (long long)row * 576;
    float ss = 0.f;
    for (int i = threadIdx.x; i < 512; i += 128) { float v = __half2float(r[i]); ss += v * v; }
    __shared__ float red[4];
#pragma unroll
    for (int o = 16; o; o >>= 1) ss += __shfl_xor_sync(0xffffffffu, ss, o);
    if ((threadIdx.x & 31) == 0) red[threadIdx.x >> 5] = ss;
    __syncthreads();
    float tot = red[0] + red[1] + red[2] + red[3];
    float scale = rsqrtf(tot / 512.f + 1e-6f);
    for (int i = threadIdx.x; i < 512; i += 128)
        r[i] = __float2half_rn(__half2float(r[i]) * scale * w[i]);
    if (threadIdx.x < 32) {
        int i = threadIdx.x;
        float x0 = __half2float(r[512 + 2 * i]), x1 = __half2float(r[513 + 2 * i]);
        float c = cosp[s * 32 + i], sn = sinp[s * 32 + i];
        r[512 + 2 * i] = __float2half_rn(x0 * c - x1 * sn);
        r[513 + 2 * i] = __float2half_rn(x0 * sn + x1 * c);
    }
}

// ---------------- RoPE on q2 in place ----------------------------------------
__global__ void rope_q2(__half* __restrict__ q2,
                        const float* __restrict__ cosp, const float* __restrict__ sinp)
{
    int idx = blockIdx.x * 256 + threadIdx.x;
    if (idx >= 4096 * CH * 32) return;
    int i = idx & 31;
    int h = (idx >> 5) & 15;
    int row = idx >> 9;
    int s = row % CS;
    __half* p = q2 + (long long)row * 3072 + h * 192 + 128 + 2 * i;
    float x0 = __half2float(p[0]), x1 = __half2float(p[1]);
    float c = cosp[s * 32 + i], sn = sinp[s * 32 + i];
    p[0] = __float2half_rn(x0 * c - x1 * sn);
    p[1] = __float2half_rn(x0 * sn + x1 * c);
}

// ---------------- duplicate roped k_pe into Kp per head -----------------------
__global__ void kpe_dup(const __half* __restrict__ kv, __half* __restrict__ kp)
{
    int idx = blockIdx.x * 256 + threadIdx.x;
    if (idx >= 2 * 2048 * 16 * 32) return;
    int j2 = idx & 31;
    int h = (idx >> 5) & 15;
    int row = idx >> 9;
    uint32_t v = *(const uint32_t*)(kv + (long long)row * 576 + 512 + 2 * j2);
    *(uint32_t*)(kp + (long long)row * 3072 + h * 192 + 128 + 2 * j2) = v;
}

// ---------------- host: tensormap encode via dlopen(libcuda) -----------------
typedef CUresult (*PFN_tmEncode)(
    CUtensorMap*, CUtensorMapDataType, cuuint32_t, void*,
    const cuuint64_t*, const cuuint64_t*, const cuuint32_t*, const cuuint32_t*,
    CUtensorMapInterleave, CUtensorMapSwizzle, CUtensorMapL2promotion,
    CUtensorMapFloatOOBfill);

static PFN_tmEncode tm_encode()
{
    static PFN_tmEncode fn = nullptr;
    if (!fn) {
        void* h = dlopen("libcuda.so.1", RTLD_NOW | RTLD_GLOBAL);
        if (!h) h = dlopen("libcuda.so", RTLD_NOW | RTLD_GLOBAL);
        if (h) fn = (PFN_tmEncode)dlsym(h, "cuTensorMapEncodeTiled");
    }
    return fn;
}

static void make_map_h(CUtensorMap* m, void* base, long long cols, long long rows, long long ld)
{
    cuuint64_t dims[2]    = {(cuuint64_t)cols, (cuuint64_t)rows};
    cuuint64_t strides[1] = {(cuuint64_t)(ld * 2)};
    cuuint32_t box[2]     = {64u, 128u};
    cuuint32_t es[2]      = {1u, 1u};
    tm_encode()(m, CU_TENSOR_MAP_DATA_TYPE_FLOAT16, 2, base, dims, strides, box, es,
                CU_TENSOR_MAP_INTERLEAVE_NONE, CU_TENSOR_MAP_SWIZZLE_128B,
                CU_TENSOR_MAP_L2_PROMOTION_L2_128B, CU_TENSOR_MAP_FLOAT_OOB_FILL_NONE);
}

// ---------------------------------------------------------------------------
extern "C" void kernel_launch(void* const* d_in, const int* in_sizes, int n_in,
                              void* d_out, int out_size)
{
    (void)in_sizes; (void)n_in; (void)out_size;
    const float* x        = (const float*)d_in[0];
    const float* wq_a     = (const float*)d_in[1];
    const float* q_norm_w = (const float*)d_in[2];
    const float* wq_b     = (const float*)d_in[3];
    const float* wkv_a    = (const float*)d_in[4];
    const float* kv_norm_w= (const float*)d_in[5];
    const float* wkv_b    = (const float*)d_in[6];
    const float* wo       = (const float*)d_in[7];
    const float* cosp     = (const float*)d_in[8];
    const float* sinp     = (const float*)d_in[9];
    float* out = (float*)d_out;

    __half *xh, *wqah, *wkvah, *wqbh, *woh, *wvh, *wnh;
    __half *q1, *kvb, *q2, *kp, *vt, *ov;
    cudaGetSymbolAddress((void**)&xh,   g_xh);
    cudaGetSymbolAddress((void**)&wqah, g_wqah);
    cudaGetSymbolAddress((void**)&wkvah,g_wkvah);
    cudaGetSymbolAddress((void**)&wqbh, g_wqbh);
    cudaGetSymbolAddress((void**)&woh,  g_woh);
    cudaGetSymbolAddress((void**)&wvh,  g_wvh);
    cudaGetSymbolAddress((void**)&wnh,  g_wnh);
    cudaGetSymbolAddress((void**)&q1,   g_q1);
    cudaGetSymbolAddress((void**)&kvb,  g_kv);
    cudaGetSymbolAddress((void**)&q2,   g_q2);
    cudaGetSymbolAddress((void**)&kp,   g_kp);
    cudaGetSymbolAddress((void**)&vt,   g_vt);
    cudaGetSymbolAddress((void**)&ov,   g_ov);

    cudaFuncSetAttribute(gemm_h, cudaFuncAttributeMaxDynamicSharedMemorySize, SMEM_TMA);
    cudaFuncSetAttribute(flash_h, cudaFuncAttributeMaxDynamicSharedMemorySize, SMEM_FA);

    CUtensorMap mXH, mWQA, mWKVA, mWQB, mWO, mWNH, mWVH;
    CUtensorMap mQ1, mKV, mQ2, mKP, mVT, mOV;
    make_map_h(&mXH,  xh,   2048, 4096, 2048);
    make_map_h(&mWQA, wqah, 2048, 1536, 2048);
    make_map_h(&mWKVA,wkvah,2048, 576,  2048);
    make_map_h(&mWQB, wqbh, 1536, 3072, 1536);
    make_map_h(&mWO,  woh,  2048, 2048, 2048);
    make_map_h(&mWNH, wnh,  512,  2048, 512);
    make_map_h(&mWVH, wvh,  512,  2048, 512);
    make_map_h(&mQ1,  q1,   1536, 4096, 1536);
    make_map_h(&mKV,  kvb,  576,  4096, 576);
    make_map_h(&mQ2,  q2,   3072, 4096, 3072);
    make_map_h(&mKP,  kp,   3072, 4096, 3072);
    make_map_h(&mVT,  vt,   2048, 4096, 2048);
    make_map_h(&mOV,  ov,   2048, 4096, 2048);

    // ---- streams/events: created ONCE (driver-side pools count as device
    //      memory, so per-call creation trips the allocation guard). The
    //      launched work is identical on every call; only handles persist.
    static bool s_init = false;
    static cudaStream_t s1, s2, s3;
    static cudaEvent_t evRoot, evX, evWQB, evWO, evWNH, evKVP, evKP, evVT;
    if (!s_init) {
        cudaStreamCreateWithFlags(&s1, cudaStreamNonBlocking);
        cudaStreamCreateWithFlags(&s2, cudaStreamNonBlocking);
        cudaStreamCreateWithFlags(&s3, cudaStreamNonBlocking);
        cudaEventCreateWithFlags(&evRoot, cudaEventDisableTiming);
        cudaEventCreateWithFlags(&evX,    cudaEventDisableTiming);
        cudaEventCreateWithFlags(&evWQB,  cudaEventDisableTiming);
        cudaEventCreateWithFlags(&evWO,   cudaEventDisableTiming);
        cudaEventCreateWithFlags(&evWNH,  cudaEventDisableTiming);
        cudaEventCreateWithFlags(&evKVP,  cudaEventDisableTiming);
        cudaEventCreateWithFlags(&evKP,   cudaEventDisableTiming);
        cudaEventCreateWithFlags(&evVT,   cudaEventDisableTiming);
        s_init = true;
    }

    // ---- origin stream (0): root event, then x convert
    cudaEventRecord(evRoot, 0);
    f2h_copy<<<8192, 256>>>(x, xh, 2097152);
    cudaEventRecord(evX, 0);

    // ---- s1: big weight converts (fork from root)
    cudaStreamWaitEvent(s1, evRoot, 0);
    f2h_copy<<<4608, 256, 0, s1>>>(wq_b, wqbh, 1179648);
    cudaEventRecord(evWQB, s1);
    f2h_copy<<<4096, 256, 0, s1>>>(wo, woh, 1048576);
    cudaEventRecord(evWO, s1);

    // ---- s3: per-head weight converts (fork from root)
    cudaStreamWaitEvent(s3, evRoot, 0);
    f2h_head<<<1024, 256, 0, s3>>>(wkv_b, wnh, 0);
    cudaEventRecord(evWNH, s3);
    f2h_head<<<1024, 256, 0, s3>>>(wkv_b, wvh, 65536);

    // ---- s2: KV chain (fork from evX)
    cudaStreamWaitEvent(s2, evX, 0);
    f2h_copy<<<1152, 256, 0, s2>>>(wkv_a, wkvah, 294912);
    gemm_h<<<dim3(5, 32, 1), 256, SMEM_TMA, s2>>>(mXH, mWKVA, 0,0,0,0, 0,0,0,0,
        nullptr, kvb, 576, 0, 0, 4096, 576, 2048, 0, 0);
    kv_process_h<<<4096, 128, 0, s2>>>(kvb, kv_norm_w, cosp, sinp);
    cudaEventRecord(evKVP, s2);
    cudaStreamWaitEvent(s2, evWNH, 0);
    gemm_h<<<dim3(1, 16, 32), 256, SMEM_TMA, s2>>>(mKV, mWNH, 0,0,0,2048, 0,128,0,0,
        nullptr, kp, 3072, 192, (long long)2048*3072, 2048, 128, 512, 0, 0);
    kpe_dup<<<8192, 256, 0, s2>>>(kvb, kp);
    cudaEventRecord(evKP, s2);

    // ---- s3 continued: V_h after kv_process + wvh
    cudaStreamWaitEvent(s3, evKVP, 0);
    gemm_h<<<dim3(16, 1, 32), 256, SMEM_TMA, s3>>>(mWVH, mKV, 0,128,0,0, 0,0,0,2048,
        nullptr, vt, 2048, (long long)128*2048, (long long)16*128*2048,
        128, 2048, 512, 0, 0);
    cudaEventRecord(evVT, s3);

    // ---- origin stream: Q chain
    f2h_copy<<<3072, 256>>>(wq_a, wqah, 786432);
    gemm_h<<<dim3(12, 32, 1), 256, SMEM_TMA>>>(mXH, mWQA, 0,0,0,0, 0,0,0,0,
        nullptr, q1, 1536, 0, 0, 4096, 1536, 2048, 0, 0);
    rmsnorm_h<<<4096, 256>>>(q1, q_norm_w, 1536);
    cudaStreamWaitEvent(0, evWQB, 0);
    gemm_h<<<dim3(24, 32, 1), 256, SMEM_TMA>>>(mQ1, mWQB, 0,0,0,0, 0,0,0,0,
        nullptr, q2, 3072, 0, 0, 4096, 3072, 1536, 0, 0);
    rope_q2<<<8192, 256>>>(q2, cosp, sinp);

    // ---- join: flash needs q2 (origin), Kp (s2), Vt (s3)
    cudaStreamWaitEvent(0, evKP, 0);
    cudaStreamWaitEvent(0, evVT, 0);
    flash_h<<<dim3(16, 32, 1), 256, SMEM_FA>>>(mQ2, mKP, mVT, ov);

    // ---- out = ov @ wo^T (fp32)
    cudaStreamWaitEvent(0, evWO, 0);
    gemm_h<<<dim3(16, 32, 1), 256, SMEM_TMA>>>(mOV, mWO, 0,0,0,0, 0,0,0,0,
        out, nullptr, 2048, 0, 0, 4096, 2048, 2048, 0, 0);
}

// round 13
// speedup vs baseline: 4.9591x; 1.0707x over previous
#include <cuda_runtime.h>
#include <cuda_fp16.h>
#include <cuda.h>
#include <cstdint>
#include <dlfcn.h>

#define CS 2048
#define CH 16
#define FA_C 0.10411754f   // 192^-0.5 * log2(e)

// ---------------- scratch (device globals, fp16 operands) -------------------
__device__ __align__(256) __half g_xh [(size_t)4096*2048];
__device__ __align__(256) __half g_wqah[(size_t)1536*2048];
__device__ __align__(256) __half g_wkvah[(size_t)576*2048];
__device__ __align__(256) __half g_wqbh[(size_t)3072*1536];
__device__ __align__(256) __half g_woh[(size_t)2048*2048];
__device__ __align__(256) __half g_wvh[(size_t)16*128*512];   // w_v per head [128][512]
__device__ __align__(256) __half g_wnh[(size_t)16*128*512];   // w_nope per head [128][512]
__device__ __align__(256) __half g_q1 [(size_t)4096*1536];
__device__ __align__(256) __half g_kv [(size_t)4096*576];
__device__ __align__(256) __half g_q2 [(size_t)4096*3072];    // rope applied in place
__device__ __align__(256) __half g_kp [(size_t)4096*3072];    // per-head K
__device__ __align__(256) __half g_vt [(size_t)32*128*2048];  // per (b,h): V^T [128][2048]
__device__ __align__(256) __half g_ov [(size_t)4096*2048];

// ---------------- ptx helpers ----------------
__device__ __forceinline__ void mma_fp16(float* c, const uint32_t* a, uint32_t b0, uint32_t b1) {
    asm volatile(
        "mma.sync.aligned.m16n8k16.row.col.f32.f16.f16.f32 "
        "{%0,%1,%2,%3},{%4,%5,%6,%7},{%8,%9},{%0,%1,%2,%3};"
        : "+f"(c[0]), "+f"(c[1]), "+f"(c[2]), "+f"(c[3])
        : "r"(a[0]), "r"(a[1]), "r"(a[2]), "r"(a[3]), "r"(b0), "r"(b1));
}
__device__ __forceinline__ void ldsm4(uint32_t* r, uint32_t addr) {
    asm volatile("ldmatrix.sync.aligned.m8n8.x4.shared.b16 {%0,%1,%2,%3}, [%4];"
        : "=r"(r[0]), "=r"(r[1]), "=r"(r[2]), "=r"(r[3]) : "r"(addr));
}
#define MBAR_INIT(a, c) \
    asm volatile("mbarrier.init.shared.b64 [%0], %1;" :: "r"(a), "r"(c) : "memory")
#define MBAR_EXPECT(a, tx) \
    asm volatile("mbarrier.arrive.expect_tx.shared.b64 _, [%0], %1;" :: "r"(a), "r"(tx) : "memory")
#define MBAR_WAIT(a, ph) do { \
    asm volatile("{\n\t.reg .pred P1;\n\tWL%=:\n\t" \
        "mbarrier.try_wait.parity.acquire.cta.shared::cta.b64 P1, [%0], %1, 0x989680;\n\t" \
        "@P1 bra.uni WD%=;\n\tbra.uni WL%=;\n\tWD%=:\n\t}" \
        :: "r"(a), "r"(ph) : "memory"); } while (0)
__device__ __forceinline__ void tma2d(uint32_t dst, const void* map, int x, int y, uint32_t mbar) {
    asm volatile(
        "cp.async.bulk.tensor.2d.shared::cta.global.tile.mbarrier::complete_tx::bytes "
        "[%0], [%1, {%2, %3}], [%4];"
        :: "r"(dst), "l"(map), "r"(x), "r"(y), "r"(mbar) : "memory");
}
__device__ __forceinline__ float ex2(float x) {
    float y; asm("ex2.approx.f32 %0, %1;" : "=f"(y) : "f"(x)); return y;
}

// Per-lane ldmatrix address selectors (match mma fragment layouts):
// A-frag x4: {m+0/k0, m+8/k0, m+0/k8, m+8/k8}
//   rowA = ((lane>>3)&1)*8 + (lane&7), khalfA = ((lane>>4)&1)*16
// B-frag x4: {n grp0/k0, grp0/k8, grp1/k0, grp1/k8}
//   rowB = ((lane>>4)&1)*8 + (lane&7), khalfB = ((lane>>3)&1)*16
// SW128 per-row XOR: (lane&7)<<4

// ---------------- TMA fp16 GEMM (ldmatrix mainloop) ---------------------------
#define NST 3
#define STAGE 32768
#define SMEM_TMA (1024 + NST * STAGE)

__global__ __launch_bounds__(256, 2) void gemm_h(
    const __grid_constant__ CUtensorMap mA,
    const __grid_constant__ CUtensorMap mB,
    int axh, int ayh, int axb, int ayb,
    int bxh, int byh, int bxb, int byb,
    float* __restrict__ Cf, __half* __restrict__ Chh,
    int ldc, long long strCh, long long strCb,
    int M, int N, int K, int causal, int kclamp)
{
    int bm = blockIdx.y, bn = blockIdx.x;
    if (kclamp) bm = gridDim.y - 1 - bm;
    if (causal && bn > bm) return;
    int zh = blockIdx.z & 15, zb = blockIdx.z >> 4;
    if (Cf) Cf += (long long)zh * strCh + (long long)zb * strCb;
    else    Chh += (long long)zh * strCh + (long long)zb * strCb;
    int m0 = bm * 128, n0 = bn * 128;
    int Keff = kclamp ? (K < m0 + 128 ? K : m0 + 128) : K;
    int ntk = Keff >> 6;

    extern __shared__ __align__(1024) char smem[];
    uint32_t sbase = (uint32_t)__cvta_generic_to_shared(smem);

    int tid = threadIdx.x;
    int wid = tid >> 5, lane = tid & 31;
    int wm = wid >> 1, wn = wid & 1;
    int g = lane >> 2, tg = lane & 3;

    uint32_t swzr  = (uint32_t)(lane & 7) << 4;
    uint32_t rowA  = (uint32_t)(((lane >> 3) & 1) * 8 + (lane & 7));
    uint32_t khA   = (uint32_t)(((lane >> 4) & 1) * 16);
    uint32_t rowB  = (uint32_t)(((lane >> 4) & 1) * 8 + (lane & 7));
    uint32_t khB   = (uint32_t)(((lane >> 3) & 1) * 16);

    if (tid == 0) {
#pragma unroll
        for (int s = 0; s < NST; s++) MBAR_INIT(sbase + s * 8, 1);
    }
    __syncthreads();

    int xa = zh * axh + zb * axb, ya = m0 + zh * ayh + zb * ayb;
    int xb = zh * bxh + zb * bxb, yb = n0 + zh * byh + zb * byb;

    auto issue = [&](int j, int jb) {
        uint32_t mb = sbase + jb * 8;
        uint32_t da = sbase + 1024 + jb * STAGE;
        int k0 = j * 64;
        MBAR_EXPECT(mb, STAGE);
        tma2d(da, &mA, xa + k0, ya, mb);
        tma2d(da + 16384, &mB, xb + k0, yb, mb);
    };

    if (tid == 0) {
        issue(0, 0);
        if (ntk > 1) issue(1, 1);
    }

    float acc[2][8][4];
#pragma unroll
    for (int mi = 0; mi < 2; mi++)
#pragma unroll
        for (int j = 0; j < 8; j++)
#pragma unroll
            for (int r = 0; r < 4; r++) acc[mi][j][r] = 0.f;

    int buf = 0, ph = 0;
    int pj = NST - 1, pbuf = NST - 1;

    for (int kt = 0; kt < ntk; kt++) {
        MBAR_WAIT(sbase + buf * 8, ph);
        uint32_t As_u = sbase + 1024 + buf * STAGE;
        uint32_t Bs_u = As_u + 16384;
#pragma unroll
        for (int ks = 0; ks < 4; ks++) {
            uint32_t cb = (uint32_t)(ks * 32);
            uint32_t a[2][4];
            ldsm4(a[0], As_u + (wm * 32 +      rowA) * 128 + ((cb + khA) ^ swzr));
            ldsm4(a[1], As_u + (wm * 32 + 16 + rowA) * 128 + ((cb + khA) ^ swzr));
#pragma unroll
            for (int p = 0; p < 4; p++) {
                uint32_t bb[4];
                ldsm4(bb, Bs_u + (wn * 64 + p * 16 + rowB) * 128 + ((cb + khB) ^ swzr));
                mma_fp16(acc[0][2*p],   a[0], bb[0], bb[1]);
                mma_fp16(acc[1][2*p],   a[1], bb[0], bb[1]);
                mma_fp16(acc[0][2*p+1], a[0], bb[2], bb[3]);
                mma_fp16(acc[1][2*p+1], a[1], bb[2], bb[3]);
            }
        }
        __syncthreads();
        if (tid == 0 && pj < ntk) issue(pj, pbuf);
        pj++;
        if (++pbuf == NST) pbuf = 0;
        if (++buf == NST) { buf = 0; ph ^= 1; }
    }

#pragma unroll
    for (int mi = 0; mi < 2; mi++) {
#pragma unroll
        for (int j = 0; j < 8; j++) {
            int row = m0 + wm * 32 + mi * 16 + g;
            int col = n0 + wn * 64 + j * 8 + 2 * tg;
            if (col < N) {
                float v0 = acc[mi][j][0], v1 = acc[mi][j][1];
                float v2 = acc[mi][j][2], v3 = acc[mi][j][3];
                if (Cf) {
                    *(float2*)&Cf[(long long)row * ldc + col] = make_float2(v0, v1);
                    *(float2*)&Cf[(long long)(row + 8) * ldc + col] = make_float2(v2, v3);
                } else {
                    *(__half2*)&Chh[(long long)row * ldc + col] = __floats2half2_rn(v0, v1);
                    *(__half2*)&Chh[(long long)(row + 8) * ldc + col] = __floats2half2_rn(v2, v3);
                }
            }
        }
    }
}

// ---------------- fused flash attention (ldmatrix operand loads) -------------
#define SMQ_OFF 1024
#define RING_OFF (SMQ_OFF + 49152)
#define KVSTG 81920
#define SMEM_FA (RING_OFF + 2 * KVSTG)   // 214016

__global__ __launch_bounds__(256, 1) void flash_h(
    const __grid_constant__ CUtensorMap mQ,
    const __grid_constant__ CUtensorMap mK,
    const __grid_constant__ CUtensorMap mV,
    __half* __restrict__ ov)
{
    int qt = (int)gridDim.x - 1 - (int)blockIdx.x;   // heavy tiles first
    int bh = blockIdx.y;
    int b = bh >> 4, h = bh & 15;
    int ntk = qt + 1;

    extern __shared__ __align__(1024) char smem[];
    uint32_t sbase = (uint32_t)__cvta_generic_to_shared(smem);

    int tid = threadIdx.x;
    int wid = tid >> 5, lane = tid & 31;
    int g = lane >> 2, tg = lane & 3;

    uint32_t swzr = (uint32_t)(lane & 7) << 4;
    uint32_t rowA = (uint32_t)(((lane >> 3) & 1) * 8 + (lane & 7));
    uint32_t khA  = (uint32_t)(((lane >> 4) & 1) * 16);
    uint32_t rowB = (uint32_t)(((lane >> 4) & 1) * 8 + (lane & 7));
    uint32_t khB  = (uint32_t)(((lane >> 3) & 1) * 16);

    if (tid == 0) {
        MBAR_INIT(sbase + 0, 1);
        MBAR_INIT(sbase + 8, 1);
        MBAR_INIT(sbase + 16, 1);
    }
    __syncthreads();

    auto issueKV = [&](int kt, int st) {
        uint32_t mb = sbase + 8 + st * 8;
        uint32_t base = sbase + RING_OFF + st * KVSTG;
        MBAR_EXPECT(mb, KVSTG);
#pragma unroll
        for (int c = 0; c < 3; c++)
            tma2d(base + c * 16384, &mK, h * 192 + c * 64, b * 2048 + kt * 128, mb);
#pragma unroll
        for (int c = 0; c < 2; c++)
            tma2d(base + 49152 + c * 16384, &mV, kt * 128 + c * 64, bh * 128, mb);
    };

    if (tid == 0) {
        MBAR_EXPECT(sbase + 0, 49152);
#pragma unroll
        for (int c = 0; c < 3; c++)
            tma2d(sbase + SMQ_OFF + c * 16384, &mQ, h * 192 + c * 64, b * 2048 + qt * 128, sbase + 0);
        issueKV(0, 0);
        if (ntk > 1) issueKV(1, 1);
    }

    // Q fragments to registers (ldmatrix.x4 per 16-fp16 k chunk)
    MBAR_WAIT(sbase + 0, 0);
    uint32_t qf[12][4];
#pragma unroll
    for (int kk = 0; kk < 12; kk++) {
        uint32_t ch = sbase + SMQ_OFF + (kk >> 2) * 16384;
        uint32_t cb = (uint32_t)((kk & 3) * 32);
        ldsm4(qf[kk], ch + (wid * 16 + rowA) * 128 + ((cb + khA) ^ swzr));
    }

    float of[16][4];
#pragma unroll
    for (int j = 0; j < 16; j++)
#pragma unroll
        for (int r = 0; r < 4; r++) of[j][r] = 0.f;
    float m0r = -1e30f, m1r = -1e30f, l0r = 0.f, l1r = 0.f;

    for (int kt = 0; kt < ntk; kt++) {
        int st = kt & 1;
        MBAR_WAIT(sbase + 8 + st * 8, (kt >> 1) & 1);
        uint32_t kbs = sbase + RING_OFF + st * KVSTG;
        uint32_t vbs = kbs + 49152;

        // S = Q @ K^T
        float sj[16][4];
#pragma unroll
        for (int j = 0; j < 16; j++)
#pragma unroll
            for (int r = 0; r < 4; r++) sj[j][r] = 0.f;
#pragma unroll
        for (int kk = 0; kk < 12; kk++) {
            uint32_t ch = kbs + (kk >> 2) * 16384;
            uint32_t cb = (uint32_t)((kk & 3) * 32);
#pragma unroll
            for (int p = 0; p < 8; p++) {
                uint32_t bb[4];
                ldsm4(bb, ch + (p * 16 + rowB) * 128 + ((cb + khB) ^ swzr));
                mma_fp16(sj[2*p],   qf[kk], bb[0], bb[1]);
                mma_fp16(sj[2*p+1], qf[kk], bb[2], bb[3]);
            }
        }

        // causal mask on diagonal tile
        if (kt == qt) {
            int r0 = wid * 16 + g, r1 = r0 + 8;
#pragma unroll
            for (int jn = 0; jn < 16; jn++) {
                int c0 = jn * 8 + 2 * tg, c1 = c0 + 1;
                if (c0 > r0) sj[jn][0] = -1e30f;
                if (c1 > r0) sj[jn][1] = -1e30f;
                if (c0 > r1) sj[jn][2] = -1e30f;
                if (c1 > r1) sj[jn][3] = -1e30f;
            }
        }

        // online softmax
        float mx0 = -1e30f, mx1 = -1e30f;
#pragma unroll
        for (int jn = 0; jn < 16; jn++) {
            mx0 = fmaxf(mx0, fmaxf(sj[jn][0], sj[jn][1]));
            mx1 = fmaxf(mx1, fmaxf(sj[jn][2], sj[jn][3]));
        }
        mx0 = fmaxf(mx0, __shfl_xor_sync(0xffffffffu, mx0, 1));
        mx0 = fmaxf(mx0, __shfl_xor_sync(0xffffffffu, mx0, 2));
        mx1 = fmaxf(mx1, __shfl_xor_sync(0xffffffffu, mx1, 1));
        mx1 = fmaxf(mx1, __shfl_xor_sync(0xffffffffu, mx1, 2));
        float mn0 = fmaxf(m0r, mx0), mn1 = fmaxf(m1r, mx1);
        float f0 = ex2((m0r - mn0) * FA_C), f1 = ex2((m1r - mn1) * FA_C);
        m0r = mn0; m1r = mn1;

        float s0 = 0.f, s1 = 0.f;
        uint32_t pjf[8][4];
#pragma unroll
        for (int u = 0; u < 8; u++) {
            float e00 = ex2((sj[2*u][0] - mn0) * FA_C);
            float e01 = ex2((sj[2*u][1] - mn0) * FA_C);
            float e02 = ex2((sj[2*u][2] - mn1) * FA_C);
            float e03 = ex2((sj[2*u][3] - mn1) * FA_C);
            float e10 = ex2((sj[2*u+1][0] - mn0) * FA_C);
            float e11 = ex2((sj[2*u+1][1] - mn0) * FA_C);
            float e12 = ex2((sj[2*u+1][2] - mn1) * FA_C);
            float e13 = ex2((sj[2*u+1][3] - mn1) * FA_C);
            s0 += e00 + e01 + e10 + e11;
            s1 += e02 + e03 + e12 + e13;
            __half2 h0 = __floats2half2_rn(e00, e01);
            __half2 h1 = __floats2half2_rn(e02, e03);
            __half2 h2 = __floats2half2_rn(e10, e11);
            __half2 h3 = __floats2half2_rn(e12, e13);
            pjf[u][0] = *(uint32_t*)&h0;
            pjf[u][1] = *(uint32_t*)&h1;
            pjf[u][2] = *(uint32_t*)&h2;
            pjf[u][3] = *(uint32_t*)&h3;
        }
        s0 += __shfl_xor_sync(0xffffffffu, s0, 1);
        s0 += __shfl_xor_sync(0xffffffffu, s0, 2);
        s1 += __shfl_xor_sync(0xffffffffu, s1, 1);
        s1 += __shfl_xor_sync(0xffffffffu, s1, 2);
        l0r = l0r * f0 + s0;
        l1r = l1r * f1 + s1;

#pragma unroll
        for (int j = 0; j < 16; j++) {
            of[j][0] *= f0; of[j][1] *= f0;
            of[j][2] *= f1; of[j][3] *= f1;
        }

        // O += P @ V (V^T rows = dv, cols = keys)
#pragma unroll
        for (int u = 0; u < 8; u++) {
            uint32_t ch = vbs + (u >> 2) * 16384;
            uint32_t cb = (uint32_t)((u & 3) * 32);
#pragma unroll
            for (int p = 0; p < 8; p++) {
                uint32_t bb[4];
                ldsm4(bb, ch + (p * 16 + rowB) * 128 + ((cb + khB) ^ swzr));
                mma_fp16(of[2*p],   pjf[u], bb[0], bb[1]);
                mma_fp16(of[2*p+1], pjf[u], bb[2], bb[3]);
            }
        }

        __syncthreads();
        if (tid == 0 && kt + 2 < ntk) issueKV(kt + 2, st);
    }

    float inv0 = 1.f / l0r, inv1 = 1.f / l1r;
    long long row0 = (long long)b * 2048 + qt * 128 + wid * 16 + g;
#pragma unroll
    for (int jn = 0; jn < 16; jn++) {
        int d = h * 128 + jn * 8 + 2 * tg;
        __half2 h0 = __floats2half2_rn(of[jn][0] * inv0, of[jn][1] * inv0);
        __half2 h1 = __floats2half2_rn(of[jn][2] * inv1, of[jn][3] * inv1);
        *(__half2*)&ov[row0 * 2048 + d] = h0;
        *(__half2*)&ov[(row0 + 8) * 2048 + d] = h1;
    }
}

// ---------------- prep: fp32 -> fp16 copies ----------------------------------
__global__ void f2h_copy(const float* __restrict__ s, __half* __restrict__ d, long long n4)
{
    long long i = (long long)blockIdx.x * 256 + threadIdx.x;
    if (i >= n4) return;
    float4 v = ((const float4*)s)[i];
    __half2 h0 = __floats2half2_rn(v.x, v.y);
    __half2 h1 = __floats2half2_rn(v.z, v.w);
    ((uint2*)d)[i] = make_uint2(*(uint32_t*)&h0, *(uint32_t*)&h1);
}

__global__ void f2h_head(const float* __restrict__ wkvb, __half* __restrict__ d, int srcOff)
{
    long long i4 = (long long)blockIdx.x * 256 + threadIdx.x;
    long long head = i4 >> 14, off = (i4 & 16383) * 4;
    float4 v = *(const float4*)(wkvb + head * 131072 + srcOff + off);
    __half2 h0 = __floats2half2_rn(v.x, v.y);
    __half2 h1 = __floats2half2_rn(v.z, v.w);
    ((uint2*)d)[i4] = make_uint2(*(uint32_t*)&h0, *(uint32_t*)&h1);
}

// ---------------- rmsnorm rows (fp16 data, fp32 math) ------------------------
__global__ void rmsnorm_h(__half* __restrict__ x, const float* __restrict__ w, int n)
{
    long long row = blockIdx.x;
    __half* r = x + row * n;
    float ss = 0.f;
    for (int i = threadIdx.x; i < n; i += 256) { float v = __half2float(r[i]); ss += v * v; }
    __shared__ float red[8];
#pragma unroll
    for (int o = 16; o; o >>= 1) ss += __shfl_xor_sync(0xffffffffu, ss, o);
    if ((threadIdx.x & 31) == 0) red[threadIdx.x >> 5] = ss;
    __syncthreads();
    float tot = 0.f;
#pragma unroll
    for (int wv = 0; wv < 8; wv++) tot += red[wv];
    float scale = rsqrtf(tot / (float)n + 1e-6f);
    for (int i = threadIdx.x; i < n; i += 256)
        r[i] = __float2half_rn(__half2float(r[i]) * scale * w[i]);
}

// -------- kv row: rmsnorm first 512 (+w), rope last 64 (fp16 data) -----------
__global__ void kv_process_h(__half* __restrict__ kv, const float* __restrict__ w,
                             const float* __restrict__ cosp, const float* __restrict__ sinp)
{
    int row = blockIdx.x;
    int s = row % CS;
    __half* r = kv + (long long)row * 576;
    float ss = 0.f;
    for (int i = threadIdx.x; i < 512; i += 128) { float v = __half2float(r[i]); ss += v * v; }
    __shared__ float red[4];
#pragma unroll
    for (int o = 16; o; o >>= 1) ss += __shfl_xor_sync(0xffffffffu, ss, o);
    if ((threadIdx.x & 31) == 0) red[threadIdx.x >> 5] = ss;
    __syncthreads();
    float tot = red[0] + red[1] + red[2] + red[3];
    float scale = rsqrtf(tot / 512.f + 1e-6f);
    for (int i = threadIdx.x; i < 512; i += 128)
        r[i] = __float2half_rn(__half2float(r[i]) * scale * w[i]);
    if (threadIdx.x < 32) {
        int i = threadIdx.x;
        float x0 = __half2float(r[512 + 2 * i]), x1 = __half2float(r[513 + 2 * i]);
        float c = cosp[s * 32 + i], sn = sinp[s * 32 + i];
        r[512 + 2 * i] = __float2half_rn(x0 * c - x1 * sn);
        r[513 + 2 * i] = __float2half_rn(x0 * sn + x1 * c);
    }
}

// ---------------- RoPE on q2 in place ----------------------------------------
__global__ void rope_q2(__half* __restrict__ q2,
                        const float* __restrict__ cosp, const float* __restrict__ sinp)
{
    int idx = blockIdx.x * 256 + threadIdx.x;
    if (idx >= 4096 * CH * 32) return;
    int i = idx & 31;
    int h = (idx >> 5) & 15;
    int row = idx >> 9;
    int s = row % CS;
    __half* p = q2 + (long long)row * 3072 + h * 192 + 128 + 2 * i;
    float x0 = __half2float(p[0]), x1 = __half2float(p[1]);
    float c = cosp[s * 32 + i], sn = sinp[s * 32 + i];
    p[0] = __float2half_rn(x0 * c - x1 * sn);
    p[1] = __float2half_rn(x0 * sn + x1 * c);
}

// ---------------- duplicate roped k_pe into Kp per head -----------------------
__global__ void kpe_dup(const __half* __restrict__ kv, __half* __restrict__ kp)
{
    int idx = blockIdx.x * 256 + threadIdx.x;
    if (idx >= 2 * 2048 * 16 * 32) return;
    int j2 = idx & 31;
    int h = (idx >> 5) & 15;
    int row = idx >> 9;
    uint32_t v = *(const uint32_t*)(kv + (long long)row * 576 + 512 + 2 * j2);
    *(uint32_t*)(kp + (long long)row * 3072 + h * 192 + 128 + 2 * j2) = v;
}

// ---------------- host: tensormap encode via dlopen(libcuda) -----------------
typedef CUresult (*PFN_tmEncode)(
    CUtensorMap*, CUtensorMapDataType, cuuint32_t, void*,
    const cuuint64_t*, const cuuint64_t*, const cuuint32_t*, const cuuint32_t*,
    CUtensorMapInterleave, CUtensorMapSwizzle, CUtensorMapL2promotion,
    CUtensorMapFloatOOBfill);

static PFN_tmEncode tm_encode()
{
    static PFN_tmEncode fn = nullptr;
    if (!fn) {
        void* h = dlopen("libcuda.so.1", RTLD_NOW | RTLD_GLOBAL);
        if (!h) h = dlopen("libcuda.so", RTLD_NOW | RTLD_GLOBAL);
        if (h) fn = (PFN_tmEncode)dlsym(h, "cuTensorMapEncodeTiled");
    }
    return fn;
}

static void make_map_h(CUtensorMap* m, void* base, long long cols, long long rows, long long ld)
{
    cuuint64_t dims[2]    = {(cuuint64_t)cols, (cuuint64_t)rows};
    cuuint64_t strides[1] = {(cuuint64_t)(ld * 2)};
    cuuint32_t box[2]     = {64u, 128u};
    cuuint32_t es[2]      = {1u, 1u};
    tm_encode()(m, CU_TENSOR_MAP_DATA_TYPE_FLOAT16, 2, base, dims, strides, box, es,
                CU_TENSOR_MAP_INTERLEAVE_NONE, CU_TENSOR_MAP_SWIZZLE_128B,
                CU_TENSOR_MAP_L2_PROMOTION_L2_128B, CU_TENSOR_MAP_FLOAT_OOB_FILL_NONE);
}

// ---------------------------------------------------------------------------
extern "C" void kernel_launch(void* const* d_in, const int* in_sizes, int n_in,
                              void* d_out, int out_size)
{
    (void)in_sizes; (void)n_in; (void)out_size;
    const float* x        = (const float*)d_in[0];
    const float* wq_a     = (const float*)d_in[1];
    const float* q_norm_w = (const float*)d_in[2];
    const float* wq_b     = (const float*)d_in[3];
    const float* wkv_a    = (const float*)d_in[4];
    const float* kv_norm_w= (const float*)d_in[5];
    const float* wkv_b    = (const float*)d_in[6];
    const float* wo       = (const float*)d_in[7];
    const float* cosp     = (const float*)d_in[8];
    const float* sinp     = (const float*)d_in[9];
    float* out = (float*)d_out;

    __half *xh, *wqah, *wkvah, *wqbh, *woh, *wvh, *wnh;
    __half *q1, *kvb, *q2, *kp, *vt, *ov;
    cudaGetSymbolAddress((void**)&xh,   g_xh);
    cudaGetSymbolAddress((void**)&wqah, g_wqah);
    cudaGetSymbolAddress((void**)&wkvah,g_wkvah);
    cudaGetSymbolAddress((void**)&wqbh, g_wqbh);
    cudaGetSymbolAddress((void**)&woh,  g_woh);
    cudaGetSymbolAddress((void**)&wvh,  g_wvh);
    cudaGetSymbolAddress((void**)&wnh,  g_wnh);
    cudaGetSymbolAddress((void**)&q1,   g_q1);
    cudaGetSymbolAddress((void**)&kvb,  g_kv);
    cudaGetSymbolAddress((void**)&q2,   g_q2);
    cudaGetSymbolAddress((void**)&kp,   g_kp);
    cudaGetSymbolAddress((void**)&vt,   g_vt);
    cudaGetSymbolAddress((void**)&ov,   g_ov);

    cudaFuncSetAttribute(gemm_h, cudaFuncAttributeMaxDynamicSharedMemorySize, SMEM_TMA);
    cudaFuncSetAttribute(flash_h, cudaFuncAttributeMaxDynamicSharedMemorySize, SMEM_FA);

    CUtensorMap mXH, mWQA, mWKVA, mWQB, mWO, mWNH, mWVH;
    CUtensorMap mQ1, mKV, mQ2, mKP, mVT, mOV;
    make_map_h(&mXH,  xh,   2048, 4096, 2048);
    make_map_h(&mWQA, wqah, 2048, 1536, 2048);
    make_map_h(&mWKVA,wkvah,2048, 576,  2048);
    make_map_h(&mWQB, wqbh, 1536, 3072, 1536);
    make_map_h(&mWO,  woh,  2048, 2048, 2048);
    make_map_h(&mWNH, wnh,  512,  2048, 512);
    make_map_h(&mWVH, wvh,  512,  2048, 512);
    make_map_h(&mQ1,  q1,   1536, 4096, 1536);
    make_map_h(&mKV,  kvb,  576,  4096, 576);
    make_map_h(&mQ2,  q2,   3072, 4096, 3072);
    make_map_h(&mKP,  kp,   3072, 4096, 3072);
    make_map_h(&mVT,  vt,   2048, 4096, 2048);
    make_map_h(&mOV,  ov,   2048, 4096, 2048);

    // ---- streams/events: created ONCE (driver pools count as device memory)
    static bool s_init = false;
    static cudaStream_t s1, s2, s3;
    static cudaEvent_t evRoot, evX, evWQB, evWO, evWNH, evKVP, evKP, evVT;
    if (!s_init) {
        cudaStreamCreateWithFlags(&s1, cudaStreamNonBlocking);
        cudaStreamCreateWithFlags(&s2, cudaStreamNonBlocking);
        cudaStreamCreateWithFlags(&s3, cudaStreamNonBlocking);
        cudaEventCreateWithFlags(&evRoot, cudaEventDisableTiming);
        cudaEventCreateWithFlags(&evX,    cudaEventDisableTiming);
        cudaEventCreateWithFlags(&evWQB,  cudaEventDisableTiming);
        cudaEventCreateWithFlags(&evWO,   cudaEventDisableTiming);
        cudaEventCreateWithFlags(&evWNH,  cudaEventDisableTiming);
        cudaEventCreateWithFlags(&evKVP,  cudaEventDisableTiming);
        cudaEventCreateWithFlags(&evKP,   cudaEventDisableTiming);
        cudaEventCreateWithFlags(&evVT,   cudaEventDisableTiming);
        s_init = true;
    }

    // ---- origin stream (0): root event, then x convert
    cudaEventRecord(evRoot, 0);
    f2h_copy<<<8192, 256>>>(x, xh, 2097152);
    cudaEventRecord(evX, 0);

    // ---- s1: big weight converts (fork from root)
    cudaStreamWaitEvent(s1, evRoot, 0);
    f2h_copy<<<4608, 256, 0, s1>>>(wq_b, wqbh, 1179648);
    cudaEventRecord(evWQB, s1);
    f2h_copy<<<4096, 256, 0, s1>>>(wo, woh, 1048576);
    cudaEventRecord(evWO, s1);

    // ---- s3: per-head weight converts (fork from root)
    cudaStreamWaitEvent(s3, evRoot, 0);
    f2h_head<<<1024, 256, 0, s3>>>(wkv_b, wnh, 0);
    cudaEventRecord(evWNH, s3);
    f2h_head<<<1024, 256, 0, s3>>>(wkv_b, wvh, 65536);

    // ---- s2: KV chain (fork from evX)
    cudaStreamWaitEvent(s2, evX, 0);
    f2h_copy<<<1152, 256, 0, s2>>>(wkv_a, wkvah, 294912);
    gemm_h<<<dim3(5, 32, 1), 256, SMEM_TMA, s2>>>(mXH, mWKVA, 0,0,0,0, 0,0,0,0,
        nullptr, kvb, 576, 0, 0, 4096, 576, 2048, 0, 0);
    kv_process_h<<<4096, 128, 0, s2>>>(kvb, kv_norm_w, cosp, sinp);
    cudaEventRecord(evKVP, s2);
    cudaStreamWaitEvent(s2, evWNH, 0);
    gemm_h<<<dim3(1, 16, 32), 256, SMEM_TMA, s2>>>(mKV, mWNH, 0,0,0,2048, 0,128,0,0,
        nullptr, kp, 3072, 192, (long long)2048*3072, 2048, 128, 512, 0, 0);
    kpe_dup<<<8192, 256, 0, s2>>>(kvb, kp);
    cudaEventRecord(evKP, s2);

    // ---- s3 continued: V_h after kv_process + wvh
    cudaStreamWaitEvent(s3, evKVP, 0);
    gemm_h<<<dim3(16, 1, 32), 256, SMEM_TMA, s3>>>(mWVH, mKV, 0,128,0,0, 0,0,0,2048,
        nullptr, vt, 2048, (long long)128*2048, (long long)16*128*2048,
        128, 2048, 512, 0, 0);
    cudaEventRecord(evVT, s3);

    // ---- origin stream: Q chain
    f2h_copy<<<3072, 256>>>(wq_a, wqah, 786432);
    gemm_h<<<dim3(12, 32, 1), 256, SMEM_TMA>>>(mXH, mWQA, 0,0,0,0, 0,0,0,0,
        nullptr, q1, 1536, 0, 0, 4096, 1536, 2048, 0, 0);
    rmsnorm_h<<<4096, 256>>>(q1, q_norm_w, 1536);
    cudaStreamWaitEvent(0, evWQB, 0);
    gemm_h<<<dim3(24, 32, 1), 256, SMEM_TMA>>>(mQ1, mWQB, 0,0,0,0, 0,0,0,0,
        nullptr, q2, 3072, 0, 0, 4096, 3072, 1536, 0, 0);
    rope_q2<<<8192, 256>>>(q2, cosp, sinp);

    // ---- join: flash needs q2 (origin), Kp (s2), Vt (s3)
    cudaStreamWaitEvent(0, evKP, 0);
    cudaStreamWaitEvent(0, evVT, 0);
    flash_h<<<dim3(16, 32, 1), 256, SMEM_FA>>>(mQ2, mKP, mVT, ov);

    // ---- out = ov @ wo^T (fp32)
    cudaStreamWaitEvent(0, evWO, 0);
    gemm_h<<<dim3(16, 32, 1), 256, SMEM_TMA>>>(mOV, mWO, 0,0,0,0, 0,0,0,0,
        out, nullptr, 2048, 0, 0, 4096, 2048, 2048, 0, 0);
}

// round 15
// speedup vs baseline: 5.5932x; 1.1279x over previous
#include <cuda_runtime.h>
#include <cuda_fp16.h>
#include <cuda.h>
#include <cstdint>
#include <dlfcn.h>

#define CS 2048
#define CH 16
#define FA_C 0.10411754f   // 192^-0.5 * log2(e)

// ---------------- scratch (device globals, fp16 operands) -------------------
__device__ __align__(256) __half g_xh [(size_t)4096*2048];
__device__ __align__(256) __half g_wqah[(size_t)1536*2048];
__device__ __align__(256) __half g_wkvah[(size_t)576*2048];
__device__ __align__(256) __half g_wqbh[(size_t)3072*1536];
__device__ __align__(256) __half g_woh[(size_t)2048*2048];
__device__ __align__(256) __half g_wvh[(size_t)16*128*512];
__device__ __align__(256) __half g_wnh[(size_t)16*128*512];
__device__ __align__(256) __half g_q1 [(size_t)4096*1536];
__device__ __align__(256) __half g_kv [(size_t)4096*576];
__device__ __align__(256) __half g_q2 [(size_t)4096*3072];
__device__ __align__(256) __half g_kp [(size_t)4096*3072];
__device__ __align__(256) __half g_vt [(size_t)32*128*2048];
__device__ __align__(256) __half g_ov [(size_t)4096*2048];

// ---------------- ptx helpers ----------------
__device__ __forceinline__ void mma_fp16(float* c, const uint32_t* a, uint32_t b0, uint32_t b1) {
    asm volatile(
        "mma.sync.aligned.m16n8k16.row.col.f32.f16.f16.f32 "
        "{%0,%1,%2,%3},{%4,%5,%6,%7},{%8,%9},{%0,%1,%2,%3};"
        : "+f"(c[0]), "+f"(c[1]), "+f"(c[2]), "+f"(c[3])
        : "r"(a[0]), "r"(a[1]), "r"(a[2]), "r"(a[3]), "r"(b0), "r"(b1));
}
__device__ __forceinline__ void ldsm4(uint32_t* r, uint32_t addr) {
    asm volatile("ldmatrix.sync.aligned.m8n8.x4.shared.b16 {%0,%1,%2,%3}, [%4];"
        : "=r"(r[0]), "=r"(r[1]), "=r"(r[2]), "=r"(r[3]) : "r"(addr));
}
#define MBAR_INIT(a, c) \
    asm volatile("mbarrier.init.shared.b64 [%0], %1;" :: "r"(a), "r"(c) : "memory")
#define MBAR_EXPECT(a, tx) \
    asm volatile("mbarrier.arrive.expect_tx.shared.b64 _, [%0], %1;" :: "r"(a), "r"(tx) : "memory")
#define MBAR_WAIT(a, ph) do { \
    asm volatile("{\n\t.reg .pred P1;\n\tWL%=:\n\t" \
        "mbarrier.try_wait.parity.acquire.cta.shared::cta.b64 P1, [%0], %1, 0x989680;\n\t" \
        "@P1 bra.uni WD%=;\n\tbra.uni WL%=;\n\tWD%=:\n\t}" \
        :: "r"(a), "r"(ph) : "memory"); } while (0)
__device__ __forceinline__ void tma2d(uint32_t dst, const void* map, int x, int y, uint32_t mbar) {
    asm volatile(
        "cp.async.bulk.tensor.2d.shared::cta.global.tile.mbarrier::complete_tx::bytes "
        "[%0], [%1, {%2, %3}], [%4];"
        :: "r"(dst), "l"(map), "r"(x), "r"(y), "r"(mbar) : "memory");
}
__device__ __forceinline__ float ex2(float x) {
    float y; asm("ex2.approx.f32 %0, %1;" : "=f"(y) : "f"(x)); return y;
}

// ---------------- TMA fp16 GEMM (ldmatrix mainloop) ---------------------------
#define NST 3
#define STAGE 32768
#define SMEM_TMA (1024 + NST * STAGE)

__global__ __launch_bounds__(256, 2) void gemm_h(
    const __grid_constant__ CUtensorMap mA,
    const __grid_constant__ CUtensorMap mB,
    int axh, int ayh, int axb, int ayb,
    int bxh, int byh, int bxb, int byb,
    float* __restrict__ Cf, __half* __restrict__ Chh,
    int ldc, long long strCh, long long strCb,
    int M, int N, int K, int causal, int kclamp)
{
    int bm = blockIdx.y, bn = blockIdx.x;
    if (kclamp) bm = gridDim.y - 1 - bm;
    if (causal && bn > bm) return;
    int zh = blockIdx.z & 15, zb = blockIdx.z >> 4;
    if (Cf) Cf += (long long)zh * strCh + (long long)zb * strCb;
    else    Chh += (long long)zh * strCh + (long long)zb * strCb;
    int m0 = bm * 128, n0 = bn * 128;
    int Keff = kclamp ? (K < m0 + 128 ? K : m0 + 128) : K;
    int ntk = Keff >> 6;

    extern __shared__ __align__(1024) char smem[];
    uint32_t sbase = (uint32_t)__cvta_generic_to_shared(smem);

    int tid = threadIdx.x;
    int wid = tid >> 5, lane = tid & 31;
    int wm = wid >> 1, wn = wid & 1;
    int g = lane >> 2, tg = lane & 3;

    uint32_t swzr  = (uint32_t)(lane & 7) << 4;
    uint32_t rowA  = (uint32_t)(((lane >> 3) & 1) * 8 + (lane & 7));
    uint32_t khA   = (uint32_t)(((lane >> 4) & 1) * 16);
    uint32_t rowB  = (uint32_t)(((lane >> 4) & 1) * 8 + (lane & 7));
    uint32_t khB   = (uint32_t)(((lane >> 3) & 1) * 16);

    if (tid == 0) {
#pragma unroll
        for (int s = 0; s < NST; s++) MBAR_INIT(sbase + s * 8, 1);
    }
    __syncthreads();

    int xa = zh * axh + zb * axb, ya = m0 + zh * ayh + zb * ayb;
    int xb = zh * bxh + zb * bxb, yb = n0 + zh * byh + zb * byb;

    auto issue = [&](int j, int jb) {
        uint32_t mb = sbase + jb * 8;
        uint32_t da = sbase + 1024 + jb * STAGE;
        int k0 = j * 64;
        MBAR_EXPECT(mb, STAGE);
        tma2d(da, &mA, xa + k0, ya, mb);
        tma2d(da + 16384, &mB, xb + k0, yb, mb);
    };

    if (tid == 0) {
        issue(0, 0);
        if (ntk > 1) issue(1, 1);
    }

    float acc[2][8][4];
#pragma unroll
    for (int mi = 0; mi < 2; mi++)
#pragma unroll
        for (int j = 0; j < 8; j++)
#pragma unroll
            for (int r = 0; r < 4; r++) acc[mi][j][r] = 0.f;

    int buf = 0, ph = 0;
    int pj = NST - 1, pbuf = NST - 1;

    for (int kt = 0; kt < ntk; kt++) {
        MBAR_WAIT(sbase + buf * 8, ph);
        uint32_t As_u = sbase + 1024 + buf * STAGE;
        uint32_t Bs_u = As_u + 16384;
#pragma unroll
        for (int ks = 0; ks < 4; ks++) {
            uint32_t cb = (uint32_t)(ks * 32);
            uint32_t a[2][4];
            ldsm4(a[0], As_u + (wm * 32 +      rowA) * 128 + ((cb + khA) ^ swzr));
            ldsm4(a[1], As_u + (wm * 32 + 16 + rowA) * 128 + ((cb + khA) ^ swzr));
#pragma unroll
            for (int p = 0; p < 4; p++) {
                uint32_t bb[4];
                ldsm4(bb, Bs_u + (wn * 64 + p * 16 + rowB) * 128 + ((cb + khB) ^ swzr));
                mma_fp16(acc[0][2*p],   a[0], bb[0], bb[1]);
                mma_fp16(acc[1][2*p],   a[1], bb[0], bb[1]);
                mma_fp16(acc[0][2*p+1], a[0], bb[2], bb[3]);
                mma_fp16(acc[1][2*p+1], a[1], bb[2], bb[3]);
            }
        }
        __syncthreads();
        if (tid == 0 && pj < ntk) issue(pj, pbuf);
        pj++;
        if (++pbuf == NST) pbuf = 0;
        if (++buf == NST) { buf = 0; ph ^= 1; }
    }

#pragma unroll
    for (int mi = 0; mi < 2; mi++) {
#pragma unroll
        for (int j = 0; j < 8; j++) {
            int row = m0 + wm * 32 + mi * 16 + g;
            int col = n0 + wn * 64 + j * 8 + 2 * tg;
            if (col < N) {
                float v0 = acc[mi][j][0], v1 = acc[mi][j][1];
                float v2 = acc[mi][j][2], v3 = acc[mi][j][3];
                if (Cf) {
                    *(float2*)&Cf[(long long)row * ldc + col] = make_float2(v0, v1);
                    *(float2*)&Cf[(long long)(row + 8) * ldc + col] = make_float2(v2, v3);
                } else {
                    *(__half2*)&Chh[(long long)row * ldc + col] = __floats2half2_rn(v0, v1);
                    *(__half2*)&Chh[(long long)(row + 8) * ldc + col] = __floats2half2_rn(v2, v3);
                }
            }
        }
    }
}

// ---------------- fused flash attention (ldmatrix, bh offset) ----------------
#define SMQ_OFF 1024
#define RING_OFF (SMQ_OFF + 49152)
#define KVSTG 81920
#define SMEM_FA (RING_OFF + 2 * KVSTG)   // 214016

__global__ __launch_bounds__(256, 1) void flash_h(
    const __grid_constant__ CUtensorMap mQ,
    const __grid_constant__ CUtensorMap mK,
    const __grid_constant__ CUtensorMap mV,
    __half* __restrict__ ov, int bhoff)
{
    int qt = (int)gridDim.x - 1 - (int)blockIdx.x;   // heavy tiles first
    int bh = blockIdx.y + bhoff;
    int b = bh >> 4, h = bh & 15;
    int ntk = qt + 1;

    extern __shared__ __align__(1024) char smem[];
    uint32_t sbase = (uint32_t)__cvta_generic_to_shared(smem);

    int tid = threadIdx.x;
    int wid = tid >> 5, lane = tid & 31;
    int g = lane >> 2, tg = lane & 3;

    uint32_t swzr = (uint32_t)(lane & 7) << 4;
    uint32_t rowA = (uint32_t)(((lane >> 3) & 1) * 8 + (lane & 7));
    uint32_t khA  = (uint32_t)(((lane >> 4) & 1) * 16);
    uint32_t rowB = (uint32_t)(((lane >> 4) & 1) * 8 + (lane & 7));
    uint32_t khB  = (uint32_t)(((lane >> 3) & 1) * 16);

    if (tid == 0) {
        MBAR_INIT(sbase + 0, 1);
        MBAR_INIT(sbase + 8, 1);
        MBAR_INIT(sbase + 16, 1);
    }
    __syncthreads();

    auto issueKV = [&](int kt, int st) {
        uint32_t mb = sbase + 8 + st * 8;
        uint32_t base = sbase + RING_OFF + st * KVSTG;
        MBAR_EXPECT(mb, KVSTG);
#pragma unroll
        for (int c = 0; c < 3; c++)
            tma2d(base + c * 16384, &mK, h * 192 + c * 64, b * 2048 + kt * 128, mb);
#pragma unroll
        for (int c = 0; c < 2; c++)
            tma2d(base + 49152 + c * 16384, &mV, kt * 128 + c * 64, bh * 128, mb);
    };

    if (tid == 0) {
        MBAR_EXPECT(sbase + 0, 49152);
#pragma unroll
        for (int c = 0; c < 3; c++)
            tma2d(sbase + SMQ_OFF + c * 16384, &mQ, h * 192 + c * 64, b * 2048 + qt * 128, sbase + 0);
        issueKV(0, 0);
        if (ntk > 1) issueKV(1, 1);
    }

    MBAR_WAIT(sbase + 0, 0);
    uint32_t qf[12][4];
#pragma unroll
    for (int kk = 0; kk < 12; kk++) {
        uint32_t ch = sbase + SMQ_OFF + (kk >> 2) * 16384;
        uint32_t cb = (uint32_t)((kk & 3) * 32);
        ldsm4(qf[kk], ch + (wid * 16 + rowA) * 128 + ((cb + khA) ^ swzr));
    }

    float of[16][4];
#pragma unroll
    for (int j = 0; j < 16; j++)
#pragma unroll
        for (int r = 0; r < 4; r++) of[j][r] = 0.f;
    float m0r = -1e30f, m1r = -1e30f, l0r = 0.f, l1r = 0.f;

    for (int kt = 0; kt < ntk; kt++) {
        int st = kt & 1;
        MBAR_WAIT(sbase + 8 + st * 8, (kt >> 1) & 1);
        uint32_t kbs = sbase + RING_OFF + st * KVSTG;
        uint32_t vbs = kbs + 49152;

        float sj[16][4];
#pragma unroll
        for (int j = 0; j < 16; j++)
#pragma unroll
            for (int r = 0; r < 4; r++) sj[j][r] = 0.f;
#pragma unroll
        for (int kk = 0; kk < 12; kk++) {
            uint32_t ch = kbs + (kk >> 2) * 16384;
            uint32_t cb = (uint32_t)((kk & 3) * 32);
#pragma unroll
            for (int p = 0; p < 8; p++) {
                uint32_t bb[4];
                ldsm4(bb, ch + (p * 16 + rowB) * 128 + ((cb + khB) ^ swzr));
                mma_fp16(sj[2*p],   qf[kk], bb[0], bb[1]);
                mma_fp16(sj[2*p+1], qf[kk], bb[2], bb[3]);
            }
        }

        if (kt == qt) {
            int r0 = wid * 16 + g, r1 = r0 + 8;
#pragma unroll
            for (int jn = 0; jn < 16; jn++) {
                int c0 = jn * 8 + 2 * tg, c1 = c0 + 1;
                if (c0 > r0) sj[jn][0] = -1e30f;
                if (c1 > r0) sj[jn][1] = -1e30f;
                if (c0 > r1) sj[jn][2] = -1e30f;
                if (c1 > r1) sj[jn][3] = -1e30f;
            }
        }

        float mx0 = -1e30f, mx1 = -1e30f;
#pragma unroll
        for (int jn = 0; jn < 16; jn++) {
            mx0 = fmaxf(mx0, fmaxf(sj[jn][0], sj[jn][1]));
            mx1 = fmaxf(mx1, fmaxf(sj[jn][2], sj[jn][3]));
        }
        mx0 = fmaxf(mx0, __shfl_xor_sync(0xffffffffu, mx0, 1));
        mx0 = fmaxf(mx0, __shfl_xor_sync(0xffffffffu, mx0, 2));
        mx1 = fmaxf(mx1, __shfl_xor_sync(0xffffffffu, mx1, 1));
        mx1 = fmaxf(mx1, __shfl_xor_sync(0xffffffffu, mx1, 2));
        float mn0 = fmaxf(m0r, mx0), mn1 = fmaxf(m1r, mx1);
        float f0 = ex2((m0r - mn0) * FA_C), f1 = ex2((m1r - mn1) * FA_C);
        m0r = mn0; m1r = mn1;

        float s0 = 0.f, s1 = 0.f;
        uint32_t pjf[8][4];
#pragma unroll
        for (int u = 0; u < 8; u++) {
            float e00 = ex2((sj[2*u][0] - mn0) * FA_C);
            float e01 = ex2((sj[2*u][1] - mn0) * FA_C);
            float e02 = ex2((sj[2*u][2] - mn1) * FA_C);
            float e03 = ex2((sj[2*u][3] - mn1) * FA_C);
            float e10 = ex2((sj[2*u+1][0] - mn0) * FA_C);
            float e11 = ex2((sj[2*u+1][1] - mn0) * FA_C);
            float e12 = ex2((sj[2*u+1][2] - mn1) * FA_C);
            float e13 = ex2((sj[2*u+1][3] - mn1) * FA_C);
            s0 += e00 + e01 + e10 + e11;
            s1 += e02 + e03 + e12 + e13;
            __half2 h0 = __floats2half2_rn(e00, e01);
            __half2 h1 = __floats2half2_rn(e02, e03);
            __half2 h2 = __floats2half2_rn(e10, e11);
            __half2 h3 = __floats2half2_rn(e12, e13);
            pjf[u][0] = *(uint32_t*)&h0;
            pjf[u][1] = *(uint32_t*)&h1;
            pjf[u][2] = *(uint32_t*)&h2;
            pjf[u][3] = *(uint32_t*)&h3;
        }
        s0 += __shfl_xor_sync(0xffffffffu, s0, 1);
        s0 += __shfl_xor_sync(0xffffffffu, s0, 2);
        s1 += __shfl_xor_sync(0xffffffffu, s1, 1);
        s1 += __shfl_xor_sync(0xffffffffu, s1, 2);
        l0r = l0r * f0 + s0;
        l1r = l1r * f1 + s1;

#pragma unroll
        for (int j = 0; j < 16; j++) {
            of[j][0] *= f0; of[j][1] *= f0;
            of[j][2] *= f1; of[j][3] *= f1;
        }

#pragma unroll
        for (int u = 0; u < 8; u++) {
            uint32_t ch = vbs + (u >> 2) * 16384;
            uint32_t cb = (uint32_t)((u & 3) * 32);
#pragma unroll
            for (int p = 0; p < 8; p++) {
                uint32_t bb[4];
                ldsm4(bb, ch + (p * 16 + rowB) * 128 + ((cb + khB) ^ swzr));
                mma_fp16(of[2*p],   pjf[u], bb[0], bb[1]);
                mma_fp16(of[2*p+1], pjf[u], bb[2], bb[3]);
            }
        }

        __syncthreads();
        if (tid == 0 && kt + 2 < ntk) issueKV(kt + 2, st);
    }

    float inv0 = 1.f / l0r, inv1 = 1.f / l1r;
    long long row0 = (long long)b * 2048 + qt * 128 + wid * 16 + g;
#pragma unroll
    for (int jn = 0; jn < 16; jn++) {
        int d = h * 128 + jn * 8 + 2 * tg;
        __half2 h0 = __floats2half2_rn(of[jn][0] * inv0, of[jn][1] * inv0);
        __half2 h1 = __floats2half2_rn(of[jn][2] * inv1, of[jn][3] * inv1);
        *(__half2*)&ov[row0 * 2048 + d] = h0;
        *(__half2*)&ov[(row0 + 8) * 2048 + d] = h1;
    }
}

// ---------------- prep: fp32 -> fp16 copies ----------------------------------
__global__ void f2h_copy(const float* __restrict__ s, __half* __restrict__ d, long long n4)
{
    long long i = (long long)blockIdx.x * 256 + threadIdx.x;
    if (i >= n4) return;
    float4 v = ((const float4*)s)[i];
    __half2 h0 = __floats2half2_rn(v.x, v.y);
    __half2 h1 = __floats2half2_rn(v.z, v.w);
    ((uint2*)d)[i] = make_uint2(*(uint32_t*)&h0, *(uint32_t*)&h1);
}

__global__ void f2h_head(const float* __restrict__ wkvb, __half* __restrict__ d, int srcOff)
{
    long long i4 = (long long)blockIdx.x * 256 + threadIdx.x;
    long long head = i4 >> 14, off = (i4 & 16383) * 4;
    float4 v = *(const float4*)(wkvb + head * 131072 + srcOff + off);
    __half2 h0 = __floats2half2_rn(v.x, v.y);
    __half2 h1 = __floats2half2_rn(v.z, v.w);
    ((uint2*)d)[i4] = make_uint2(*(uint32_t*)&h0, *(uint32_t*)&h1);
}

// ---------------- rmsnorm rows (fp16 data, fp32 math) ------------------------
__global__ void rmsnorm_h(__half* __restrict__ x, const float* __restrict__ w, int n)
{
    long long row = blockIdx.x;
    __half* r = x + row * n;
    float ss = 0.f;
    for (int i = threadIdx.x; i < n; i += 256) { float v = __half2float(r[i]); ss += v * v; }
    __shared__ float red[8];
#pragma unroll
    for (int o = 16; o; o >>= 1) ss += __shfl_xor_sync(0xffffffffu, ss, o);
    if ((threadIdx.x & 31) == 0) red[threadIdx.x >> 5] = ss;
    __syncthreads();
    float tot = 0.f;
#pragma unroll
    for (int wv = 0; wv < 8; wv++) tot += red[wv];
    float scale = rsqrtf(tot / (float)n + 1e-6f);
    for (int i = threadIdx.x; i < n; i += 256)
        r[i] = __float2half_rn(__half2float(r[i]) * scale * w[i]);
}

// -------- kv row: rmsnorm first 512 (+w), rope last 64 (fp16 data) -----------
__global__ void kv_process_h(__half* __restrict__ kv, const float* __restrict__ w,
                             const float* __restrict__ cosp, const float* __restrict__ sinp)
{
    int row = blockIdx.x;
    int s = row % CS;
    __half* r = kv + (long long)row * 576;
    float ss = 0.f;
    for (int i = threadIdx.x; i < 512; i += 128) { float v = __half2float(r[i]); ss += v * v; }
    __shared__ float red[4];
#pragma unroll
    for (int o = 16; o; o >>= 1) ss += __shfl_xor_sync(0xffffffffu, ss, o);
    if ((threadIdx.x & 31) == 0) red[threadIdx.x >> 5] = ss;
    __syncthreads();
    float tot = red[0] + red[1] + red[2] + red[3];
    float scale = rsqrtf(tot / 512.f + 1e-6f);
    for (int i = threadIdx.x; i < 512; i += 128)
        r[i] = __float2half_rn(__half2float(r[i]) * scale * w[i]);
    if (threadIdx.x < 32) {
        int i = threadIdx.x;
        float x0 = __half2float(r[512 + 2 * i]), x1 = __half2float(r[513 + 2 * i]);
        float c = cosp[s * 32 + i], sn = sinp[s * 32 + i];
        r[512 + 2 * i] = __float2half_rn(x0 * c - x1 * sn);
        r[513 + 2 * i] = __float2half_rn(x0 * sn + x1 * c);
    }
}

// ---------------- RoPE on q2 rows (per-batch half) ----------------------------
__global__ void rope_q2(__half* __restrict__ q2,
                        const float* __restrict__ cosp, const float* __restrict__ sinp)
{
    int idx = blockIdx.x * 256 + threadIdx.x;
    if (idx >= 2048 * CH * 32) return;
    int i = idx & 31;
    int h = (idx >> 5) & 15;
    int row = idx >> 9;
    int s = row;
    __half* p = q2 + (long long)row * 3072 + h * 192 + 128 + 2 * i;
    float x0 = __half2float(p[0]), x1 = __half2float(p[1]);
    float c = cosp[s * 32 + i], sn = sinp[s * 32 + i];
    p[0] = __float2half_rn(x0 * c - x1 * sn);
    p[1] = __float2half_rn(x0 * sn + x1 * c);
}

// ---------------- duplicate roped k_pe into Kp per head -----------------------
__global__ void kpe_dup(const __half* __restrict__ kv, __half* __restrict__ kp)
{
    int idx = blockIdx.x * 256 + threadIdx.x;
    if (idx >= 2 * 2048 * 16 * 32) return;
    int j2 = idx & 31;
    int h = (idx >> 5) & 15;
    int row = idx >> 9;
    uint32_t v = *(const uint32_t*)(kv + (long long)row * 576 + 512 + 2 * j2);
    *(uint32_t*)(kp + (long long)row * 3072 + h * 192 + 128 + 2 * j2) = v;
}

// ---------------- host: tensormap encode via dlopen(libcuda) -----------------
typedef CUresult (*PFN_tmEncode)(
    CUtensorMap*, CUtensorMapDataType, cuuint32_t, void*,
    const cuuint64_t*, const cuuint64_t*, const cuuint32_t*, const cuuint32_t*,
    CUtensorMapInterleave, CUtensorMapSwizzle, CUtensorMapL2promotion,
    CUtensorMapFloatOOBfill);

static PFN_tmEncode tm_encode()
{
    static PFN_tmEncode fn = nullptr;
    if (!fn) {
        void* h = dlopen("libcuda.so.1", RTLD_NOW | RTLD_GLOBAL);
        if (!h) h = dlopen("libcuda.so", RTLD_NOW | RTLD_GLOBAL);
        if (h) fn = (PFN_tmEncode)dlsym(h, "cuTensorMapEncodeTiled");
    }
    return fn;
}

static void make_map_h(CUtensorMap* m, void* base, long long cols, long long rows, long long ld)
{
    cuuint64_t dims[2]    = {(cuuint64_t)cols, (cuuint64_t)rows};
    cuuint64_t strides[1] = {(cuuint64_t)(ld * 2)};
    cuuint32_t box[2]     = {64u, 128u};
    cuuint32_t es[2]      = {1u, 1u};
    tm_encode()(m, CU_TENSOR_MAP_DATA_TYPE_FLOAT16, 2, base, dims, strides, box, es,
                CU_TENSOR_MAP_INTERLEAVE_NONE, CU_TENSOR_MAP_SWIZZLE_128B,
                CU_TENSOR_MAP_L2_PROMOTION_L2_128B, CU_TENSOR_MAP_FLOAT_OOB_FILL_NONE);
}

// ---------------------------------------------------------------------------
extern "C" void kernel_launch(void* const* d_in, const int* in_sizes, int n_in,
                              void* d_out, int out_size)
{
    (void)in_sizes; (void)n_in; (void)out_size;
    const float* x        = (const float*)d_in[0];
    const float* wq_a     = (const float*)d_in[1];
    const float* q_norm_w = (const float*)d_in[2];
    const float* wq_b     = (const float*)d_in[3];
    const float* wkv_a    = (const float*)d_in[4];
    const float* kv_norm_w= (const float*)d_in[5];
    const float* wkv_b    = (const float*)d_in[6];
    const float* wo       = (const float*)d_in[7];
    const float* cosp     = (const float*)d_in[8];
    const float* sinp     = (const float*)d_in[9];
    float* out = (float*)d_out;

    __half *xh, *wqah, *wkvah, *wqbh, *woh, *wvh, *wnh;
    __half *q1, *kvb, *q2, *kp, *vt, *ov;
    cudaGetSymbolAddress((void**)&xh,   g_xh);
    cudaGetSymbolAddress((void**)&wqah, g_wqah);
    cudaGetSymbolAddress((void**)&wkvah,g_wkvah);
    cudaGetSymbolAddress((void**)&wqbh, g_wqbh);
    cudaGetSymbolAddress((void**)&woh,  g_woh);
    cudaGetSymbolAddress((void**)&wvh,  g_wvh);
    cudaGetSymbolAddress((void**)&wnh,  g_wnh);
    cudaGetSymbolAddress((void**)&q1,   g_q1);
    cudaGetSymbolAddress((void**)&kvb,  g_kv);
    cudaGetSymbolAddress((void**)&q2,   g_q2);
    cudaGetSymbolAddress((void**)&kp,   g_kp);
    cudaGetSymbolAddress((void**)&vt,   g_vt);
    cudaGetSymbolAddress((void**)&ov,   g_ov);

    cudaFuncSetAttribute(gemm_h, cudaFuncAttributeMaxDynamicSharedMemorySize, SMEM_TMA);
    cudaFuncSetAttribute(flash_h, cudaFuncAttributeMaxDynamicSharedMemorySize, SMEM_FA);

    CUtensorMap mXH0, mXH1, mWQA, mWKVA, mWQB, mWO, mWNH, mWVH;
    CUtensorMap mXHf, mQ1a, mQ1b, mKV, mQ2, mKP, mVT, mOVa, mOVb;
    make_map_h(&mXHf, xh, 2048, 4096, 2048);
    make_map_h(&mXH0, xh, 2048, 2048, 2048);
    make_map_h(&mXH1, xh + (size_t)2048*2048, 2048, 2048, 2048);
    make_map_h(&mWQA, wqah, 2048, 1536, 2048);
    make_map_h(&mWKVA,wkvah,2048, 576,  2048);
    make_map_h(&mWQB, wqbh, 1536, 3072, 1536);
    make_map_h(&mWO,  woh,  2048, 2048, 2048);
    make_map_h(&mWNH, wnh,  512,  2048, 512);
    make_map_h(&mWVH, wvh,  512,  2048, 512);
    make_map_h(&mQ1a, q1, 1536, 2048, 1536);
    make_map_h(&mQ1b, q1 + (size_t)2048*1536, 1536, 2048, 1536);
    make_map_h(&mKV,  kvb,  576,  4096, 576);
    make_map_h(&mQ2,  q2,   3072, 4096, 3072);
    make_map_h(&mKP,  kp,   3072, 4096, 3072);
    make_map_h(&mVT,  vt,   2048, 4096, 2048);
    make_map_h(&mOVa, ov, 2048, 2048, 2048);
    make_map_h(&mOVb, ov + (size_t)2048*2048, 2048, 2048, 2048);

    // ---- streams/events: created ONCE; graph width kept at R13 level
    //      (origin + 3 side streams) — wider graphs leave driver pool residue.
    static bool s_init = false;
    static cudaStream_t s1, s2, s3;
    static cudaEvent_t evRoot, evX, evWQA, evWQB, evWO, evWNH, evKVP, evKP, evVT, evB;
    if (!s_init) {
        cudaStreamCreateWithFlags(&s1, cudaStreamNonBlocking);
        cudaStreamCreateWithFlags(&s2, cudaStreamNonBlocking);
        cudaStreamCreateWithFlags(&s3, cudaStreamNonBlocking);
        cudaEventCreateWithFlags(&evRoot, cudaEventDisableTiming);
        cudaEventCreateWithFlags(&evX,    cudaEventDisableTiming);
        cudaEventCreateWithFlags(&evWQA,  cudaEventDisableTiming);
        cudaEventCreateWithFlags(&evWQB,  cudaEventDisableTiming);
        cudaEventCreateWithFlags(&evWO,   cudaEventDisableTiming);
        cudaEventCreateWithFlags(&evWNH,  cudaEventDisableTiming);
        cudaEventCreateWithFlags(&evKVP,  cudaEventDisableTiming);
        cudaEventCreateWithFlags(&evKP,   cudaEventDisableTiming);
        cudaEventCreateWithFlags(&evVT,   cudaEventDisableTiming);
        cudaEventCreateWithFlags(&evB,    cudaEventDisableTiming);
        s_init = true;
    }

    // ---- origin: full x convert, wqa convert, then b0 Q chain
    cudaEventRecord(evRoot, 0);
    f2h_copy<<<8192, 256>>>(x, xh, 2097152);
    cudaEventRecord(evX, 0);
    f2h_copy<<<3072, 256>>>(wq_a, wqah, 786432);
    cudaEventRecord(evWQA, 0);

    // ---- s1: big weight converts, then b1 Q chain
    cudaStreamWaitEvent(s1, evRoot, 0);
    f2h_copy<<<4608, 256, 0, s1>>>(wq_b, wqbh, 1179648);
    cudaEventRecord(evWQB, s1);
    f2h_copy<<<4096, 256, 0, s1>>>(wo, woh, 1048576);
    cudaEventRecord(evWO, s1);

    // ---- s3: per-head weight converts, later V_h
    cudaStreamWaitEvent(s3, evRoot, 0);
    f2h_head<<<1024, 256, 0, s3>>>(wkv_b, wnh, 0);
    cudaEventRecord(evWNH, s3);
    f2h_head<<<1024, 256, 0, s3>>>(wkv_b, wvh, 65536);

    // ---- s2: KV chain (both batches)
    cudaStreamWaitEvent(s2, evX, 0);
    f2h_copy<<<1152, 256, 0, s2>>>(wkv_a, wkvah, 294912);
    gemm_h<<<dim3(5, 32, 1), 256, SMEM_TMA, s2>>>(mXHf, mWKVA, 0,0,0,0, 0,0,0,0,
        nullptr, kvb, 576, 0, 0, 4096, 576, 2048, 0, 0);
    kv_process_h<<<4096, 128, 0, s2>>>(kvb, kv_norm_w, cosp, sinp);
    cudaEventRecord(evKVP, s2);
    cudaStreamWaitEvent(s2, evWNH, 0);
    gemm_h<<<dim3(1, 16, 32), 256, SMEM_TMA, s2>>>(mKV, mWNH, 0,0,0,2048, 0,128,0,0,
        nullptr, kp, 3072, 192, (long long)2048*3072, 2048, 128, 512, 0, 0);
    kpe_dup<<<8192, 256, 0, s2>>>(kvb, kp);
    cudaEventRecord(evKP, s2);

    // ---- s3 continued: V_h (both batches)
    cudaStreamWaitEvent(s3, evKVP, 0);
    gemm_h<<<dim3(16, 1, 32), 256, SMEM_TMA, s3>>>(mWVH, mKV, 0,128,0,0, 0,0,0,2048,
        nullptr, vt, 2048, (long long)128*2048, (long long)16*128*2048,
        128, 2048, 512, 0, 0);
    cudaEventRecord(evVT, s3);

    // ---- origin: b0 Q chain
    gemm_h<<<dim3(12, 16, 1), 256, SMEM_TMA>>>(mXH0, mWQA, 0,0,0,0, 0,0,0,0,
        nullptr, q1, 1536, 0, 0, 2048, 1536, 2048, 0, 0);
    rmsnorm_h<<<2048, 256>>>(q1, q_norm_w, 1536);
    cudaStreamWaitEvent(0, evWQB, 0);
    gemm_h<<<dim3(24, 16, 1), 256, SMEM_TMA>>>(mQ1a, mWQB, 0,0,0,0, 0,0,0,0,
        nullptr, q2, 3072, 0, 0, 2048, 3072, 1536, 0, 0);
    rope_q2<<<4096, 256>>>(q2, cosp, sinp);
    cudaStreamWaitEvent(0, evKP, 0);
    cudaStreamWaitEvent(0, evVT, 0);
    flash_h<<<dim3(16, 16, 1), 256, SMEM_FA>>>(mQ2, mKP, mVT, ov, 0);
    cudaStreamWaitEvent(0, evWO, 0);
    gemm_h<<<dim3(16, 16, 1), 256, SMEM_TMA>>>(mOVa, mWO, 0,0,0,0, 0,0,0,0,
        out, nullptr, 2048, 0, 0, 2048, 2048, 2048, 0, 0);

    // ---- s1 continued: b1 Q chain (wo convert already done on this stream)
    cudaStreamWaitEvent(s1, evX, 0);
    cudaStreamWaitEvent(s1, evWQA, 0);
    gemm_h<<<dim3(12, 16, 1), 256, SMEM_TMA, s1>>>(mXH1, mWQA, 0,0,0,0, 0,0,0,0,
        nullptr, q1 + (size_t)2048*1536, 1536, 0, 0, 2048, 1536, 2048, 0, 0);
    rmsnorm_h<<<2048, 256, 0, s1>>>(q1 + (size_t)2048*1536, q_norm_w, 1536);
    gemm_h<<<dim3(24, 16, 1), 256, SMEM_TMA, s1>>>(mQ1b, mWQB, 0,0,0,0, 0,0,0,0,
        nullptr, q2 + (size_t)2048*3072, 3072, 0, 0, 2048, 3072, 1536, 0, 0);
    rope_q2<<<4096, 256, 0, s1>>>(q2 + (size_t)2048*3072, cosp, sinp);
    cudaStreamWaitEvent(s1, evKP, 0);
    cudaStreamWaitEvent(s1, evVT, 0);
    flash_h<<<dim3(16, 16, 1), 256, SMEM_FA, s1>>>(mQ2, mKP, mVT, ov, 16);
    gemm_h<<<dim3(16, 16, 1), 256, SMEM_TMA, s1>>>(mOVb, mWO, 0,0,0,0, 0,0,0,0,
        out + (size_t)2048*2048, nullptr, 2048, 0, 0, 2048, 2048, 2048, 0, 0);
    cudaEventRecord(evB, s1);

    // ---- join s1 back into origin
    cudaStreamWaitEvent(0, evB, 0);
}